// round 1
// baseline (speedup 1.0000x reference)
#include <cuda_runtime.h>
#include <cuda_bf16.h>
#include <math.h>

// Problem constants (fixed by setup_inputs)
#define NIMG 256
#define NREG 36
#define NCAP 256
#define MAXW 60
#define DIM  1024

#define SMOOTH 9.0f
#define EPSV   1e-8f
#define LEAK   0.1f

// Scratch (device globals: no allocation allowed in kernel_launch)
__device__ float g_G[NIMG * NREG * NREG];   // per-image Gram matrices
__device__ float g_w1[NCAP * MAXW];         // per-word caption norms

// ---------------------------------------------------------------------------
// packed f32x2 helpers (sm_100+)
// ---------------------------------------------------------------------------
__device__ __forceinline__ unsigned long long pack2(float lo, float hi) {
    unsigned long long r;
    asm("mov.b64 %0, {%1, %2};" : "=l"(r) : "f"(lo), "f"(hi));
    return r;
}
__device__ __forceinline__ void unpack2(unsigned long long v, float &lo, float &hi) {
    asm("mov.b64 {%0, %1}, %2;" : "=f"(lo), "=f"(hi) : "l"(v));
}
__device__ __forceinline__ void ffma2(unsigned long long &d,
                                      unsigned long long a,
                                      unsigned long long b) {
    asm("fma.rn.f32x2 %0, %1, %2, %0;" : "+l"(d) : "l"(a), "l"(b));
}

__device__ __forceinline__ float warpSum(float v) {
    v += __shfl_xor_sync(0xffffffffu, v, 16);
    v += __shfl_xor_sync(0xffffffffu, v, 8);
    v += __shfl_xor_sync(0xffffffffu, v, 4);
    v += __shfl_xor_sync(0xffffffffu, v, 2);
    v += __shfl_xor_sync(0xffffffffu, v, 1);
    return v;
}

// ---------------------------------------------------------------------------
// Kernel 1: per-image Gram matrices G[i][r][r'] = imgs[i][r] . imgs[i][r']
// grid = NIMG, block = 256
// ---------------------------------------------------------------------------
__global__ void gram_kernel(const float* __restrict__ imgs) {
    const int i = blockIdx.x;
    __shared__ float chunk[NREG * 129];   // 129-pad: conflict-free
    float acc[6];
#pragma unroll
    for (int j = 0; j < 6; j++) acc[j] = 0.f;

    for (int d0 = 0; d0 < DIM; d0 += 128) {
        __syncthreads();
        for (int idx = threadIdx.x; idx < NREG * 32; idx += 256) {
            int r = idx >> 5, dq = idx & 31;
            float4 v = *(const float4*)(imgs + ((size_t)i * NREG + r) * DIM + d0 + dq * 4);
            int base = r * 129 + dq * 4;
            chunk[base + 0] = v.x; chunk[base + 1] = v.y;
            chunk[base + 2] = v.z; chunk[base + 3] = v.w;
        }
        __syncthreads();
#pragma unroll
        for (int j = 0; j < 6; j++) {
            int p = threadIdx.x + j * 256;
            if (p < NREG * NREG) {
                int r = p / NREG, rp = p - r * NREG;
                const float* A = chunk + r * 129;
                const float* B = chunk + rp * 129;
                float s = 0.f;
#pragma unroll 8
                for (int d = 0; d < 128; d++) s += A[d] * B[d];
                acc[j] += s;
            }
        }
    }
#pragma unroll
    for (int j = 0; j < 6; j++) {
        int p = threadIdx.x + j * 256;
        if (p < NREG * NREG) g_G[(size_t)i * NREG * NREG + p] = acc[j];
    }
}

// ---------------------------------------------------------------------------
// Kernel 2: per-word caption norms w1[c][w] = ||caps[c][w]|| (0 for padded w)
// grid = NCAP, block = 256 (8 warps; warp handles word w, w+8, ...)
// ---------------------------------------------------------------------------
__global__ void w1_kernel(const float* __restrict__ caps,
                          const int* __restrict__ cap_lens) {
    const int c = blockIdx.x;
    const int wid = threadIdx.x >> 5, lane = threadIdx.x & 31;
    const int len = cap_lens[c];
    for (int w = wid; w < MAXW; w += 8) {
        const float* row = caps + ((size_t)c * MAXW + w) * DIM;
        float s = 0.f;
#pragma unroll
        for (int j = 0; j < 8; j++) {
            float4 v = *(const float4*)(row + j * 128 + lane * 4);
            s += v.x * v.x + v.y * v.y + v.z * v.z + v.w * v.w;
        }
        s = warpSum(s);
        if (lane == 0) g_w1[c * MAXW + w] = (w < len) ? sqrtf(s) : 0.f;
    }
}

// ---------------------------------------------------------------------------
// Kernel 3: fused main kernel.
// One CTA handles caption c x image-pair (i0, i0+1).
//   GEMM: S[w][rr] = q[c][w] . img[rr]   (M=60 pad 64, N=72, K=1024, f32x2)
//   Epilogue: leaky -> l2norm over w -> softmax over r -> w12, attn^T G attn
// grid = (NIMG/2, NCAP), block = 192 (tx 0..15 over w, ty 0..11 over rr)
// ---------------------------------------------------------------------------
__global__ void __launch_bounds__(192)
main_kernel(const float* __restrict__ imgs,
            const float* __restrict__ caps,
            const int* __restrict__ cap_lens,
            float* __restrict__ out) {
    const int c  = blockIdx.y;
    const int i0 = blockIdx.x * 2;
    const int tid = threadIdx.x;
    const int tx = tid & 15, ty = tid >> 4;
    const int lane = tid & 31, wid = tid >> 5;

    __shared__ __align__(16) float buf[4456];   // GEMM tiles / S + scale (union)
    __shared__ float Gsm[2 * NREG * 37];        // padded Gram, both images
    __shared__ float w1s[MAXW];
    __shared__ float warpPart[12];

    const int capLen = cap_lens[c];

    // stage Gram matrices (stride-37 pad: conflict-free row reads)
    for (int idx = tid; idx < 2 * NREG * NREG; idx += 192) {
        int img = idx / (NREG * NREG);
        int rem = idx - img * (NREG * NREG);
        int r = rem / NREG, rp = rem - r * NREG;
        Gsm[img * (NREG * 37) + r * 37 + rp] =
            g_G[(size_t)(i0 + img) * NREG * NREG + rem];
    }
    if (tid < MAXW) w1s[tid] = g_w1[c * MAXW + tid];

    // ---------------- GEMM ----------------
    float* asub = buf;          // [32][64]  k-major
    float* bsub = buf + 2048;   // [32][72]  k-major
    unsigned long long acc[12];
#pragma unroll
    for (int j = 0; j < 12; j++) acc[j] = 0ull;

    const float* qbase = caps + (size_t)c * MAXW * DIM;
    const float* ibase = imgs + (size_t)i0 * NREG * DIM;

    for (int k0 = 0; k0 < DIM; k0 += 32) {
        __syncthreads();
        // A tile: caps (masked). idx -> (kq, w); consecutive tid -> consecutive w
        for (int idx = tid; idx < 480; idx += 192) {
            int kq = idx / 60, w = idx - kq * 60;
            float4 v = make_float4(0.f, 0.f, 0.f, 0.f);
            if (w < capLen)
                v = *(const float4*)(qbase + (size_t)w * DIM + k0 + kq * 4);
            int kk = kq * 4;
            asub[(kk + 0) * 64 + w] = v.x;
            asub[(kk + 1) * 64 + w] = v.y;
            asub[(kk + 2) * 64 + w] = v.z;
            asub[(kk + 3) * 64 + w] = v.w;
        }
        // B tile: two images stacked (rr = img*36 + r)
        for (int idx = tid; idx < 576; idx += 192) {
            int kq = idx / 72, rr = idx - kq * 72;
            float4 v = *(const float4*)(ibase + (size_t)rr * DIM + k0 + kq * 4);
            int kk = kq * 4;
            bsub[(kk + 0) * 72 + rr] = v.x;
            bsub[(kk + 1) * 72 + rr] = v.y;
            bsub[(kk + 2) * 72 + rr] = v.z;
            bsub[(kk + 3) * 72 + rr] = v.w;
        }
        __syncthreads();
#pragma unroll 8
        for (int k = 0; k < 32; k++) {
            float4 av = *(const float4*)(asub + k * 64 + tx * 4);
            unsigned long long a01 = pack2(av.x, av.y);
            unsigned long long a23 = pack2(av.z, av.w);
            const float* bp = bsub + k * 72 + ty * 6;
            float2 b0 = *(const float2*)(bp);
            float2 b1 = *(const float2*)(bp + 2);
            float2 b2 = *(const float2*)(bp + 4);
            float bv[6] = {b0.x, b0.y, b1.x, b1.y, b2.x, b2.y};
#pragma unroll
            for (int j = 0; j < 6; j++) {
                unsigned long long bb = pack2(bv[j], bv[j]);
                ffma2(acc[j * 2 + 0], a01, bb);
                ffma2(acc[j * 2 + 1], a23, bb);
            }
        }
    }
    __syncthreads();   // GEMM tiles dead; reuse buf for S

    // ---------------- epilogue ----------------
    float* Ssm      = buf;          // [60][73]
    float* scaleArr = buf + 4380;   // [72]

    {
        float sv[4][6];
#pragma unroll
        for (int j = 0; j < 6; j++) {
            unpack2(acc[j * 2 + 0], sv[0][j], sv[1][j]);
            unpack2(acc[j * 2 + 1], sv[2][j], sv[3][j]);
        }
#pragma unroll
        for (int jj = 0; jj < 4; jj++) {
            int w = tx * 4 + jj;
            if (w < MAXW) {
#pragma unroll
                for (int j = 0; j < 6; j++)
                    Ssm[w * 73 + ty * 6 + j] = sv[jj][j];
            }
        }
    }
    __syncthreads();

    // per-column scale = SMOOTH / (||leaky(S[:,rr])||_w + eps)
    if (tid < 72) {
        float ss = 0.f;
#pragma unroll 4
        for (int w = 0; w < MAXW; w++) {
            float v = Ssm[w * 73 + tid];
            v = (v < 0.f) ? LEAK * v : v;
            ss += v * v;
        }
        scaleArr[tid] = SMOOTH / (sqrtf(ss) + EPSV);
    }
    __syncthreads();

    // tasks: (w, img) pairs; one warp per task; lane covers r (lane<4 also r+32)
    float part0 = 0.f, part1 = 0.f;
    for (int task = wid; task < 2 * MAXW; task += 6) {
        int w = task >> 1, img = task & 1;
        const float* Srow = Ssm + w * 73 + img * NREG;
        const float* scl  = scaleArr + img * NREG;

        float raw0 = Srow[lane];
        float raw1 = (lane < 4) ? Srow[32 + lane] : 0.f;

        float l0 = ((raw0 < 0.f) ? LEAK * raw0 : raw0) * scl[lane];
        float e0 = __expf(l0);
        float e1 = 0.f;
        if (lane < 4) {
            float l1 = ((raw1 < 0.f) ? LEAK * raw1 : raw1) * scl[32 + lane];
            e1 = __expf(l1);
        }
        float inv = 1.f / warpSum(e0 + e1);
        float a0 = e0 * inv, a1 = e1 * inv;

        float w12 = warpSum(a0 * raw0 + a1 * raw1);

        // ||wctx||^2 = attn^T G attn  via y = G.attn (attn broadcast by shfl)
        const float* Gi  = Gsm + img * (NREG * 37);
        const float* Gr0 = Gi + lane * 37;
        const float* Gr1 = Gi + ((lane < 4) ? (lane + 32) * 37 : 0);
        float y0 = 0.f, y1 = 0.f;
#pragma unroll
        for (int rp = 0; rp < NREG; rp++) {
            float arp = __shfl_sync(0xffffffffu, (rp < 32) ? a0 : a1, rp & 31);
            y0 += Gr0[rp] * arp;
            if (lane < 4) y1 += Gr1[rp] * arp;
        }
        float w2sq = warpSum(a0 * y0 + a1 * y1);

        float sim = w12 / fmaxf(w1s[w] * sqrtf(w2sq), EPSV);
        if (img) part1 += sim; else part0 += sim;
    }

    if (lane == 0) {
        warpPart[wid * 2 + 0] = part0;
        warpPart[wid * 2 + 1] = part1;
    }
    __syncthreads();
    if (tid < 2) {
        float s = 0.f;
#pragma unroll
        for (int k = 0; k < 6; k++) s += warpPart[k * 2 + tid];
        out[(size_t)(i0 + tid) * NCAP + c] = s / (float)capLen;
    }
}

// ---------------------------------------------------------------------------
extern "C" void kernel_launch(void* const* d_in, const int* in_sizes, int n_in,
                              void* d_out, int out_size) {
    const float* imgs     = (const float*)d_in[0];
    const float* caps     = (const float*)d_in[1];
    const int*   cap_lens = (const int*)d_in[3];
    float*       out      = (float*)d_out;

    gram_kernel<<<NIMG, 256>>>(imgs);
    w1_kernel<<<NCAP, 256>>>(caps, cap_lens);
    dim3 grid(NIMG / 2, NCAP);
    main_kernel<<<grid, 192>>>(imgs, caps, cap_lens, out);
}

// round 3
// speedup vs baseline: 2.8694x; 2.8694x over previous
#include <cuda_runtime.h>
#include <cuda_bf16.h>
#include <cstdint>
#include <math.h>

#define NIMG 256
#define NREG 36
#define NCAP 256
#define MAXW 60
#define CAPW 64
#define DIM  1024

#define SMOOTH 9.0f
#define EPSV   1e-8f
#define LEAK   0.1f

// ---------------------------------------------------------------------------
// Device global scratch
// ---------------------------------------------------------------------------
__device__ __nv_bfloat16 g_caps_hi[NCAP * CAPW * DIM];
__device__ __nv_bfloat16 g_caps_lo[NCAP * CAPW * DIM];
__device__ __nv_bfloat16 g_imgs_hi[NIMG * NREG * DIM];
__device__ __nv_bfloat16 g_imgs_lo[NIMG * NREG * DIM];
__device__ float g_G[NIMG * NREG * NREG];
__device__ float g_w1[NCAP * MAXW];

// ---------------------------------------------------------------------------
// Helpers (all arch-portable PTX: sm_80+ only, nothing 'a'-gated)
// ---------------------------------------------------------------------------
__device__ __forceinline__ uint32_t smem_to_u32(const void* p) {
    uint32_t a;
    asm("{ .reg .u64 t; cvta.to.shared.u64 t, %1; cvt.u32.u64 %0, t; }"
        : "=r"(a) : "l"(p));
    return a;
}
__device__ __forceinline__ void cp16(uint32_t dst, const void* src) {
    asm volatile("cp.async.cg.shared.global [%0], [%1], 16;" :: "r"(dst), "l"(src) : "memory");
}
__device__ __forceinline__ void ldsm_x4(uint32_t &r0, uint32_t &r1, uint32_t &r2,
                                        uint32_t &r3, uint32_t addr) {
    asm volatile("ldmatrix.sync.aligned.m8n8.x4.shared.b16 {%0,%1,%2,%3}, [%4];"
                 : "=r"(r0), "=r"(r1), "=r"(r2), "=r"(r3) : "r"(addr));
}
__device__ __forceinline__ void mma_bf16(float &c0, float &c1, float &c2, float &c3,
                                         uint32_t a0, uint32_t a1, uint32_t a2, uint32_t a3,
                                         uint32_t b0, uint32_t b1) {
    asm volatile("mma.sync.aligned.m16n8k16.row.col.f32.bf16.bf16.f32 "
                 "{%0,%1,%2,%3}, {%4,%5,%6,%7}, {%8,%9}, {%0,%1,%2,%3};"
                 : "+f"(c0), "+f"(c1), "+f"(c2), "+f"(c3)
                 : "r"(a0), "r"(a1), "r"(a2), "r"(a3), "r"(b0), "r"(b1));
}
__device__ __forceinline__ float warpSum(float v) {
    v += __shfl_xor_sync(0xffffffffu, v, 16);
    v += __shfl_xor_sync(0xffffffffu, v, 8);
    v += __shfl_xor_sync(0xffffffffu, v, 4);
    v += __shfl_xor_sync(0xffffffffu, v, 2);
    v += __shfl_xor_sync(0xffffffffu, v, 1);
    return v;
}

// ---------------------------------------------------------------------------
// Prep: bf16 hi/lo split of caps (masked + padded to 64 words) and imgs
// ---------------------------------------------------------------------------
__global__ void split_caps_kernel(const float* __restrict__ caps,
                                  const int* __restrict__ cap_lens) {
    int idx = blockIdx.x * 256 + threadIdx.x;
    int e = idx * 4;
    int c = e >> 16;
    int rem = e & 65535;
    int w = rem >> 10;
    int d = rem & 1023;
    float4 v = make_float4(0.f, 0.f, 0.f, 0.f);
    int len = cap_lens[c];
    if (w < len)
        v = *(const float4*)(caps + ((size_t)c * MAXW + w) * DIM + d);
    __nv_bfloat16 hx = __float2bfloat16(v.x), hy = __float2bfloat16(v.y);
    __nv_bfloat16 hz = __float2bfloat16(v.z), hw = __float2bfloat16(v.w);
    float lx = v.x - __bfloat162float(hx), ly = v.y - __bfloat162float(hy);
    float lz = v.z - __bfloat162float(hz), lw = v.w - __bfloat162float(hw);
    size_t o = (size_t)e;
    *(__nv_bfloat162*)(g_caps_hi + o)     = __nv_bfloat162(hx, hy);
    *(__nv_bfloat162*)(g_caps_hi + o + 2) = __nv_bfloat162(hz, hw);
    *(__nv_bfloat162*)(g_caps_lo + o)     = __floats2bfloat162_rn(lx, ly);
    *(__nv_bfloat162*)(g_caps_lo + o + 2) = __floats2bfloat162_rn(lz, lw);
}

__global__ void split_imgs_kernel(const float* __restrict__ imgs) {
    int idx = blockIdx.x * 256 + threadIdx.x;
    size_t e = (size_t)idx * 4;
    float4 v = *(const float4*)(imgs + e);
    __nv_bfloat16 hx = __float2bfloat16(v.x), hy = __float2bfloat16(v.y);
    __nv_bfloat16 hz = __float2bfloat16(v.z), hw = __float2bfloat16(v.w);
    float lx = v.x - __bfloat162float(hx), ly = v.y - __bfloat162float(hy);
    float lz = v.z - __bfloat162float(hz), lw = v.w - __bfloat162float(hw);
    *(__nv_bfloat162*)(g_imgs_hi + e)     = __nv_bfloat162(hx, hy);
    *(__nv_bfloat162*)(g_imgs_hi + e + 2) = __nv_bfloat162(hz, hw);
    *(__nv_bfloat162*)(g_imgs_lo + e)     = __floats2bfloat162_rn(lx, ly);
    *(__nv_bfloat162*)(g_imgs_lo + e + 2) = __floats2bfloat162_rn(lz, lw);
}

// ---------------------------------------------------------------------------
// Per-image Gram matrices (fp32, exact)
// ---------------------------------------------------------------------------
__global__ void gram_kernel(const float* __restrict__ imgs) {
    const int i = blockIdx.x;
    __shared__ float chunk[NREG * 132];
    float acc[6];
#pragma unroll
    for (int j = 0; j < 6; j++) acc[j] = 0.f;

    for (int d0 = 0; d0 < DIM; d0 += 128) {
        __syncthreads();
        for (int idx = threadIdx.x; idx < NREG * 32; idx += 256) {
            int r = idx >> 5, dq = idx & 31;
            float4 v = *(const float4*)(imgs + ((size_t)i * NREG + r) * DIM + d0 + dq * 4);
            *(float4*)(chunk + r * 132 + dq * 4) = v;
        }
        __syncthreads();
#pragma unroll
        for (int j = 0; j < 6; j++) {
            int p = threadIdx.x + j * 256;
            if (p < NREG * NREG) {
                int r = p / NREG, rp = p - r * NREG;
                const float4* A = (const float4*)(chunk + r * 132);
                const float4* B = (const float4*)(chunk + rp * 132);
                float s = 0.f;
#pragma unroll
                for (int q = 0; q < 32; q++) {
                    float4 a = A[q], b = B[q];
                    s += a.x * b.x + a.y * b.y + a.z * b.z + a.w * b.w;
                }
                acc[j] += s;
            }
        }
    }
#pragma unroll
    for (int j = 0; j < 6; j++) {
        int p = threadIdx.x + j * 256;
        if (p < NREG * NREG) g_G[(size_t)i * NREG * NREG + p] = acc[j];
    }
}

// ---------------------------------------------------------------------------
// Per-word caption norms
// ---------------------------------------------------------------------------
__global__ void w1_kernel(const float* __restrict__ caps,
                          const int* __restrict__ cap_lens) {
    const int c = blockIdx.x;
    const int wid = threadIdx.x >> 5, lane = threadIdx.x & 31;
    const int len = cap_lens[c];
    for (int w = wid; w < MAXW; w += 8) {
        const float* row = caps + ((size_t)c * MAXW + w) * DIM;
        float s = 0.f;
#pragma unroll
        for (int j = 0; j < 8; j++) {
            float4 v = *(const float4*)(row + j * 128 + lane * 4);
            s += v.x * v.x + v.y * v.y + v.z * v.z + v.w * v.w;
        }
        s = warpSum(s);
        if (lane == 0) g_w1[c * MAXW + w] = (w < len) ? sqrtf(s) : 0.f;
    }
}

// ---------------------------------------------------------------------------
// Main fused kernel: HMMA (mma.sync bf16) GEMM M=128, N=144, K=3072 + epilogue
// Shared memory layout (bytes):
//   [0,18432)        A stage 0   (128 rows x 144B; row = 64 bf16 + 8 pad)
//   [18432,39168)    B stage 0   (144 rows x 144B)
//   [39168,57600)    A stage 1
//   [57600,78336)    B stage 1
//   [0,75776)        S matrix after GEMM (128 x 148 fp32)  -- reuses stages
//   [78336,101376)   Gram (4 x 36 x 40 fp32)
//   [101376,101888)  w1   (2 x 64 fp32)
//   [101888,103040)  scale (2 x 144 fp32)
//   [103040,103104)  warp partials (16 fp32)
// ---------------------------------------------------------------------------
#define SA0 0
#define SB0 18432
#define SA1 39168
#define SB1 57600
#define SOFF_G     78336
#define SOFF_W1    101376
#define SOFF_SCALE 101888
#define SOFF_WP    103040
#define SMEM_TOTAL_MAIN 103104
#define NCHUNK 48
#define ASTRIDE 144   // bytes per A/B smem row (72 bf16)
#define SSTRIDE 148   // floats per S row

__device__ __forceinline__ void load_stage(uint32_t sb, int chunk, int tid,
                                           int arowbase, int browbase) {
    int p = chunk >> 4;                 // pass: 0 hi*hi, 1 hi*lo, 2 lo*hi
    int k0 = (chunk & 15) << 6;
    const __nv_bfloat16* Abase = (p == 2) ? g_caps_lo : g_caps_hi;
    const __nv_bfloat16* Bbase = (p == 1) ? g_imgs_lo : g_imgs_hi;
    uint32_t sA = sb + ((chunk & 1) ? SA1 : SA0);
    uint32_t sB = sb + ((chunk & 1) ? SB1 : SB0);
#pragma unroll
    for (int t = 0; t < 4; t++) {
        int o = tid + t * 256;
        int row = o >> 3, seg = o & 7;
        cp16(sA + row * ASTRIDE + seg * 16,
             Abase + (((size_t)(arowbase + row)) << 10) + k0 + (seg << 3));
    }
#pragma unroll
    for (int t = 0; t < 4; t++) {
        int o = tid + t * 256;
        int row = o >> 3, seg = o & 7;
        cp16(sB + row * ASTRIDE + seg * 16,
             Bbase + (((size_t)(browbase + row)) << 10) + k0 + (seg << 3));
    }
    {   // B tail: rows 128..143
        int o = tid + 1024;
        if (o < 1152) {
            int row = o >> 3, seg = o & 7;
            cp16(sB + row * ASTRIDE + seg * 16,
                 Bbase + (((size_t)(browbase + row)) << 10) + k0 + (seg << 3));
        }
    }
    asm volatile("cp.async.commit_group;" ::: "memory");
}

__global__ void __launch_bounds__(256, 2)
main_kernel(const int* __restrict__ cap_lens, float* __restrict__ out) {
    extern __shared__ __align__(16) char smem[];
    const uint32_t sb = smem_to_u32(smem);
    const int tid = threadIdx.x, lane = tid & 31, wid = tid >> 5;
    const int c0 = blockIdx.y * 2;
    const int i0 = blockIdx.x * 4;
    const int arowbase = blockIdx.y * 128;   // rows into g_caps_* (64/cap)
    const int browbase = blockIdx.x * 144;   // rows into g_imgs_* (36/img)

    // stage Gram (40-float stride) + caption norms
    {
        float* Gs = (float*)(smem + SOFF_G);
        if (tid < 4 * NREG) {
            int blk = tid / NREG, r = tid - blk * NREG;
            const float4* src = (const float4*)(g_G + ((size_t)(i0 + blk) * NREG + r) * NREG);
            float4* dst = (float4*)(Gs + (blk * NREG + r) * 40);
#pragma unroll
            for (int q = 0; q < 9; q++) dst[q] = src[q];
        }
        float* w1s = (float*)(smem + SOFF_W1);
        if (tid < 128) {
            int cc = tid >> 6, w = tid & 63;
            w1s[tid] = (w < MAXW) ? g_w1[(c0 + cc) * MAXW + w] : 0.f;
        }
    }

    // ---------------- pipelined HMMA GEMM ----------------
    float acc[72];
#pragma unroll
    for (int j = 0; j < 72; j++) acc[j] = 0.f;

    load_stage(sb, 0, tid, arowbase, browbase);
    load_stage(sb, 1, tid, arowbase, browbase);

    // per-lane ldmatrix address components
    const int a_row = wid * 16 + (lane & 15);
    const int a_kad = (lane >> 4) << 3;          // +8 halfs for lanes>=16
    const int b_rowoff = ((lane >> 4) << 3) + (lane & 7);
    const int b_kad = ((lane >> 3) & 1) << 3;

    for (int i = 0; i < NCHUNK; i++) {
        const int s = i & 1;
        if (i == NCHUNK - 1) asm volatile("cp.async.wait_group 0;" ::: "memory");
        else                 asm volatile("cp.async.wait_group 1;" ::: "memory");
        __syncthreads();

        uint32_t Asm = sb + (s ? SA1 : SA0);
        uint32_t Bsm = sb + (s ? SB1 : SB0);
#pragma unroll
        for (int ks = 0; ks < 4; ks++) {
            uint32_t a0, a1, a2, a3;
            ldsm_x4(a0, a1, a2, a3,
                    Asm + a_row * ASTRIDE + (ks * 16 + a_kad) * 2);
#pragma unroll
            for (int np = 0; np < 9; np++) {
                uint32_t b0, b1, b2, b3;
                ldsm_x4(b0, b1, b2, b3,
                        Bsm + (np * 16 + b_rowoff) * ASTRIDE + (ks * 16 + b_kad) * 2);
                int j0 = np * 8;
                mma_bf16(acc[j0 + 0], acc[j0 + 1], acc[j0 + 2], acc[j0 + 3],
                         a0, a1, a2, a3, b0, b1);
                mma_bf16(acc[j0 + 4], acc[j0 + 5], acc[j0 + 6], acc[j0 + 7],
                         a0, a1, a2, a3, b2, b3);
            }
        }
        __syncthreads();
        if (i + 2 < NCHUNK)
            load_stage(sb, i + 2, tid, arowbase, browbase);
    }

    // ---------------- write S to shared ----------------
    float* S = (float*)smem;
    {
        const int r1 = wid * 16 + (lane >> 2);
        const int cbase = (lane & 3) * 2;
#pragma unroll
        for (int nt = 0; nt < 18; nt++) {
            int col = nt * 8 + cbase;
            *(float2*)(S + r1 * SSTRIDE + col)       = make_float2(acc[nt * 4 + 0], acc[nt * 4 + 1]);
            *(float2*)(S + (r1 + 8) * SSTRIDE + col) = make_float2(acc[nt * 4 + 2], acc[nt * 4 + 3]);
        }
    }
    __syncthreads();

    // ---------------- column norms -> scale ----------------
    float* scaleF = (float*)(smem + SOFF_SCALE);
    for (int task = tid; task < 288; task += 256) {
        int cap = task >= 144;
        int j = task - cap * 144;
        const float* p = S + (cap * 64) * SSTRIDE + j;
        float ssum = 0.f;
#pragma unroll 8
        for (int w = 0; w < 64; w++) {
            float v = p[w * SSTRIDE];
            v = (v < 0.f) ? LEAK * v : v;
            ssum += v * v;
        }
        scaleF[cap * 144 + j] = SMOOTH / (sqrtf(ssum) + EPSV);
    }
    __syncthreads();

    // ---------------- per-row epilogue (threads 0..127, row = tid) ----------
    if (tid < 128) {
        const int cap = tid >> 6;
        const int word = tid & 63;
        const int mylen = cap_lens[c0 + cap];
        const bool valid = word < mylen;
        const float myw1 = ((const float*)(smem + SOFF_W1))[tid];
        const float* Srow = S + tid * SSTRIDE;
        float* wp = (float*)(smem + SOFF_WP);

#pragma unroll
        for (int blk = 0; blk < 4; blk++) {
            const float* scl = scaleF + cap * 144 + blk * 36;
            float raw[36], e[36];
            {
                const float4* p4 = (const float4*)(Srow + blk * 36);
#pragma unroll
                for (int q = 0; q < 9; q++) {
                    float4 v = p4[q];
                    raw[q * 4 + 0] = v.x; raw[q * 4 + 1] = v.y;
                    raw[q * 4 + 2] = v.z; raw[q * 4 + 3] = v.w;
                }
            }
            float se = 0.f;
#pragma unroll
            for (int r = 0; r < 36; r++) {
                float v = raw[r];
                float l = ((v < 0.f) ? LEAK * v : v) * scl[r];
                e[r] = __expf(l);
                se += e[r];
            }
            float inv = 1.f / se;
            float w12 = 0.f;
#pragma unroll
            for (int r = 0; r < 36; r++) w12 += e[r] * raw[r];
            w12 *= inv;

            const float4* G4 = (const float4*)(smem + SOFF_G) + blk * NREG * 10;
            float t = 0.f;
#pragma unroll
            for (int r = 0; r < 36; r++) {
                const float4* grow = G4 + r * 10;
                float dot = 0.f;
#pragma unroll
                for (int q = 0; q < 9; q++) {
                    float4 g = grow[q];
                    dot += g.x * e[q * 4] + g.y * e[q * 4 + 1] +
                           g.z * e[q * 4 + 2] + g.w * e[q * 4 + 3];
                }
                t += e[r] * dot;
            }
            float w2 = sqrtf(t) * inv;
            float sim = w12 / fmaxf(myw1 * w2, EPSV);
            sim = valid ? sim : 0.f;

            float s = warpSum(sim);
            if (lane == 0) wp[wid * 4 + blk] = s;
        }
    }
    __syncthreads();
    if (tid < 8) {
        int blk = tid & 3, cc = tid >> 2;
        float* wp = (float*)(smem + SOFF_WP);
        float s = wp[(cc * 2) * 4 + blk] + wp[(cc * 2 + 1) * 4 + blk];
        out[(size_t)(i0 + blk) * NCAP + (c0 + cc)] = s / (float)cap_lens[c0 + cc];
    }
}

// ---------------------------------------------------------------------------
extern "C" void kernel_launch(void* const* d_in, const int* in_sizes, int n_in,
                              void* d_out, int out_size) {
    const float* imgs     = (const float*)d_in[0];
    const float* caps     = (const float*)d_in[1];
    const int*   cap_lens = (const int*)d_in[3];
    float*       out      = (float*)d_out;

    split_caps_kernel<<<NCAP * CAPW * DIM / 4 / 256, 256>>>(caps, cap_lens);
    split_imgs_kernel<<<NIMG * NREG * DIM / 4 / 256, 256>>>(imgs);
    gram_kernel<<<NIMG, 256>>>(imgs);
    w1_kernel<<<NCAP, 256>>>(caps, cap_lens);

    cudaFuncSetAttribute(main_kernel, cudaFuncAttributeMaxDynamicSharedMemorySize,
                         SMEM_TOTAL_MAIN);
    dim3 grid(NIMG / 4, NCAP / 2);
    main_kernel<<<grid, 256, SMEM_TOTAL_MAIN>>>(cap_lens, out);
}

// round 4
// speedup vs baseline: 3.3271x; 1.1595x over previous
#include <cuda_runtime.h>
#include <cuda_bf16.h>
#include <cstdint>
#include <math.h>

#define NIMG 256
#define NREG 36
#define NCAP 256
#define MAXW 60
#define CAPW 64
#define DIM  1024

#define SMOOTH 9.0f
#define EPSV   1e-8f
#define LEAK   0.1f

// ---------------------------------------------------------------------------
// Device global scratch
// ---------------------------------------------------------------------------
__device__ __nv_bfloat16 g_caps_hi[NCAP * CAPW * DIM];
__device__ __nv_bfloat16 g_caps_lo[NCAP * CAPW * DIM];
__device__ __nv_bfloat16 g_imgs_hi[NIMG * NREG * DIM];
__device__ __nv_bfloat16 g_imgs_lo[NIMG * NREG * DIM];
__device__ float g_G[NIMG * NREG * NREG];
__device__ float g_w1[NCAP * MAXW];

// ---------------------------------------------------------------------------
// Helpers (arch-portable PTX only: sm_80+, nothing 'a'-gated)
// ---------------------------------------------------------------------------
__device__ __forceinline__ uint32_t smem_to_u32(const void* p) {
    uint32_t a;
    asm("{ .reg .u64 t; cvta.to.shared.u64 t, %1; cvt.u32.u64 %0, t; }"
        : "=r"(a) : "l"(p));
    return a;
}
__device__ __forceinline__ void cp16(uint32_t dst, const void* src) {
    asm volatile("cp.async.cg.shared.global [%0], [%1], 16;" :: "r"(dst), "l"(src) : "memory");
}
__device__ __forceinline__ void ldsm_x4(uint32_t &r0, uint32_t &r1, uint32_t &r2,
                                        uint32_t &r3, uint32_t addr) {
    asm volatile("ldmatrix.sync.aligned.m8n8.x4.shared.b16 {%0,%1,%2,%3}, [%4];"
                 : "=r"(r0), "=r"(r1), "=r"(r2), "=r"(r3) : "r"(addr));
}
__device__ __forceinline__ void ldsm_x2(uint32_t &r0, uint32_t &r1, uint32_t addr) {
    asm volatile("ldmatrix.sync.aligned.m8n8.x2.shared.b16 {%0,%1}, [%2];"
                 : "=r"(r0), "=r"(r1) : "r"(addr));
}
__device__ __forceinline__ void mma_bf16(float &c0, float &c1, float &c2, float &c3,
                                         uint32_t a0, uint32_t a1, uint32_t a2, uint32_t a3,
                                         uint32_t b0, uint32_t b1) {
    asm volatile("mma.sync.aligned.m16n8k16.row.col.f32.bf16.bf16.f32 "
                 "{%0,%1,%2,%3}, {%4,%5,%6,%7}, {%8,%9}, {%0,%1,%2,%3};"
                 : "+f"(c0), "+f"(c1), "+f"(c2), "+f"(c3)
                 : "r"(a0), "r"(a1), "r"(a2), "r"(a3), "r"(b0), "r"(b1));
}
__device__ __forceinline__ float warpSum(float v) {
    v += __shfl_xor_sync(0xffffffffu, v, 16);
    v += __shfl_xor_sync(0xffffffffu, v, 8);
    v += __shfl_xor_sync(0xffffffffu, v, 4);
    v += __shfl_xor_sync(0xffffffffu, v, 2);
    v += __shfl_xor_sync(0xffffffffu, v, 1);
    return v;
}

// ---------------------------------------------------------------------------
// Prep 1: caps -> hi/lo split (masked, padded to 64 words) + per-word norms
// grid = NCAP, block = 256 (8 warps, warp per word)
// ---------------------------------------------------------------------------
__global__ void prep_caps_kernel(const float* __restrict__ caps,
                                 const int* __restrict__ cap_lens) {
    const int c = blockIdx.x;
    const int wid = threadIdx.x >> 5, lane = threadIdx.x & 31;
    const int len = cap_lens[c];
    for (int w = wid; w < CAPW; w += 8) {
        size_t dsto = ((size_t)c * CAPW + w) * DIM;
        if (w < len) {
            const float* row = caps + ((size_t)c * MAXW + w) * DIM;
            float ss = 0.f;
#pragma unroll
            for (int j = 0; j < 8; j++) {
                float4 v = *(const float4*)(row + j * 128 + lane * 4);
                ss += v.x * v.x + v.y * v.y + v.z * v.z + v.w * v.w;
                __nv_bfloat16 hx = __float2bfloat16(v.x), hy = __float2bfloat16(v.y);
                __nv_bfloat16 hz = __float2bfloat16(v.z), hw = __float2bfloat16(v.w);
                float lx = v.x - __bfloat162float(hx), ly = v.y - __bfloat162float(hy);
                float lz = v.z - __bfloat162float(hz), lw = v.w - __bfloat162float(hw);
                size_t o = dsto + j * 128 + lane * 4;
                *(__nv_bfloat162*)(g_caps_hi + o)     = __nv_bfloat162(hx, hy);
                *(__nv_bfloat162*)(g_caps_hi + o + 2) = __nv_bfloat162(hz, hw);
                *(__nv_bfloat162*)(g_caps_lo + o)     = __floats2bfloat162_rn(lx, ly);
                *(__nv_bfloat162*)(g_caps_lo + o + 2) = __floats2bfloat162_rn(lz, lw);
            }
            ss = warpSum(ss);
            if (lane == 0 && w < MAXW) g_w1[c * MAXW + w] = sqrtf(ss);
        } else {
            uint2 z = make_uint2(0u, 0u);
#pragma unroll
            for (int j = 0; j < 8; j++) {
                size_t o = dsto + j * 128 + lane * 4;
                *(uint2*)(g_caps_hi + o) = z;
                *(uint2*)(g_caps_lo + o) = z;
            }
            if (lane == 0 && w < MAXW) g_w1[c * MAXW + w] = 0.f;
        }
    }
}

// ---------------------------------------------------------------------------
// Prep 2: imgs -> hi/lo split + per-image Gram matrix (fp32, exact)
// grid = NIMG, block = 256
// ---------------------------------------------------------------------------
__global__ void prep_imgs_kernel(const float* __restrict__ imgs) {
    const int i = blockIdx.x;
    __shared__ float chunk[NREG * 132];
    float acc[6];
#pragma unroll
    for (int j = 0; j < 6; j++) acc[j] = 0.f;

    for (int d0 = 0; d0 < DIM; d0 += 128) {
        __syncthreads();
        for (int idx = threadIdx.x; idx < NREG * 32; idx += 256) {
            int r = idx >> 5, dq = idx & 31;
            size_t e = ((size_t)i * NREG + r) * DIM + d0 + dq * 4;
            float4 v = *(const float4*)(imgs + e);
            *(float4*)(chunk + r * 132 + dq * 4) = v;
            __nv_bfloat16 hx = __float2bfloat16(v.x), hy = __float2bfloat16(v.y);
            __nv_bfloat16 hz = __float2bfloat16(v.z), hw = __float2bfloat16(v.w);
            float lx = v.x - __bfloat162float(hx), ly = v.y - __bfloat162float(hy);
            float lz = v.z - __bfloat162float(hz), lw = v.w - __bfloat162float(hw);
            *(__nv_bfloat162*)(g_imgs_hi + e)     = __nv_bfloat162(hx, hy);
            *(__nv_bfloat162*)(g_imgs_hi + e + 2) = __nv_bfloat162(hz, hw);
            *(__nv_bfloat162*)(g_imgs_lo + e)     = __floats2bfloat162_rn(lx, ly);
            *(__nv_bfloat162*)(g_imgs_lo + e + 2) = __floats2bfloat162_rn(lz, lw);
        }
        __syncthreads();
#pragma unroll
        for (int j = 0; j < 6; j++) {
            int p = threadIdx.x + j * 256;
            if (p < NREG * NREG) {
                int r = p / NREG, rp = p - r * NREG;
                const float4* A = (const float4*)(chunk + r * 132);
                const float4* B = (const float4*)(chunk + rp * 132);
                float s = 0.f;
#pragma unroll
                for (int q = 0; q < 32; q++) {
                    float4 a = A[q], b = B[q];
                    s += a.x * b.x + a.y * b.y + a.z * b.z + a.w * b.w;
                }
                acc[j] += s;
            }
        }
    }
#pragma unroll
    for (int j = 0; j < 6; j++) {
        int p = threadIdx.x + j * 256;
        if (p < NREG * NREG) g_G[(size_t)i * NREG * NREG + p] = acc[j];
    }
}

// ---------------------------------------------------------------------------
// Main fused kernel: HMMA GEMM M=128, N=144, K=3072 (split-bf16) + epilogue
// Warp tiling: 8 warps = 4 m-strips (32 rows) x 2 n-halves (72 cols); 72 acc.
// ---------------------------------------------------------------------------
#define SA0 0
#define SB0 18432
#define SA1 39168
#define SB1 57600
#define SOFF_G     78336
#define SOFF_W1    101376
#define SOFF_SCALE 101888
#define SOFF_WP    103040
#define SMEM_TOTAL_MAIN 103104
#define NCHUNK 48
#define ASTRIDE 144   // bytes per A/B smem row (64 bf16 + 8 pad)
#define SSTRIDE 148   // floats per S row

__device__ __forceinline__ void load_stage(uint32_t sb, int chunk, int tid,
                                           int arowbase, int browbase) {
    int p = chunk >> 4;                 // pass: 0 hi*hi, 1 hi*lo, 2 lo*hi
    int k0 = (chunk & 15) << 6;
    const __nv_bfloat16* Abase = (p == 2) ? g_caps_lo : g_caps_hi;
    const __nv_bfloat16* Bbase = (p == 1) ? g_imgs_lo : g_imgs_hi;
    uint32_t sA = sb + ((chunk & 1) ? SA1 : SA0);
    uint32_t sB = sb + ((chunk & 1) ? SB1 : SB0);
#pragma unroll
    for (int t = 0; t < 4; t++) {
        int o = tid + t * 256;
        int row = o >> 3, seg = o & 7;
        cp16(sA + row * ASTRIDE + seg * 16,
             Abase + (((size_t)(arowbase + row)) << 10) + k0 + (seg << 3));
    }
#pragma unroll
    for (int t = 0; t < 4; t++) {
        int o = tid + t * 256;
        int row = o >> 3, seg = o & 7;
        cp16(sB + row * ASTRIDE + seg * 16,
             Bbase + (((size_t)(browbase + row)) << 10) + k0 + (seg << 3));
    }
    {   // B tail rows 128..143
        int o = tid + 1024;
        if (o < 1152) {
            int row = o >> 3, seg = o & 7;
            cp16(sB + row * ASTRIDE + seg * 16,
                 Bbase + (((size_t)(browbase + row)) << 10) + k0 + (seg << 3));
        }
    }
    asm volatile("cp.async.commit_group;" ::: "memory");
}

__global__ void __launch_bounds__(256, 2)
main_kernel(const int* __restrict__ cap_lens, float* __restrict__ out) {
    extern __shared__ __align__(16) char smem[];
    const uint32_t sb = smem_to_u32(smem);
    const int tid = threadIdx.x, lane = tid & 31, wid = tid >> 5;
    const int c0 = blockIdx.y * 2;
    const int i0 = blockIdx.x * 4;
    const int arowbase = blockIdx.y * 128;
    const int browbase = blockIdx.x * 144;

    // stage Gram (40-float stride) + caption norms
    {
        float* Gs = (float*)(smem + SOFF_G);
        if (tid < 4 * NREG) {
            int blk = tid / NREG, r = tid - blk * NREG;
            const float4* src = (const float4*)(g_G + ((size_t)(i0 + blk) * NREG + r) * NREG);
            float4* dst = (float4*)(Gs + (blk * NREG + r) * 40);
#pragma unroll
            for (int q = 0; q < 9; q++) dst[q] = src[q];
        }
        float* w1s = (float*)(smem + SOFF_W1);
        if (tid < 128) {
            int cc = tid >> 6, w = tid & 63;
            w1s[tid] = (w < MAXW) ? g_w1[(c0 + cc) * MAXW + w] : 0.f;
        }
    }

    // ---------------- pipelined HMMA GEMM ----------------
    float acc[72];
#pragma unroll
    for (int j = 0; j < 72; j++) acc[j] = 0.f;

    load_stage(sb, 0, tid, arowbase, browbase);
    load_stage(sb, 1, tid, arowbase, browbase);

    // warp tile: rows mbase..mbase+31, cols ncb..ncb+71
    const int mbase = (wid & 3) * 32;
    const int ncb = (wid >> 2) * 72;
    // ldmatrix lane addressing
    const int a_roff = lane & 15;
    const int a_kad  = (lane >> 4) << 3;
    const int b_roff = ((lane >> 4) << 3) + (lane & 7);      // x4
    const int b_kad  = ((lane >> 3) & 1) << 3;               // x4
    const int l16 = lane & 15;
    const int b2_roff = l16 & 7;                              // x2
    const int b2_kad  = ((l16 >> 3) & 1) << 3;                // x2

    for (int i = 0; i < NCHUNK; i++) {
        const int s = i & 1;
        if (i == NCHUNK - 1) asm volatile("cp.async.wait_group 0;" ::: "memory");
        else                 asm volatile("cp.async.wait_group 1;" ::: "memory");
        __syncthreads();

        uint32_t Asm = sb + (s ? SA1 : SA0);
        uint32_t Bsm = sb + (s ? SB1 : SB0);
#pragma unroll
        for (int ks = 0; ks < 4; ks++) {
            const int kbyte = (ks * 16) * 2;
            uint32_t a[2][4];
#pragma unroll
            for (int s2 = 0; s2 < 2; s2++)
                ldsm_x4(a[s2][0], a[s2][1], a[s2][2], a[s2][3],
                        Asm + (mbase + s2 * 16 + a_roff) * ASTRIDE + kbyte + a_kad * 2);
#pragma unroll
            for (int t = 0; t < 4; t++) {
                uint32_t b0, b1, b2, b3;
                ldsm_x4(b0, b1, b2, b3,
                        Bsm + (ncb + t * 16 + b_roff) * ASTRIDE + kbyte + b_kad * 2);
#pragma unroll
                for (int s2 = 0; s2 < 2; s2++) {
                    int j0 = s2 * 36 + t * 8;
                    mma_bf16(acc[j0 + 0], acc[j0 + 1], acc[j0 + 2], acc[j0 + 3],
                             a[s2][0], a[s2][1], a[s2][2], a[s2][3], b0, b1);
                    mma_bf16(acc[j0 + 4], acc[j0 + 5], acc[j0 + 6], acc[j0 + 7],
                             a[s2][0], a[s2][1], a[s2][2], a[s2][3], b2, b3);
                }
            }
            {   // half tile: cols ncb+64..71
                uint32_t b0, b1;
                ldsm_x2(b0, b1,
                        Bsm + (ncb + 64 + b2_roff) * ASTRIDE + kbyte + b2_kad * 2);
#pragma unroll
                for (int s2 = 0; s2 < 2; s2++) {
                    int j0 = s2 * 36 + 32;
                    mma_bf16(acc[j0 + 0], acc[j0 + 1], acc[j0 + 2], acc[j0 + 3],
                             a[s2][0], a[s2][1], a[s2][2], a[s2][3], b0, b1);
                }
            }
        }
        __syncthreads();
        if (i + 2 < NCHUNK)
            load_stage(sb, i + 2, tid, arowbase, browbase);
    }

    // ---------------- write S to shared ----------------
    float* S = (float*)smem;
    {
        const int cA = (lane & 3) * 2;
        const int rA = lane >> 2;
#pragma unroll
        for (int s2 = 0; s2 < 2; s2++) {
            int r1 = mbase + s2 * 16 + rA;
#pragma unroll
            for (int j = 0; j < 9; j++) {
                int col = ncb + j * 8 + cA;
                *(float2*)(S + r1 * SSTRIDE + col) =
                    make_float2(acc[s2 * 36 + j * 4 + 0], acc[s2 * 36 + j * 4 + 1]);
                *(float2*)(S + (r1 + 8) * SSTRIDE + col) =
                    make_float2(acc[s2 * 36 + j * 4 + 2], acc[s2 * 36 + j * 4 + 3]);
            }
        }
    }
    __syncthreads();

    // ---------------- column norms -> scale ----------------
    float* scaleF = (float*)(smem + SOFF_SCALE);
    for (int task = tid; task < 288; task += 256) {
        int cap = task >= 144;
        int j = task - cap * 144;
        const float* p = S + (cap * 64) * SSTRIDE + j;
        float ssum = 0.f;
#pragma unroll 8
        for (int w = 0; w < 64; w++) {
            float v = p[w * SSTRIDE];
            v = (v < 0.f) ? LEAK * v : v;
            ssum += v * v;
        }
        scaleF[cap * 144 + j] = SMOOTH / (sqrtf(ssum) + EPSV);
    }
    __syncthreads();

    // ---------------- per-row epilogue (threads 0..127) ----------------
    if (tid < 128) {
        const int cap = tid >> 6;
        const int word = tid & 63;
        const int mylen = cap_lens[c0 + cap];
        const bool valid = word < mylen;
        const float myw1 = ((const float*)(smem + SOFF_W1))[tid];
        const float* Srow = S + tid * SSTRIDE;
        float* wp = (float*)(smem + SOFF_WP);

#pragma unroll
        for (int blk = 0; blk < 4; blk++) {
            const float* scl = scaleF + cap * 144 + blk * 36;
            float raw[36], e[36];
            {
                const float4* p4 = (const float4*)(Srow + blk * 36);
#pragma unroll
                for (int q = 0; q < 9; q++) {
                    float4 v = p4[q];
                    raw[q * 4 + 0] = v.x; raw[q * 4 + 1] = v.y;
                    raw[q * 4 + 2] = v.z; raw[q * 4 + 3] = v.w;
                }
            }
            float se = 0.f;
#pragma unroll
            for (int r = 0; r < 36; r++) {
                float v = raw[r];
                float l = ((v < 0.f) ? LEAK * v : v) * scl[r];
                e[r] = __expf(l);
                se += e[r];
            }
            float inv = 1.f / se;
            float w12 = 0.f;
#pragma unroll
            for (int r = 0; r < 36; r++) w12 += e[r] * raw[r];
            w12 *= inv;

            const float4* G4 = (const float4*)(smem + SOFF_G) + blk * NREG * 10;
            float t = 0.f;
#pragma unroll
            for (int r = 0; r < 36; r++) {
                const float4* grow = G4 + r * 10;
                float dot = 0.f;
#pragma unroll
                for (int q = 0; q < 9; q++) {
                    float4 g = grow[q];
                    dot += g.x * e[q * 4] + g.y * e[q * 4 + 1] +
                           g.z * e[q * 4 + 2] + g.w * e[q * 4 + 3];
                }
                t += e[r] * dot;
            }
            float w2 = sqrtf(t) * inv;
            float sim = w12 / fmaxf(myw1 * w2, EPSV);
            sim = valid ? sim : 0.f;

            float s = warpSum(sim);
            if (lane == 0) wp[wid * 4 + blk] = s;
        }
    }
    __syncthreads();
    if (tid < 8) {
        int blk = tid & 3, cc = tid >> 2;
        float* wp = (float*)(smem + SOFF_WP);
        float s = wp[(cc * 2) * 4 + blk] + wp[(cc * 2 + 1) * 4 + blk];
        out[(size_t)(i0 + blk) * NCAP + (c0 + cc)] = s / (float)cap_lens[c0 + cc];
    }
}

// ---------------------------------------------------------------------------
extern "C" void kernel_launch(void* const* d_in, const int* in_sizes, int n_in,
                              void* d_out, int out_size) {
    const float* imgs     = (const float*)d_in[0];
    const float* caps     = (const float*)d_in[1];
    const int*   cap_lens = (const int*)d_in[3];
    float*       out      = (float*)d_out;

    prep_caps_kernel<<<NCAP, 256>>>(caps, cap_lens);
    prep_imgs_kernel<<<NIMG, 256>>>(imgs);

    cudaFuncSetAttribute(main_kernel, cudaFuncAttributeMaxDynamicSharedMemorySize,
                         SMEM_TOTAL_MAIN);
    dim3 grid(NIMG / 4, NCAP / 2);
    main_kernel<<<grid, 256, SMEM_TOTAL_MAIN>>>(cap_lens, out);
}

// round 5
// speedup vs baseline: 5.1800x; 1.5569x over previous
#include <cuda_runtime.h>
#include <cuda_fp16.h>
#include <cstdint>
#include <math.h>

#define NIMG 256
#define NREG 36
#define NCAP 256
#define MAXW 60
#define CAPW 64
#define DIM  1024

#define SMOOTH 9.0f
#define EPSV   1e-8f
#define LEAK   0.1f

// ---------------------------------------------------------------------------
// Device global scratch
// ---------------------------------------------------------------------------
__device__ __half g_caps_hi[NCAP * CAPW * DIM];
__device__ __half g_caps_lo[NCAP * CAPW * DIM];
__device__ __half g_imgs_h[NIMG * NREG * DIM];
__device__ float g_G[NIMG * NREG * NREG];
__device__ float g_w1[NCAP * MAXW];

// ---------------------------------------------------------------------------
// Helpers (arch-portable PTX only: sm_80+, nothing 'a'-gated)
// ---------------------------------------------------------------------------
__device__ __forceinline__ uint32_t smem_to_u32(const void* p) {
    uint32_t a;
    asm("{ .reg .u64 t; cvta.to.shared.u64 t, %1; cvt.u32.u64 %0, t; }"
        : "=r"(a) : "l"(p));
    return a;
}
__device__ __forceinline__ void cp16(uint32_t dst, const void* src) {
    asm volatile("cp.async.cg.shared.global [%0], [%1], 16;" :: "r"(dst), "l"(src) : "memory");
}
__device__ __forceinline__ void ldsm_x4(uint32_t &r0, uint32_t &r1, uint32_t &r2,
                                        uint32_t &r3, uint32_t addr) {
    asm volatile("ldmatrix.sync.aligned.m8n8.x4.shared.b16 {%0,%1,%2,%3}, [%4];"
                 : "=r"(r0), "=r"(r1), "=r"(r2), "=r"(r3) : "r"(addr));
}
__device__ __forceinline__ void ldsm_x2(uint32_t &r0, uint32_t &r1, uint32_t addr) {
    asm volatile("ldmatrix.sync.aligned.m8n8.x2.shared.b16 {%0,%1}, [%2];"
                 : "=r"(r0), "=r"(r1) : "r"(addr));
}
__device__ __forceinline__ void mma_f16(float &c0, float &c1, float &c2, float &c3,
                                        uint32_t a0, uint32_t a1, uint32_t a2, uint32_t a3,
                                        uint32_t b0, uint32_t b1) {
    asm volatile("mma.sync.aligned.m16n8k16.row.col.f32.f16.f16.f32 "
                 "{%0,%1,%2,%3}, {%4,%5,%6,%7}, {%8,%9}, {%0,%1,%2,%3};"
                 : "+f"(c0), "+f"(c1), "+f"(c2), "+f"(c3)
                 : "r"(a0), "r"(a1), "r"(a2), "r"(a3), "r"(b0), "r"(b1));
}
__device__ __forceinline__ float warpSum(float v) {
    v += __shfl_xor_sync(0xffffffffu, v, 16);
    v += __shfl_xor_sync(0xffffffffu, v, 8);
    v += __shfl_xor_sync(0xffffffffu, v, 4);
    v += __shfl_xor_sync(0xffffffffu, v, 2);
    v += __shfl_xor_sync(0xffffffffu, v, 1);
    return v;
}

// ---------------------------------------------------------------------------
// Prep 1: caps -> fp16 hi/lo split (masked, padded to 64 words) + word norms
// ---------------------------------------------------------------------------
__global__ void prep_caps_kernel(const float* __restrict__ caps,
                                 const int* __restrict__ cap_lens) {
    const int c = blockIdx.x;
    const int wid = threadIdx.x >> 5, lane = threadIdx.x & 31;
    const int len = cap_lens[c];
    for (int w = wid; w < CAPW; w += 8) {
        size_t dsto = ((size_t)c * CAPW + w) * DIM;
        if (w < len) {
            const float* row = caps + ((size_t)c * MAXW + w) * DIM;
            float ss = 0.f;
#pragma unroll
            for (int j = 0; j < 8; j++) {
                float4 v = *(const float4*)(row + j * 128 + lane * 4);
                ss += v.x * v.x + v.y * v.y + v.z * v.z + v.w * v.w;
                __half hx = __float2half_rn(v.x), hy = __float2half_rn(v.y);
                __half hz = __float2half_rn(v.z), hw = __float2half_rn(v.w);
                float lx = v.x - __half2float(hx), ly = v.y - __half2float(hy);
                float lz = v.z - __half2float(hz), lw = v.w - __half2float(hw);
                size_t o = dsto + j * 128 + lane * 4;
                *(__half2*)(g_caps_hi + o)     = __half2(hx, hy);
                *(__half2*)(g_caps_hi + o + 2) = __half2(hz, hw);
                *(__half2*)(g_caps_lo + o)     = __floats2half2_rn(lx, ly);
                *(__half2*)(g_caps_lo + o + 2) = __floats2half2_rn(lz, lw);
            }
            ss = warpSum(ss);
            if (lane == 0 && w < MAXW) g_w1[c * MAXW + w] = sqrtf(ss);
        } else {
            uint2 z = make_uint2(0u, 0u);
#pragma unroll
            for (int j = 0; j < 8; j++) {
                size_t o = dsto + j * 128 + lane * 4;
                *(uint2*)(g_caps_hi + o) = z;
                *(uint2*)(g_caps_lo + o) = z;
            }
            if (lane == 0 && w < MAXW) g_w1[c * MAXW + w] = 0.f;
        }
    }
}

// ---------------------------------------------------------------------------
// Prep 2: imgs -> fp16 (hi only) + per-image Gram matrix (fp32, exact)
// ---------------------------------------------------------------------------
__global__ void prep_imgs_kernel(const float* __restrict__ imgs) {
    const int i = blockIdx.x;
    __shared__ float chunk[NREG * 132];
    float acc[6];
#pragma unroll
    for (int j = 0; j < 6; j++) acc[j] = 0.f;

    for (int d0 = 0; d0 < DIM; d0 += 128) {
        __syncthreads();
        for (int idx = threadIdx.x; idx < NREG * 32; idx += 256) {
            int r = idx >> 5, dq = idx & 31;
            size_t e = ((size_t)i * NREG + r) * DIM + d0 + dq * 4;
            float4 v = *(const float4*)(imgs + e);
            *(float4*)(chunk + r * 132 + dq * 4) = v;
            *(__half2*)(g_imgs_h + e)     = __floats2half2_rn(v.x, v.y);
            *(__half2*)(g_imgs_h + e + 2) = __floats2half2_rn(v.z, v.w);
        }
        __syncthreads();
#pragma unroll
        for (int j = 0; j < 6; j++) {
            int p = threadIdx.x + j * 256;
            if (p < NREG * NREG) {
                int r = p / NREG, rp = p - r * NREG;
                const float4* A = (const float4*)(chunk + r * 132);
                const float4* B = (const float4*)(chunk + rp * 132);
                float s = 0.f;
#pragma unroll
                for (int q = 0; q < 32; q++) {
                    float4 a = A[q], b = B[q];
                    s += a.x * b.x + a.y * b.y + a.z * b.z + a.w * b.w;
                }
                acc[j] += s;
            }
        }
    }
#pragma unroll
    for (int j = 0; j < 6; j++) {
        int p = threadIdx.x + j * 256;
        if (p < NREG * NREG) g_G[(size_t)i * NREG * NREG + p] = acc[j];
    }
}

// ---------------------------------------------------------------------------
// Main fused kernel: fp16 split GEMM (M=128, N=144, K=1024, 2 A-passes that
// share each B tile) + fused SCAN epilogue.
// Shared memory during GEMM (bytes):
//   [0,18432)        A-hi stage 0      [18432,36864)  A-lo stage 0
//   [36864,57600)    B stage 0
//   [57600,76032)    A-hi stage 1      [76032,94464)  A-lo stage 1
//   [94464,115200)   B stage 1
// After GEMM (reuse):
//   [0,75776)        S (128 x 148 f32)
//   [75776,76928)    scale  [76928,77440) w1  [77440,77504) wp
//   [77504,100544)   Gram (4 x 36 x 40 f32)
// ---------------------------------------------------------------------------
#define SA_HI0 0
#define SA_LO0 18432
#define SB0    36864
#define SA_HI1 57600
#define SA_LO1 76032
#define SB1    94464
#define SOFF_SCALE 75776
#define SOFF_W1    76928
#define SOFF_WP    77440
#define SOFF_G     77504
#define SMEM_TOTAL_MAIN 115200
#define NCHUNK 16
#define ASTRIDE 144   // bytes per smem row (64 fp16 + 8 pad)
#define SSTRIDE 148   // floats per S row

__device__ __forceinline__ void load_stage(uint32_t sb, int chunk, int tid,
                                           int arowbase, int browbase) {
    int k0 = chunk << 6;
    uint32_t sAh = sb + ((chunk & 1) ? SA_HI1 : SA_HI0);
    uint32_t sAl = sb + ((chunk & 1) ? SA_LO1 : SA_LO0);
    uint32_t sB  = sb + ((chunk & 1) ? SB1 : SB0);
#pragma unroll
    for (int t = 0; t < 4; t++) {
        int o = tid + t * 256;
        int row = o >> 3, seg = o & 7;
        size_t go = (((size_t)(arowbase + row)) << 10) + k0 + (seg << 3);
        uint32_t so = row * ASTRIDE + seg * 16;
        cp16(sAh + so, g_caps_hi + go);
        cp16(sAl + so, g_caps_lo + go);
    }
#pragma unroll
    for (int t = 0; t < 4; t++) {
        int o = tid + t * 256;
        int row = o >> 3, seg = o & 7;
        cp16(sB + row * ASTRIDE + seg * 16,
             g_imgs_h + (((size_t)(browbase + row)) << 10) + k0 + (seg << 3));
    }
    {   // B tail rows 128..143
        int o = tid + 1024;
        if (o < 1152) {
            int row = o >> 3, seg = o & 7;
            cp16(sB + row * ASTRIDE + seg * 16,
                 g_imgs_h + (((size_t)(browbase + row)) << 10) + k0 + (seg << 3));
        }
    }
    asm volatile("cp.async.commit_group;" ::: "memory");
}

__global__ void __launch_bounds__(256, 2)
main_kernel(const int* __restrict__ cap_lens, float* __restrict__ out) {
    extern __shared__ __align__(16) char smem[];
    const uint32_t sb = smem_to_u32(smem);
    const int tid = threadIdx.x, lane = tid & 31, wid = tid >> 5;
    const int c0 = blockIdx.y * 2;
    const int i0 = blockIdx.x * 4;
    const int arowbase = blockIdx.y * 128;
    const int browbase = blockIdx.x * 144;

    // ---------------- pipelined fp16 HMMA GEMM ----------------
    float acc[72];
#pragma unroll
    for (int j = 0; j < 72; j++) acc[j] = 0.f;

    load_stage(sb, 0, tid, arowbase, browbase);
    load_stage(sb, 1, tid, arowbase, browbase);

    // warp tile: rows mbase..mbase+31, cols ncb..ncb+71
    const int mbase = (wid & 3) * 32;
    const int ncb = (wid >> 2) * 72;
    const int a_roff = lane & 15;
    const int a_kad  = (lane >> 4) << 3;
    const int b_roff = ((lane >> 4) << 3) + (lane & 7);
    const int b_kad  = ((lane >> 3) & 1) << 3;
    const int l16 = lane & 15;
    const int b2_roff = l16 & 7;
    const int b2_kad  = ((l16 >> 3) & 1) << 3;

    for (int i = 0; i < NCHUNK; i++) {
        const int s = i & 1;
        if (i == NCHUNK - 1) asm volatile("cp.async.wait_group 0;" ::: "memory");
        else                 asm volatile("cp.async.wait_group 1;" ::: "memory");
        __syncthreads();

        uint32_t Ah = sb + (s ? SA_HI1 : SA_HI0);
        uint32_t Al = sb + (s ? SA_LO1 : SA_LO0);
        uint32_t Bs = sb + (s ? SB1 : SB0);
#pragma unroll
        for (int ks = 0; ks < 4; ks++) {
            const int kbyte = ks * 32;
            uint32_t ah[2][4], al[2][4];
#pragma unroll
            for (int s2 = 0; s2 < 2; s2++) {
                uint32_t ao = (mbase + s2 * 16 + a_roff) * ASTRIDE + kbyte + a_kad * 2;
                ldsm_x4(ah[s2][0], ah[s2][1], ah[s2][2], ah[s2][3], Ah + ao);
                ldsm_x4(al[s2][0], al[s2][1], al[s2][2], al[s2][3], Al + ao);
            }
#pragma unroll
            for (int t = 0; t < 4; t++) {
                uint32_t b0, b1, b2, b3;
                ldsm_x4(b0, b1, b2, b3,
                        Bs + (ncb + t * 16 + b_roff) * ASTRIDE + kbyte + b_kad * 2);
#pragma unroll
                for (int s2 = 0; s2 < 2; s2++) {
                    int j0 = s2 * 36 + t * 8;
                    mma_f16(acc[j0 + 0], acc[j0 + 1], acc[j0 + 2], acc[j0 + 3],
                            ah[s2][0], ah[s2][1], ah[s2][2], ah[s2][3], b0, b1);
                    mma_f16(acc[j0 + 4], acc[j0 + 5], acc[j0 + 6], acc[j0 + 7],
                            ah[s2][0], ah[s2][1], ah[s2][2], ah[s2][3], b2, b3);
                    mma_f16(acc[j0 + 0], acc[j0 + 1], acc[j0 + 2], acc[j0 + 3],
                            al[s2][0], al[s2][1], al[s2][2], al[s2][3], b0, b1);
                    mma_f16(acc[j0 + 4], acc[j0 + 5], acc[j0 + 6], acc[j0 + 7],
                            al[s2][0], al[s2][1], al[s2][2], al[s2][3], b2, b3);
                }
            }
            {   // half tile: cols ncb+64..71
                uint32_t b0, b1;
                ldsm_x2(b0, b1,
                        Bs + (ncb + 64 + b2_roff) * ASTRIDE + kbyte + b2_kad * 2);
#pragma unroll
                for (int s2 = 0; s2 < 2; s2++) {
                    int j0 = s2 * 36 + 32;
                    mma_f16(acc[j0 + 0], acc[j0 + 1], acc[j0 + 2], acc[j0 + 3],
                            ah[s2][0], ah[s2][1], ah[s2][2], ah[s2][3], b0, b1);
                    mma_f16(acc[j0 + 0], acc[j0 + 1], acc[j0 + 2], acc[j0 + 3],
                            al[s2][0], al[s2][1], al[s2][2], al[s2][3], b0, b1);
                }
            }
        }
        __syncthreads();
        if (i + 2 < NCHUNK)
            load_stage(sb, i + 2, tid, arowbase, browbase);
    }

    // ---------------- write S to shared + stage Gram/w1 ----------------
    float* S = (float*)smem;
    {
        const int cA = (lane & 3) * 2;
        const int rA = lane >> 2;
#pragma unroll
        for (int s2 = 0; s2 < 2; s2++) {
            int r1 = mbase + s2 * 16 + rA;
#pragma unroll
            for (int j = 0; j < 9; j++) {
                int col = ncb + j * 8 + cA;
                *(float2*)(S + r1 * SSTRIDE + col) =
                    make_float2(acc[s2 * 36 + j * 4 + 0], acc[s2 * 36 + j * 4 + 1]);
                *(float2*)(S + (r1 + 8) * SSTRIDE + col) =
                    make_float2(acc[s2 * 36 + j * 4 + 2], acc[s2 * 36 + j * 4 + 3]);
            }
        }
    }
    {
        float* Gs = (float*)(smem + SOFF_G);
        if (tid < 4 * NREG) {
            int blk = tid / NREG, r = tid - blk * NREG;
            const float4* src = (const float4*)(g_G + ((size_t)(i0 + blk) * NREG + r) * NREG);
            float4* dst = (float4*)(Gs + (blk * NREG + r) * 40);
#pragma unroll
            for (int q = 0; q < 9; q++) dst[q] = src[q];
        }
        float* w1s = (float*)(smem + SOFF_W1);
        if (tid >= 128 && tid < 256) {
            int p = tid - 128;
            int cc = p >> 6, w = p & 63;
            w1s[p] = (w < MAXW) ? g_w1[(c0 + cc) * MAXW + w] : 0.f;
        }
    }
    __syncthreads();

    // ---------------- column norms -> scale ----------------
    float* scaleF = (float*)(smem + SOFF_SCALE);
    for (int task = tid; task < 288; task += 256) {
        int cap = task >= 144;
        int j = task - cap * 144;
        const float* p = S + (cap * 64) * SSTRIDE + j;
        float ssum = 0.f;
#pragma unroll 8
        for (int w = 0; w < 64; w++) {
            float v = p[w * SSTRIDE];
            v = (v < 0.f) ? LEAK * v : v;
            ssum += v * v;
        }
        scaleF[cap * 144 + j] = SMOOTH / (sqrtf(ssum) + EPSV);
    }
    __syncthreads();

    // ---------------- per-row epilogue (all 256 threads, 2 blks each) ------
    {
        const int row = tid & 127;
        const int half = tid >> 7;          // blks {half*2, half*2+1}
        const int cap = row >> 6;
        const int word = row & 63;
        const int mylen = cap_lens[c0 + cap];
        const bool valid = word < mylen;
        const float myw1 = ((const float*)(smem + SOFF_W1))[row];
        const float* Srow = S + row * SSTRIDE;
        float* wp = (float*)(smem + SOFF_WP);

#pragma unroll
        for (int bq = 0; bq < 2; bq++) {
            const int blk = half * 2 + bq;
            const float* scl = scaleF + cap * 144 + blk * 36;
            float raw[36], e[36];
            {
                const float4* p4 = (const float4*)(Srow + blk * 36);
#pragma unroll
                for (int q = 0; q < 9; q++) {
                    float4 v = p4[q];
                    raw[q * 4 + 0] = v.x; raw[q * 4 + 1] = v.y;
                    raw[q * 4 + 2] = v.z; raw[q * 4 + 3] = v.w;
                }
            }
            float se = 0.f;
#pragma unroll
            for (int r = 0; r < 36; r++) {
                float v = raw[r];
                float l = ((v < 0.f) ? LEAK * v : v) * scl[r];
                e[r] = __expf(l);
                se += e[r];
            }
            float inv = 1.f / se;
            float w12 = 0.f;
#pragma unroll
            for (int r = 0; r < 36; r++) w12 += e[r] * raw[r];
            w12 *= inv;

            const float4* G4 = (const float4*)(smem + SOFF_G) + blk * NREG * 10;
            float t = 0.f;
#pragma unroll
            for (int r = 0; r < 36; r++) {
                const float4* grow = G4 + r * 10;
                float dot = 0.f;
#pragma unroll
                for (int q = 0; q < 9; q++) {
                    float4 g = grow[q];
                    dot += g.x * e[q * 4] + g.y * e[q * 4 + 1] +
                           g.z * e[q * 4 + 2] + g.w * e[q * 4 + 3];
                }
                t += e[r] * dot;
            }
            float w2 = sqrtf(t) * inv;
            float sim = w12 / fmaxf(myw1 * w2, EPSV);
            sim = valid ? sim : 0.f;

            float ssum = warpSum(sim);
            if (lane == 0) wp[wid * 2 + bq] = ssum;
        }
    }
    __syncthreads();
    if (tid < 8) {
        int blk = tid & 3, cc = tid >> 2;
        int h = blk >> 1, b = blk & 1;
        float* wp = (float*)(smem + SOFF_WP);
        float s = wp[(h * 4 + cc * 2) * 2 + b] + wp[(h * 4 + cc * 2 + 1) * 2 + b];
        out[(size_t)(i0 + blk) * NCAP + (c0 + cc)] = s / (float)cap_lens[c0 + cc];
    }
}

// ---------------------------------------------------------------------------
extern "C" void kernel_launch(void* const* d_in, const int* in_sizes, int n_in,
                              void* d_out, int out_size) {
    const float* imgs     = (const float*)d_in[0];
    const float* caps     = (const float*)d_in[1];
    const int*   cap_lens = (const int*)d_in[3];
    float*       out      = (float*)d_out;

    prep_caps_kernel<<<NCAP, 256>>>(caps, cap_lens);
    prep_imgs_kernel<<<NIMG, 256>>>(imgs);

    cudaFuncSetAttribute(main_kernel, cudaFuncAttributeMaxDynamicSharedMemorySize,
                         SMEM_TOTAL_MAIN);
    dim3 grid(NIMG / 4, NCAP / 2);
    main_kernel<<<grid, 256, SMEM_TOTAL_MAIN>>>(cap_lens, out);
}

// round 6
// speedup vs baseline: 5.4427x; 1.0507x over previous
#include <cuda_runtime.h>
#include <cuda_fp16.h>
#include <cstdint>
#include <math.h>

#define NIMG 256
#define NREG 36
#define NCAP 256
#define MAXW 60
#define CAPW 64
#define DIM  1024

#define SMOOTH 9.0f
#define EPSV   1e-8f
#define LEAK   0.1f

// ---------------------------------------------------------------------------
// Device global scratch
// ---------------------------------------------------------------------------
__device__ __half g_caps_hi[NCAP * CAPW * DIM];
__device__ __half g_caps_lo[NCAP * CAPW * DIM];
__device__ __half g_imgs_h[NIMG * NREG * DIM];
__device__ float g_G[NIMG * NREG * NREG];
__device__ float g_w1[NCAP * MAXW];

// ---------------------------------------------------------------------------
// Helpers (arch-portable PTX: sm_80+ ops, plus f32x2 which is plain sm_100+)
// ---------------------------------------------------------------------------
__device__ __forceinline__ uint32_t smem_to_u32(const void* p) {
    uint32_t a;
    asm("{ .reg .u64 t; cvta.to.shared.u64 t, %1; cvt.u32.u64 %0, t; }"
        : "=r"(a) : "l"(p));
    return a;
}
__device__ __forceinline__ void cp16(uint32_t dst, const void* src) {
    asm volatile("cp.async.cg.shared.global [%0], [%1], 16;" :: "r"(dst), "l"(src) : "memory");
}
__device__ __forceinline__ void ldsm_x4(uint32_t &r0, uint32_t &r1, uint32_t &r2,
                                        uint32_t &r3, uint32_t addr) {
    asm volatile("ldmatrix.sync.aligned.m8n8.x4.shared.b16 {%0,%1,%2,%3}, [%4];"
                 : "=r"(r0), "=r"(r1), "=r"(r2), "=r"(r3) : "r"(addr));
}
__device__ __forceinline__ void ldsm_x2(uint32_t &r0, uint32_t &r1, uint32_t addr) {
    asm volatile("ldmatrix.sync.aligned.m8n8.x2.shared.b16 {%0,%1}, [%2];"
                 : "=r"(r0), "=r"(r1) : "r"(addr));
}
__device__ __forceinline__ void mma_f16(float &c0, float &c1, float &c2, float &c3,
                                        uint32_t a0, uint32_t a1, uint32_t a2, uint32_t a3,
                                        uint32_t b0, uint32_t b1) {
    asm volatile("mma.sync.aligned.m16n8k16.row.col.f32.f16.f16.f32 "
                 "{%0,%1,%2,%3}, {%4,%5,%6,%7}, {%8,%9}, {%0,%1,%2,%3};"
                 : "+f"(c0), "+f"(c1), "+f"(c2), "+f"(c3)
                 : "r"(a0), "r"(a1), "r"(a2), "r"(a3), "r"(b0), "r"(b1));
}
__device__ __forceinline__ unsigned long long pack2(float lo, float hi) {
    unsigned long long r;
    asm("mov.b64 %0, {%1, %2};" : "=l"(r) : "f"(lo), "f"(hi));
    return r;
}
__device__ __forceinline__ void unpack2(unsigned long long v, float &lo, float &hi) {
    asm("mov.b64 {%0, %1}, %2;" : "=f"(lo), "=f"(hi) : "l"(v));
}
__device__ __forceinline__ void ffma2(unsigned long long &d,
                                      unsigned long long a,
                                      unsigned long long b) {
    asm("fma.rn.f32x2 %0, %1, %2, %0;" : "+l"(d) : "l"(a), "l"(b));
}
__device__ __forceinline__ float warpSum(float v) {
    v += __shfl_xor_sync(0xffffffffu, v, 16);
    v += __shfl_xor_sync(0xffffffffu, v, 8);
    v += __shfl_xor_sync(0xffffffffu, v, 4);
    v += __shfl_xor_sync(0xffffffffu, v, 2);
    v += __shfl_xor_sync(0xffffffffu, v, 1);
    return v;
}

// ---------------------------------------------------------------------------
// Prep 1: caps -> fp16 hi/lo split (masked, padded to 64 words) + word norms
// ---------------------------------------------------------------------------
__global__ void prep_caps_kernel(const float* __restrict__ caps,
                                 const int* __restrict__ cap_lens) {
    const int c = blockIdx.x;
    const int wid = threadIdx.x >> 5, lane = threadIdx.x & 31;
    const int len = cap_lens[c];
    for (int w = wid; w < CAPW; w += 8) {
        size_t dsto = ((size_t)c * CAPW + w) * DIM;
        if (w < len) {
            const float* row = caps + ((size_t)c * MAXW + w) * DIM;
            float ss = 0.f;
#pragma unroll
            for (int j = 0; j < 8; j++) {
                float4 v = *(const float4*)(row + j * 128 + lane * 4);
                ss += v.x * v.x + v.y * v.y + v.z * v.z + v.w * v.w;
                __half hx = __float2half_rn(v.x), hy = __float2half_rn(v.y);
                __half hz = __float2half_rn(v.z), hw = __float2half_rn(v.w);
                float lx = v.x - __half2float(hx), ly = v.y - __half2float(hy);
                float lz = v.z - __half2float(hz), lw = v.w - __half2float(hw);
                size_t o = dsto + j * 128 + lane * 4;
                *(__half2*)(g_caps_hi + o)     = __half2(hx, hy);
                *(__half2*)(g_caps_hi + o + 2) = __half2(hz, hw);
                *(__half2*)(g_caps_lo + o)     = __floats2half2_rn(lx, ly);
                *(__half2*)(g_caps_lo + o + 2) = __floats2half2_rn(lz, lw);
            }
            ss = warpSum(ss);
            if (lane == 0 && w < MAXW) g_w1[c * MAXW + w] = sqrtf(ss);
        } else {
            uint2 z = make_uint2(0u, 0u);
#pragma unroll
            for (int j = 0; j < 8; j++) {
                size_t o = dsto + j * 128 + lane * 4;
                *(uint2*)(g_caps_hi + o) = z;
                *(uint2*)(g_caps_lo + o) = z;
            }
            if (lane == 0 && w < MAXW) g_w1[c * MAXW + w] = 0.f;
        }
    }
}

// ---------------------------------------------------------------------------
// Prep 2: imgs -> fp16 (hi only) + per-image Gram matrix (fp32, exact)
// ---------------------------------------------------------------------------
__global__ void prep_imgs_kernel(const float* __restrict__ imgs) {
    const int i = blockIdx.x;
    __shared__ float chunk[NREG * 132];
    float acc[6];
#pragma unroll
    for (int j = 0; j < 6; j++) acc[j] = 0.f;

    for (int d0 = 0; d0 < DIM; d0 += 128) {
        __syncthreads();
        for (int idx = threadIdx.x; idx < NREG * 32; idx += 256) {
            int r = idx >> 5, dq = idx & 31;
            size_t e = ((size_t)i * NREG + r) * DIM + d0 + dq * 4;
            float4 v = *(const float4*)(imgs + e);
            *(float4*)(chunk + r * 132 + dq * 4) = v;
            *(__half2*)(g_imgs_h + e)     = __floats2half2_rn(v.x, v.y);
            *(__half2*)(g_imgs_h + e + 2) = __floats2half2_rn(v.z, v.w);
        }
        __syncthreads();
#pragma unroll
        for (int j = 0; j < 6; j++) {
            int p = threadIdx.x + j * 256;
            if (p < NREG * NREG) {
                int r = p / NREG, rp = p - r * NREG;
                const float4* A = (const float4*)(chunk + r * 132);
                const float4* B = (const float4*)(chunk + rp * 132);
                float s = 0.f;
#pragma unroll
                for (int q = 0; q < 32; q++) {
                    float4 a = A[q], b = B[q];
                    s += a.x * b.x + a.y * b.y + a.z * b.z + a.w * b.w;
                }
                acc[j] += s;
            }
        }
    }
#pragma unroll
    for (int j = 0; j < 6; j++) {
        int p = threadIdx.x + j * 256;
        if (p < NREG * NREG) g_G[(size_t)i * NREG * NREG + p] = acc[j];
    }
}

// ---------------------------------------------------------------------------
// Main fused kernel: fp16 split GEMM (M=128, N=144, K=1024, hi+lo A passes
// sharing each B tile) + fused SCAN epilogue.
// ---------------------------------------------------------------------------
#define SA_HI0 0
#define SA_LO0 18432
#define SB0    36864
#define SA_HI1 57600
#define SA_LO1 76032
#define SB1    94464
#define SOFF_SCALE 75776
#define SOFF_W1    76928
#define SOFF_WP    77440
#define SOFF_G     77504
#define SMEM_TOTAL_MAIN 115200
#define NCHUNK 16
#define ASTRIDE 144   // bytes per smem row (64 fp16 + 8 pad)
#define SSTRIDE 148   // floats per S row

__device__ __forceinline__ void load_stage(uint32_t sb, int chunk, int tid,
                                           int arowbase, int browbase) {
    int k0 = chunk << 6;
    uint32_t sAh = sb + ((chunk & 1) ? SA_HI1 : SA_HI0);
    uint32_t sAl = sb + ((chunk & 1) ? SA_LO1 : SA_LO0);
    uint32_t sB  = sb + ((chunk & 1) ? SB1 : SB0);
#pragma unroll
    for (int t = 0; t < 4; t++) {
        int o = tid + t * 256;
        int row = o >> 3, seg = o & 7;
        size_t go = (((size_t)(arowbase + row)) << 10) + k0 + (seg << 3);
        uint32_t so = row * ASTRIDE + seg * 16;
        cp16(sAh + so, g_caps_hi + go);
        cp16(sAl + so, g_caps_lo + go);
    }
#pragma unroll
    for (int t = 0; t < 4; t++) {
        int o = tid + t * 256;
        int row = o >> 3, seg = o & 7;
        cp16(sB + row * ASTRIDE + seg * 16,
             g_imgs_h + (((size_t)(browbase + row)) << 10) + k0 + (seg << 3));
    }
    {   // B tail rows 128..143
        int o = tid + 1024;
        if (o < 1152) {
            int row = o >> 3, seg = o & 7;
            cp16(sB + row * ASTRIDE + seg * 16,
                 g_imgs_h + (((size_t)(browbase + row)) << 10) + k0 + (seg << 3));
        }
    }
    asm volatile("cp.async.commit_group;" ::: "memory");
}

__global__ void __launch_bounds__(256, 2)
main_kernel(const int* __restrict__ cap_lens, float* __restrict__ out) {
    extern __shared__ __align__(16) char smem[];
    const uint32_t sb = smem_to_u32(smem);
    const int tid = threadIdx.x, lane = tid & 31, wid = tid >> 5;
    const int c0 = blockIdx.y * 2;
    const int i0 = blockIdx.x * 4;
    const int arowbase = blockIdx.y * 128;
    const int browbase = blockIdx.x * 144;

    // ---------------- pipelined fp16 HMMA GEMM ----------------
    float acc[72];
#pragma unroll
    for (int j = 0; j < 72; j++) acc[j] = 0.f;

    load_stage(sb, 0, tid, arowbase, browbase);
    load_stage(sb, 1, tid, arowbase, browbase);

    const int mbase = (wid & 3) * 32;
    const int ncb = (wid >> 2) * 72;
    const int a_roff = lane & 15;
    const int a_kad  = (lane >> 4) << 3;
    const int b_roff = ((lane >> 4) << 3) + (lane & 7);
    const int b_kad  = ((lane >> 3) & 1) << 3;
    const int l16 = lane & 15;
    const int b2_roff = l16 & 7;
    const int b2_kad  = ((l16 >> 3) & 1) << 3;

    for (int i = 0; i < NCHUNK; i++) {
        const int s = i & 1;
        if (i == NCHUNK - 1) asm volatile("cp.async.wait_group 0;" ::: "memory");
        else                 asm volatile("cp.async.wait_group 1;" ::: "memory");
        __syncthreads();

        uint32_t Ah = sb + (s ? SA_HI1 : SA_HI0);
        uint32_t Al = sb + (s ? SA_LO1 : SA_LO0);
        uint32_t Bs = sb + (s ? SB1 : SB0);
#pragma unroll
        for (int ks = 0; ks < 4; ks++) {
            const int kbyte = ks * 32;
            uint32_t ah[2][4], al[2][4];
#pragma unroll
            for (int s2 = 0; s2 < 2; s2++) {
                uint32_t ao = (mbase + s2 * 16 + a_roff) * ASTRIDE + kbyte + a_kad * 2;
                ldsm_x4(ah[s2][0], ah[s2][1], ah[s2][2], ah[s2][3], Ah + ao);
                ldsm_x4(al[s2][0], al[s2][1], al[s2][2], al[s2][3], Al + ao);
            }
            uint32_t bh0, bh1;   // half tile cols ncb+64..71
            ldsm_x2(bh0, bh1,
                    Bs + (ncb + 64 + b2_roff) * ASTRIDE + kbyte + b2_kad * 2);

#pragma unroll
            for (int tp = 0; tp < 2; tp++) {
                uint32_t b[2][4];
#pragma unroll
                for (int tt = 0; tt < 2; tt++)
                    ldsm_x4(b[tt][0], b[tt][1], b[tt][2], b[tt][3],
                            Bs + (ncb + (tp * 2 + tt) * 16 + b_roff) * ASTRIDE
                               + kbyte + b_kad * 2);
                // hi-pass MMAs for this t-pair (8)
#pragma unroll
                for (int tt = 0; tt < 2; tt++)
#pragma unroll
                    for (int s2 = 0; s2 < 2; s2++) {
                        int j0 = s2 * 36 + (tp * 2 + tt) * 8;
                        mma_f16(acc[j0 + 0], acc[j0 + 1], acc[j0 + 2], acc[j0 + 3],
                                ah[s2][0], ah[s2][1], ah[s2][2], ah[s2][3],
                                b[tt][0], b[tt][1]);
                        mma_f16(acc[j0 + 4], acc[j0 + 5], acc[j0 + 6], acc[j0 + 7],
                                ah[s2][0], ah[s2][1], ah[s2][2], ah[s2][3],
                                b[tt][2], b[tt][3]);
                    }
                // half-tile: hi after tp=0, lo after tp=1 (max RAW distance)
                if (tp == 0) {
#pragma unroll
                    for (int s2 = 0; s2 < 2; s2++) {
                        int j0 = s2 * 36 + 32;
                        mma_f16(acc[j0 + 0], acc[j0 + 1], acc[j0 + 2], acc[j0 + 3],
                                ah[s2][0], ah[s2][1], ah[s2][2], ah[s2][3], bh0, bh1);
                    }
                } else {
#pragma unroll
                    for (int s2 = 0; s2 < 2; s2++) {
                        int j0 = s2 * 36 + 32;
                        mma_f16(acc[j0 + 0], acc[j0 + 1], acc[j0 + 2], acc[j0 + 3],
                                al[s2][0], al[s2][1], al[s2][2], al[s2][3], bh0, bh1);
                    }
                }
                // lo-pass MMAs for this t-pair (8)
#pragma unroll
                for (int tt = 0; tt < 2; tt++)
#pragma unroll
                    for (int s2 = 0; s2 < 2; s2++) {
                        int j0 = s2 * 36 + (tp * 2 + tt) * 8;
                        mma_f16(acc[j0 + 0], acc[j0 + 1], acc[j0 + 2], acc[j0 + 3],
                                al[s2][0], al[s2][1], al[s2][2], al[s2][3],
                                b[tt][0], b[tt][1]);
                        mma_f16(acc[j0 + 4], acc[j0 + 5], acc[j0 + 6], acc[j0 + 7],
                                al[s2][0], al[s2][1], al[s2][2], al[s2][3],
                                b[tt][2], b[tt][3]);
                    }
            }
        }
        __syncthreads();
        if (i + 2 < NCHUNK)
            load_stage(sb, i + 2, tid, arowbase, browbase);
    }

    // ---------------- write S to shared + stage Gram/w1 ----------------
    float* S = (float*)smem;
    {
        const int cA = (lane & 3) * 2;
        const int rA = lane >> 2;
#pragma unroll
        for (int s2 = 0; s2 < 2; s2++) {
            int r1 = mbase + s2 * 16 + rA;
#pragma unroll
            for (int j = 0; j < 9; j++) {
                int col = ncb + j * 8 + cA;
                *(float2*)(S + r1 * SSTRIDE + col) =
                    make_float2(acc[s2 * 36 + j * 4 + 0], acc[s2 * 36 + j * 4 + 1]);
                *(float2*)(S + (r1 + 8) * SSTRIDE + col) =
                    make_float2(acc[s2 * 36 + j * 4 + 2], acc[s2 * 36 + j * 4 + 3]);
            }
        }
    }
    {
        float* Gs = (float*)(smem + SOFF_G);
        if (tid < 4 * NREG) {
            int blk = tid / NREG, r = tid - blk * NREG;
            const float4* src = (const float4*)(g_G + ((size_t)(i0 + blk) * NREG + r) * NREG);
            float4* dst = (float4*)(Gs + (blk * NREG + r) * 40);
#pragma unroll
            for (int q = 0; q < 9; q++) dst[q] = src[q];
        }
        float* w1s = (float*)(smem + SOFF_W1);
        if (tid >= 128 && tid < 256) {
            int p = tid - 128;
            int cc = p >> 6, w = p & 63;
            w1s[p] = (w < MAXW) ? g_w1[(c0 + cc) * MAXW + w] : 0.f;
        }
    }
    __syncthreads();

    // ---------------- column norms -> scale ----------------
    float* scaleF = (float*)(smem + SOFF_SCALE);
    for (int task = tid; task < 288; task += 256) {
        int cap = task >= 144;
        int j = task - cap * 144;
        const float* p = S + (cap * 64) * SSTRIDE + j;
        float ssum = 0.f;
#pragma unroll 8
        for (int w = 0; w < 64; w++) {
            float v = p[w * SSTRIDE];
            v = (v < 0.f) ? LEAK * v : v;
            ssum += v * v;
        }
        scaleF[cap * 144 + j] = SMOOTH / (sqrtf(ssum) + EPSV);
    }
    __syncthreads();

    // ---------------- per-row epilogue (all 256 threads, 2 blks each) ------
    {
        const int row = tid & 127;
        const int half = tid >> 7;
        const int cap = row >> 6;
        const int word = row & 63;
        const int mylen = cap_lens[c0 + cap];
        const bool valid = word < mylen;
        const float myw1 = ((const float*)(smem + SOFF_W1))[row];
        const float* Srow = S + row * SSTRIDE;
        float* wp = (float*)(smem + SOFF_WP);

#pragma unroll
        for (int bq = 0; bq < 2; bq++) {
            const int blk = half * 2 + bq;
            const float* scl = scaleF + cap * 144 + blk * 36;
            float raw[36], e[36];
            {
                const float4* p4 = (const float4*)(Srow + blk * 36);
#pragma unroll
                for (int q = 0; q < 9; q++) {
                    float4 v = p4[q];
                    raw[q * 4 + 0] = v.x; raw[q * 4 + 1] = v.y;
                    raw[q * 4 + 2] = v.z; raw[q * 4 + 3] = v.w;
                }
            }
            float se = 0.f;
#pragma unroll
            for (int r = 0; r < 36; r++) {
                float v = raw[r];
                float l = ((v < 0.f) ? LEAK * v : v) * scl[r];
                e[r] = __expf(l);
                se += e[r];
            }
            float inv = 1.f / se;
            float w12 = 0.f;
#pragma unroll
            for (int r = 0; r < 36; r++) w12 += e[r] * raw[r];
            w12 *= inv;

            // quadratic form attn^T G attn via packed f32x2
            unsigned long long ep[18];
#pragma unroll
            for (int q = 0; q < 18; q++) ep[q] = pack2(e[2 * q], e[2 * q + 1]);
            const unsigned long long* Gb =
                (const unsigned long long*)(smem + SOFF_G) + (size_t)blk * NREG * 20;
            float t = 0.f;
#pragma unroll
            for (int r = 0; r < 36; r++) {
                const unsigned long long* grow = Gb + r * 20;
                unsigned long long d2 = 0ull;
#pragma unroll
                for (int q = 0; q < 18; q++) ffma2(d2, grow[q], ep[q]);
                float dlo, dhi;
                unpack2(d2, dlo, dhi);
                t += e[r] * (dlo + dhi);
            }
            float w2 = sqrtf(t) * inv;
            float sim = w12 / fmaxf(myw1 * w2, EPSV);
            sim = valid ? sim : 0.f;

            float ssum = warpSum(sim);
            if (lane == 0) wp[wid * 2 + bq] = ssum;
        }
    }
    __syncthreads();
    if (tid < 8) {
        int blk = tid & 3, cc = tid >> 2;
        int h = blk >> 1, b = blk & 1;
        float* wp = (float*)(smem + SOFF_WP);
        float s = wp[(h * 4 + cc * 2) * 2 + b] + wp[(h * 4 + cc * 2 + 1) * 2 + b];
        out[(size_t)(i0 + blk) * NCAP + (c0 + cc)] = s / (float)cap_lens[c0 + cc];
    }
}

// ---------------------------------------------------------------------------
extern "C" void kernel_launch(void* const* d_in, const int* in_sizes, int n_in,
                              void* d_out, int out_size) {
    const float* imgs     = (const float*)d_in[0];
    const float* caps     = (const float*)d_in[1];
    const int*   cap_lens = (const int*)d_in[3];
    float*       out      = (float*)d_out;

    prep_caps_kernel<<<NCAP, 256>>>(caps, cap_lens);
    prep_imgs_kernel<<<NIMG, 256>>>(imgs);

    cudaFuncSetAttribute(main_kernel, cudaFuncAttributeMaxDynamicSharedMemorySize,
                         SMEM_TOTAL_MAIN);
    dim3 grid(NIMG / 4, NCAP / 2);
    main_kernel<<<grid, 256, SMEM_TOTAL_MAIN>>>(cap_lens, out);
}

// round 7
// speedup vs baseline: 7.7214x; 1.4187x over previous
#include <cuda_runtime.h>
#include <cuda_fp16.h>
#include <cstdint>
#include <math.h>

#define NIMG 256
#define NREG 36
#define NCAP 256
#define MAXW 60
#define CAPW 64
#define DIM  1024

#define SMOOTH 9.0f
#define EPSV   1e-8f
#define LEAK   0.1f

// ---------------------------------------------------------------------------
// Device global scratch
// ---------------------------------------------------------------------------
__device__ __half g_caps_h[NCAP * CAPW * DIM];
__device__ __half g_imgs_h[NIMG * NREG * DIM];
__device__ float g_G[NIMG * NREG * NREG];
__device__ float g_w1[NCAP * MAXW];

// ---------------------------------------------------------------------------
// Helpers
// ---------------------------------------------------------------------------
__device__ __forceinline__ uint32_t smem_to_u32(const void* p) {
    uint32_t a;
    asm("{ .reg .u64 t; cvta.to.shared.u64 t, %1; cvt.u32.u64 %0, t; }"
        : "=r"(a) : "l"(p));
    return a;
}
__device__ __forceinline__ void cp16(uint32_t dst, const void* src) {
    asm volatile("cp.async.cg.shared.global [%0], [%1], 16;" :: "r"(dst), "l"(src) : "memory");
}
__device__ __forceinline__ void ldsm_x4(uint32_t &r0, uint32_t &r1, uint32_t &r2,
                                        uint32_t &r3, uint32_t addr) {
    asm volatile("ldmatrix.sync.aligned.m8n8.x4.shared.b16 {%0,%1,%2,%3}, [%4];"
                 : "=r"(r0), "=r"(r1), "=r"(r2), "=r"(r3) : "r"(addr));
}
__device__ __forceinline__ void ldsm_x2(uint32_t &r0, uint32_t &r1, uint32_t addr) {
    asm volatile("ldmatrix.sync.aligned.m8n8.x2.shared.b16 {%0,%1}, [%2];"
                 : "=r"(r0), "=r"(r1) : "r"(addr));
}
__device__ __forceinline__ void mma_f16(float &c0, float &c1, float &c2, float &c3,
                                        uint32_t a0, uint32_t a1, uint32_t a2, uint32_t a3,
                                        uint32_t b0, uint32_t b1) {
    asm volatile("mma.sync.aligned.m16n8k16.row.col.f32.f16.f16.f32 "
                 "{%0,%1,%2,%3}, {%4,%5,%6,%7}, {%8,%9}, {%0,%1,%2,%3};"
                 : "+f"(c0), "+f"(c1), "+f"(c2), "+f"(c3)
                 : "r"(a0), "r"(a1), "r"(a2), "r"(a3), "r"(b0), "r"(b1));
}
__device__ __forceinline__ unsigned long long pack2(float lo, float hi) {
    unsigned long long r;
    asm("mov.b64 %0, {%1, %2};" : "=l"(r) : "f"(lo), "f"(hi));
    return r;
}
__device__ __forceinline__ void unpack2(unsigned long long v, float &lo, float &hi) {
    asm("mov.b64 {%0, %1}, %2;" : "=f"(lo), "=f"(hi) : "l"(v));
}
__device__ __forceinline__ void ffma2(unsigned long long &d,
                                      unsigned long long a,
                                      unsigned long long b) {
    asm("fma.rn.f32x2 %0, %1, %2, %0;" : "+l"(d) : "l"(a), "l"(b));
}
__device__ __forceinline__ float warpSum(float v) {
    v += __shfl_xor_sync(0xffffffffu, v, 16);
    v += __shfl_xor_sync(0xffffffffu, v, 8);
    v += __shfl_xor_sync(0xffffffffu, v, 4);
    v += __shfl_xor_sync(0xffffffffu, v, 2);
    v += __shfl_xor_sync(0xffffffffu, v, 1);
    return v;
}

// ---------------------------------------------------------------------------
// Prep 1: caps -> fp16 (masked, padded to 64 words) + per-word norms
// ---------------------------------------------------------------------------
__global__ void prep_caps_kernel(const float* __restrict__ caps,
                                 const int* __restrict__ cap_lens) {
    const int c = blockIdx.x;
    const int wid = threadIdx.x >> 5, lane = threadIdx.x & 31;
    const int len = cap_lens[c];
    for (int w = wid; w < CAPW; w += 8) {
        size_t dsto = ((size_t)c * CAPW + w) * DIM;
        if (w < len) {
            const float* row = caps + ((size_t)c * MAXW + w) * DIM;
            float ss = 0.f;
#pragma unroll
            for (int j = 0; j < 8; j++) {
                float4 v = *(const float4*)(row + j * 128 + lane * 4);
                ss += v.x * v.x + v.y * v.y + v.z * v.z + v.w * v.w;
                size_t o = dsto + j * 128 + lane * 4;
                *(__half2*)(g_caps_h + o)     = __floats2half2_rn(v.x, v.y);
                *(__half2*)(g_caps_h + o + 2) = __floats2half2_rn(v.z, v.w);
            }
            ss = warpSum(ss);
            if (lane == 0 && w < MAXW) g_w1[c * MAXW + w] = sqrtf(ss);
        } else {
            uint2 z = make_uint2(0u, 0u);
#pragma unroll
            for (int j = 0; j < 8; j++)
                *(uint2*)(g_caps_h + dsto + j * 128 + lane * 4) = z;
            if (lane == 0 && w < MAXW) g_w1[c * MAXW + w] = 0.f;
        }
    }
}

// ---------------------------------------------------------------------------
// Prep 2: imgs -> fp16 + per-image Gram matrix (fp32, exact)
// ---------------------------------------------------------------------------
__global__ void prep_imgs_kernel(const float* __restrict__ imgs) {
    const int i = blockIdx.x;
    __shared__ float chunk[NREG * 132];
    float acc[6];
#pragma unroll
    for (int j = 0; j < 6; j++) acc[j] = 0.f;

    for (int d0 = 0; d0 < DIM; d0 += 128) {
        __syncthreads();
        for (int idx = threadIdx.x; idx < NREG * 32; idx += 256) {
            int r = idx >> 5, dq = idx & 31;
            size_t e = ((size_t)i * NREG + r) * DIM + d0 + dq * 4;
            float4 v = *(const float4*)(imgs + e);
            *(float4*)(chunk + r * 132 + dq * 4) = v;
            *(__half2*)(g_imgs_h + e)     = __floats2half2_rn(v.x, v.y);
            *(__half2*)(g_imgs_h + e + 2) = __floats2half2_rn(v.z, v.w);
        }
        __syncthreads();
#pragma unroll
        for (int j = 0; j < 6; j++) {
            int p = threadIdx.x + j * 256;
            if (p < NREG * NREG) {
                int r = p / NREG, rp = p - r * NREG;
                const float4* A = (const float4*)(chunk + r * 132);
                const float4* B = (const float4*)(chunk + rp * 132);
                float s = 0.f;
#pragma unroll
                for (int q = 0; q < 32; q++) {
                    float4 a = A[q], b = B[q];
                    s += a.x * b.x + a.y * b.y + a.z * b.z + a.w * b.w;
                }
                acc[j] += s;
            }
        }
    }
#pragma unroll
    for (int j = 0; j < 6; j++) {
        int p = threadIdx.x + j * 256;
        if (p < NREG * NREG) g_G[(size_t)i * NREG * NREG + p] = acc[j];
    }
}

// ---------------------------------------------------------------------------
// Main fused kernel: single-pass fp16 GEMM (M=128, N=144, K=1024) + epilogue
// Shared memory during GEMM (bytes):
//   [0,18432)      A stage 0      [18432,39168)  B stage 0
//   [39168,57600)  A stage 1      [57600,78336)  B stage 1
// After GEMM (reuse):
//   [0,75776)        S (128 x 148 f32)
//   [75776,76928)    scale  [76928,77440) w1  [77440,77504) wp
//   [77504,100544)   Gram (4 x 36 x 40 f32)
// ---------------------------------------------------------------------------
#define SA0 0
#define SB0 18432
#define SA1 39168
#define SB1 57600
#define SOFF_SCALE 75776
#define SOFF_W1    76928
#define SOFF_WP    77440
#define SOFF_G     77504
#define SMEM_TOTAL_MAIN 100544
#define NCHUNK 16
#define ASTRIDE 144   // bytes per smem row (64 fp16 + 8 pad)
#define SSTRIDE 148   // floats per S row

__device__ __forceinline__ void load_stage(uint32_t sb, int chunk, int tid,
                                           int arowbase, int browbase) {
    int k0 = chunk << 6;
    uint32_t sA = sb + ((chunk & 1) ? SA1 : SA0);
    uint32_t sB = sb + ((chunk & 1) ? SB1 : SB0);
#pragma unroll
    for (int t = 0; t < 4; t++) {
        int o = tid + t * 256;
        int row = o >> 3, seg = o & 7;
        cp16(sA + row * ASTRIDE + seg * 16,
             g_caps_h + (((size_t)(arowbase + row)) << 10) + k0 + (seg << 3));
    }
#pragma unroll
    for (int t = 0; t < 4; t++) {
        int o = tid + t * 256;
        int row = o >> 3, seg = o & 7;
        cp16(sB + row * ASTRIDE + seg * 16,
             g_imgs_h + (((size_t)(browbase + row)) << 10) + k0 + (seg << 3));
    }
    {   // B tail rows 128..143
        int o = tid + 1024;
        if (o < 1152) {
            int row = o >> 3, seg = o & 7;
            cp16(sB + row * ASTRIDE + seg * 16,
                 g_imgs_h + (((size_t)(browbase + row)) << 10) + k0 + (seg << 3));
        }
    }
    asm volatile("cp.async.commit_group;" ::: "memory");
}

__global__ void __launch_bounds__(256, 2)
main_kernel(const int* __restrict__ cap_lens, float* __restrict__ out) {
    extern __shared__ __align__(16) char smem[];
    const uint32_t sb = smem_to_u32(smem);
    const int tid = threadIdx.x, lane = tid & 31, wid = tid >> 5;
    const int c0 = blockIdx.y * 2;
    const int i0 = blockIdx.x * 4;
    const int arowbase = blockIdx.y * 128;
    const int browbase = blockIdx.x * 144;

    // ---------------- pipelined fp16 HMMA GEMM ----------------
    float acc[72];
#pragma unroll
    for (int j = 0; j < 72; j++) acc[j] = 0.f;

    load_stage(sb, 0, tid, arowbase, browbase);
    load_stage(sb, 1, tid, arowbase, browbase);

    const int mbase = (wid & 3) * 32;
    const int ncb = (wid >> 2) * 72;
    const int a_roff = lane & 15;
    const int a_kad  = (lane >> 4) << 3;
    const int b_roff = ((lane >> 4) << 3) + (lane & 7);
    const int b_kad  = ((lane >> 3) & 1) << 3;
    const int l16 = lane & 15;
    const int b2_roff = l16 & 7;
    const int b2_kad  = ((l16 >> 3) & 1) << 3;

    for (int i = 0; i < NCHUNK; i++) {
        const int s = i & 1;
        if (i == NCHUNK - 1) asm volatile("cp.async.wait_group 0;" ::: "memory");
        else                 asm volatile("cp.async.wait_group 1;" ::: "memory");
        __syncthreads();

        uint32_t As = sb + (s ? SA1 : SA0);
        uint32_t Bs = sb + (s ? SB1 : SB0);
#pragma unroll
        for (int ks = 0; ks < 4; ks++) {
            const int kbyte = ks * 32;
            uint32_t a[2][4];
#pragma unroll
            for (int s2 = 0; s2 < 2; s2++)
                ldsm_x4(a[s2][0], a[s2][1], a[s2][2], a[s2][3],
                        As + (mbase + s2 * 16 + a_roff) * ASTRIDE + kbyte + a_kad * 2);
            uint32_t bh0, bh1;   // half tile cols ncb+64..71
            ldsm_x2(bh0, bh1,
                    Bs + (ncb + 64 + b2_roff) * ASTRIDE + kbyte + b2_kad * 2);
#pragma unroll
            for (int t = 0; t < 4; t++) {
                uint32_t b0, b1, b2, b3;
                ldsm_x4(b0, b1, b2, b3,
                        Bs + (ncb + t * 16 + b_roff) * ASTRIDE + kbyte + b_kad * 2);
#pragma unroll
                for (int s2 = 0; s2 < 2; s2++) {
                    int j0 = s2 * 36 + t * 8;
                    mma_f16(acc[j0 + 0], acc[j0 + 1], acc[j0 + 2], acc[j0 + 3],
                            a[s2][0], a[s2][1], a[s2][2], a[s2][3], b0, b1);
                    mma_f16(acc[j0 + 4], acc[j0 + 5], acc[j0 + 6], acc[j0 + 7],
                            a[s2][0], a[s2][1], a[s2][2], a[s2][3], b2, b3);
                }
            }
#pragma unroll
            for (int s2 = 0; s2 < 2; s2++) {
                int j0 = s2 * 36 + 32;
                mma_f16(acc[j0 + 0], acc[j0 + 1], acc[j0 + 2], acc[j0 + 3],
                        a[s2][0], a[s2][1], a[s2][2], a[s2][3], bh0, bh1);
            }
        }
        __syncthreads();
        if (i + 2 < NCHUNK)
            load_stage(sb, i + 2, tid, arowbase, browbase);
    }

    // ---------------- write S to shared + stage Gram/w1 ----------------
    float* S = (float*)smem;
    {
        const int cA = (lane & 3) * 2;
        const int rA = lane >> 2;
#pragma unroll
        for (int s2 = 0; s2 < 2; s2++) {
            int r1 = mbase + s2 * 16 + rA;
#pragma unroll
            for (int j = 0; j < 9; j++) {
                int col = ncb + j * 8 + cA;
                *(float2*)(S + r1 * SSTRIDE + col) =
                    make_float2(acc[s2 * 36 + j * 4 + 0], acc[s2 * 36 + j * 4 + 1]);
                *(float2*)(S + (r1 + 8) * SSTRIDE + col) =
                    make_float2(acc[s2 * 36 + j * 4 + 2], acc[s2 * 36 + j * 4 + 3]);
            }
        }
    }
    {
        float* Gs = (float*)(smem + SOFF_G);
        if (tid < 4 * NREG) {
            int blk = tid / NREG, r = tid - blk * NREG;
            const float4* src = (const float4*)(g_G + ((size_t)(i0 + blk) * NREG + r) * NREG);
            float4* dst = (float4*)(Gs + (blk * NREG + r) * 40);
#pragma unroll
            for (int q = 0; q < 9; q++) dst[q] = src[q];
        }
        float* w1s = (float*)(smem + SOFF_W1);
        if (tid >= 128 && tid < 256) {
            int p = tid - 128;
            int cc = p >> 6, w = p & 63;
            w1s[p] = (w < MAXW) ? g_w1[(c0 + cc) * MAXW + w] : 0.f;
        }
    }
    __syncthreads();

    // ---------------- column norms -> scale ----------------
    float* scaleF = (float*)(smem + SOFF_SCALE);
    for (int task = tid; task < 288; task += 256) {
        int cap = task >= 144;
        int j = task - cap * 144;
        const float* p = S + (cap * 64) * SSTRIDE + j;
        float ssum = 0.f;
#pragma unroll 8
        for (int w = 0; w < 64; w++) {
            float v = p[w * SSTRIDE];
            v = (v < 0.f) ? LEAK * v : v;
            ssum += v * v;
        }
        scaleF[cap * 144 + j] = SMOOTH / (sqrtf(ssum) + EPSV);
    }
    __syncthreads();

    // ---------------- per-row epilogue (all 256 threads, 2 blks each) ------
    {
        const int row = tid & 127;
        const int half = tid >> 7;
        const int cap = row >> 6;
        const int word = row & 63;
        const int mylen = cap_lens[c0 + cap];
        const bool valid = word < mylen;
        const float myw1 = ((const float*)(smem + SOFF_W1))[row];
        const float* Srow = S + row * SSTRIDE;
        float* wp = (float*)(smem + SOFF_WP);

#pragma unroll
        for (int bq = 0; bq < 2; bq++) {
            const int blk = half * 2 + bq;
            const float* scl = scaleF + cap * 144 + blk * 36;
            float raw[36], e[36];
            {
                const float4* p4 = (const float4*)(Srow + blk * 36);
#pragma unroll
                for (int q = 0; q < 9; q++) {
                    float4 v = p4[q];
                    raw[q * 4 + 0] = v.x; raw[q * 4 + 1] = v.y;
                    raw[q * 4 + 2] = v.z; raw[q * 4 + 3] = v.w;
                }
            }
            float se = 0.f;
#pragma unroll
            for (int r = 0; r < 36; r++) {
                float v = raw[r];
                float l = ((v < 0.f) ? LEAK * v : v) * scl[r];
                e[r] = __expf(l);
                se += e[r];
            }
            float inv = 1.f / se;
            float w12 = 0.f;
#pragma unroll
            for (int r = 0; r < 36; r++) w12 += e[r] * raw[r];
            w12 *= inv;

            // quadratic form attn^T G attn via packed f32x2
            unsigned long long ep[18];
#pragma unroll
            for (int q = 0; q < 18; q++) ep[q] = pack2(e[2 * q], e[2 * q + 1]);
            const unsigned long long* Gb =
                (const unsigned long long*)(smem + SOFF_G) + (size_t)blk * NREG * 20;
            float t = 0.f;
#pragma unroll
            for (int r = 0; r < 36; r++) {
                const unsigned long long* grow = Gb + r * 20;
                unsigned long long d2 = 0ull;
#pragma unroll
                for (int q = 0; q < 18; q++) ffma2(d2, grow[q], ep[q]);
                float dlo, dhi;
                unpack2(d2, dlo, dhi);
                t += e[r] * (dlo + dhi);
            }
            float w2 = sqrtf(t) * inv;
            float sim = w12 / fmaxf(myw1 * w2, EPSV);
            sim = valid ? sim : 0.f;

            float ssum = warpSum(sim);
            if (lane == 0) wp[wid * 2 + bq] = ssum;
        }
    }
    __syncthreads();
    if (tid < 8) {
        int blk = tid & 3, cc = tid >> 2;
        int h = blk >> 1, b = blk & 1;
        float* wp = (float*)(smem + SOFF_WP);
        float s = wp[(h * 4 + cc * 2) * 2 + b] + wp[(h * 4 + cc * 2 + 1) * 2 + b];
        out[(size_t)(i0 + blk) * NCAP + (c0 + cc)] = s / (float)cap_lens[c0 + cc];
    }
}

// ---------------------------------------------------------------------------
extern "C" void kernel_launch(void* const* d_in, const int* in_sizes, int n_in,
                              void* d_out, int out_size) {
    const float* imgs     = (const float*)d_in[0];
    const float* caps     = (const float*)d_in[1];
    const int*   cap_lens = (const int*)d_in[3];
    float*       out      = (float*)d_out;

    prep_caps_kernel<<<NCAP, 256>>>(caps, cap_lens);
    prep_imgs_kernel<<<NIMG, 256>>>(imgs);

    cudaFuncSetAttribute(main_kernel, cudaFuncAttributeMaxDynamicSharedMemorySize,
                         SMEM_TOTAL_MAIN);
    dim3 grid(NIMG / 4, NCAP / 2);
    main_kernel<<<grid, 256, SMEM_TOTAL_MAIN>>>(cap_lens, out);
}

// round 8
// speedup vs baseline: 7.8284x; 1.0139x over previous
#include <cuda_runtime.h>
#include <cuda_fp16.h>
#include <cstdint>
#include <math.h>

#define NIMG 256
#define NREG 36
#define NCAP 256
#define MAXW 60
#define CAPW 64
#define DIM  1024

#define SMOOTH 9.0f
#define EPSV   1e-8f
#define LEAK   0.1f

// ---------------------------------------------------------------------------
// Device global scratch
// ---------------------------------------------------------------------------
__device__ __half g_caps_h[NCAP * CAPW * DIM];
__device__ __half g_imgs_h[NIMG * NREG * DIM];
__device__ float g_G[NIMG * NREG * NREG];
__device__ float g_w1[NCAP * MAXW];

// ---------------------------------------------------------------------------
// Helpers
// ---------------------------------------------------------------------------
__device__ __forceinline__ uint32_t smem_to_u32(const void* p) {
    uint32_t a;
    asm("{ .reg .u64 t; cvta.to.shared.u64 t, %1; cvt.u32.u64 %0, t; }"
        : "=r"(a) : "l"(p));
    return a;
}
__device__ __forceinline__ void cp16(uint32_t dst, const void* src) {
    asm volatile("cp.async.cg.shared.global [%0], [%1], 16;" :: "r"(dst), "l"(src) : "memory");
}
__device__ __forceinline__ void ldsm_x4(uint32_t &r0, uint32_t &r1, uint32_t &r2,
                                        uint32_t &r3, uint32_t addr) {
    asm volatile("ldmatrix.sync.aligned.m8n8.x4.shared.b16 {%0,%1,%2,%3}, [%4];"
                 : "=r"(r0), "=r"(r1), "=r"(r2), "=r"(r3) : "r"(addr));
}
__device__ __forceinline__ void ldsm_x2(uint32_t &r0, uint32_t &r1, uint32_t addr) {
    asm volatile("ldmatrix.sync.aligned.m8n8.x2.shared.b16 {%0,%1}, [%2];"
                 : "=r"(r0), "=r"(r1) : "r"(addr));
}
__device__ __forceinline__ void mma_f16(float &c0, float &c1, float &c2, float &c3,
                                        uint32_t a0, uint32_t a1, uint32_t a2, uint32_t a3,
                                        uint32_t b0, uint32_t b1) {
    asm volatile("mma.sync.aligned.m16n8k16.row.col.f32.f16.f16.f32 "
                 "{%0,%1,%2,%3}, {%4,%5,%6,%7}, {%8,%9}, {%0,%1,%2,%3};"
                 : "+f"(c0), "+f"(c1), "+f"(c2), "+f"(c3)
                 : "r"(a0), "r"(a1), "r"(a2), "r"(a3), "r"(b0), "r"(b1));
}
__device__ __forceinline__ unsigned long long pack2(float lo, float hi) {
    unsigned long long r;
    asm("mov.b64 %0, {%1, %2};" : "=l"(r) : "f"(lo), "f"(hi));
    return r;
}
__device__ __forceinline__ void unpack2(unsigned long long v, float &lo, float &hi) {
    asm("mov.b64 {%0, %1}, %2;" : "=f"(lo), "=f"(hi) : "l"(v));
}
__device__ __forceinline__ void ffma2(unsigned long long &d,
                                      unsigned long long a,
                                      unsigned long long b) {
    asm("fma.rn.f32x2 %0, %1, %2, %0;" : "+l"(d) : "l"(a), "l"(b));
}
__device__ __forceinline__ float warpSum(float v) {
    v += __shfl_xor_sync(0xffffffffu, v, 16);
    v += __shfl_xor_sync(0xffffffffu, v, 8);
    v += __shfl_xor_sync(0xffffffffu, v, 4);
    v += __shfl_xor_sync(0xffffffffu, v, 2);
    v += __shfl_xor_sync(0xffffffffu, v, 1);
    return v;
}

// ---------------------------------------------------------------------------
// Merged prep: blocks [0,256) caps -> fp16 + word norms; [256,512) imgs ->
// fp16 + exact fp32 Gram.
// ---------------------------------------------------------------------------
__global__ void prep_kernel(const float* __restrict__ imgs,
                            const float* __restrict__ caps,
                            const int* __restrict__ cap_lens) {
    __shared__ float chunk[NREG * 132];
    if (blockIdx.x < 256) {
        const int c = blockIdx.x;
        const int wid = threadIdx.x >> 5, lane = threadIdx.x & 31;
        const int len = cap_lens[c];
        for (int w = wid; w < CAPW; w += 8) {
            size_t dsto = ((size_t)c * CAPW + w) * DIM;
            if (w < len) {
                const float* row = caps + ((size_t)c * MAXW + w) * DIM;
                float ss = 0.f;
#pragma unroll
                for (int j = 0; j < 8; j++) {
                    float4 v = *(const float4*)(row + j * 128 + lane * 4);
                    ss += v.x * v.x + v.y * v.y + v.z * v.z + v.w * v.w;
                    size_t o = dsto + j * 128 + lane * 4;
                    *(__half2*)(g_caps_h + o)     = __floats2half2_rn(v.x, v.y);
                    *(__half2*)(g_caps_h + o + 2) = __floats2half2_rn(v.z, v.w);
                }
                ss = warpSum(ss);
                if (lane == 0 && w < MAXW) g_w1[c * MAXW + w] = sqrtf(ss);
            } else {
                uint2 z = make_uint2(0u, 0u);
#pragma unroll
                for (int j = 0; j < 8; j++)
                    *(uint2*)(g_caps_h + dsto + j * 128 + lane * 4) = z;
                if (lane == 0 && w < MAXW) g_w1[c * MAXW + w] = 0.f;
            }
        }
    } else {
        const int i = blockIdx.x - 256;
        float acc[6];
#pragma unroll
        for (int j = 0; j < 6; j++) acc[j] = 0.f;
        for (int d0 = 0; d0 < DIM; d0 += 128) {
            __syncthreads();
            for (int idx = threadIdx.x; idx < NREG * 32; idx += 256) {
                int r = idx >> 5, dq = idx & 31;
                size_t e = ((size_t)i * NREG + r) * DIM + d0 + dq * 4;
                float4 v = *(const float4*)(imgs + e);
                *(float4*)(chunk + r * 132 + dq * 4) = v;
                *(__half2*)(g_imgs_h + e)     = __floats2half2_rn(v.x, v.y);
                *(__half2*)(g_imgs_h + e + 2) = __floats2half2_rn(v.z, v.w);
            }
            __syncthreads();
#pragma unroll
            for (int j = 0; j < 6; j++) {
                int p = threadIdx.x + j * 256;
                if (p < NREG * NREG) {
                    int r = p / NREG, rp = p - r * NREG;
                    const float4* A = (const float4*)(chunk + r * 132);
                    const float4* B = (const float4*)(chunk + rp * 132);
                    float s = 0.f;
#pragma unroll
                    for (int q = 0; q < 32; q++) {
                        float4 a = A[q], b = B[q];
                        s += a.x * b.x + a.y * b.y + a.z * b.z + a.w * b.w;
                    }
                    acc[j] += s;
                }
            }
        }
#pragma unroll
        for (int j = 0; j < 6; j++) {
            int p = threadIdx.x + j * 256;
            if (p < NREG * NREG) g_G[(size_t)i * NREG * NREG + p] = acc[j];
        }
    }
}

// ---------------------------------------------------------------------------
// Main fused kernel: fp16 GEMM M=128 x N=288 (8 imgs) x K=1024 + epilogue.
// 512 threads, 16 warps (warp tile 32x72), 3-stage cp.async pipeline,
// swizzled 128B smem rows, 1 barrier per chunk.
// Stage k at k*53248: A[128x128B] then B[288x128B].
// Post-GEMM union: S(128x292 f32), scale, w1, wp, Gram(8x36x40).
// ---------------------------------------------------------------------------
#define STAGE_BYTES 53248
#define SB_OFF      16384
#define SOFF_SCALE  149504
#define SOFF_W1     151808
#define SOFF_WP     152320
#define SOFF_G      152448
#define SMEM_TOTAL_MAIN 198528
#define NCHUNK 16
#define SSTRIDE 292   // floats per S row

__device__ __forceinline__ void load_stage(uint32_t sbase, int chunk, int tid,
                                           int arowbase, int browbase) {
    const int k0 = chunk << 6;
    const uint32_t sA = sbase + (chunk % 3) * STAGE_BYTES;
    const uint32_t sB = sA + SB_OFF;
#pragma unroll
    for (int t = 0; t < 2; t++) {
        int o = tid + t * 512;                 // 1024 A lines
        int row = o >> 3, seg = o & 7;
        cp16(sA + row * 128 + (((seg ^ (row & 7))) << 4),
             g_caps_h + (((size_t)(arowbase + row)) << 10) + k0 + (seg << 3));
    }
#pragma unroll
    for (int t = 0; t < 5; t++) {
        int o = tid + t * 512;                 // 2304 B lines
        if (o < 2304) {
            int row = o >> 3, seg = o & 7;
            cp16(sB + row * 128 + (((seg ^ (row & 7))) << 4),
                 g_imgs_h + (((size_t)(browbase + row)) << 10) + k0 + (seg << 3));
        }
    }
    asm volatile("cp.async.commit_group;" ::: "memory");
}

__global__ void __launch_bounds__(512, 1)
main_kernel(const int* __restrict__ cap_lens, float* __restrict__ out) {
    extern __shared__ __align__(16) char smem[];
    const uint32_t sb = smem_to_u32(smem);
    const int tid = threadIdx.x, lane = tid & 31, wid = tid >> 5;
    const int c0 = blockIdx.y * 2;
    const int i0 = blockIdx.x * 8;
    const int arowbase = blockIdx.y * 128;
    const int browbase = blockIdx.x * 288;

    float acc[72];
#pragma unroll
    for (int j = 0; j < 72; j++) acc[j] = 0.f;

    load_stage(sb, 0, tid, arowbase, browbase);
    load_stage(sb, 1, tid, arowbase, browbase);

    const int mbase = (wid & 3) * 32;
    const int ncb = (wid >> 2) * 72;
    const int a_roff = lane & 15;
    const int a_seg0 = lane >> 4;            // 0/1
    const int b_roff = ((lane >> 4) << 3) + (lane & 7);
    const int b_seg0 = (lane >> 3) & 1;
    const int l16 = lane & 15;
    const int b2_roff = l16 & 7;
    const int b2_seg0 = (l16 >> 3) & 1;
    const int sw = lane & 7;                 // row&7 for all ldsm rows

    for (int i = 0; i < NCHUNK; i++) {
        if (i == NCHUNK - 1) asm volatile("cp.async.wait_group 0;" ::: "memory");
        else                 asm volatile("cp.async.wait_group 1;" ::: "memory");
        __syncthreads();
        if (i + 2 < NCHUNK)
            load_stage(sb, i + 2, tid, arowbase, browbase);

        const uint32_t As = sb + (i % 3) * STAGE_BYTES;
        const uint32_t Bs = As + SB_OFF;
#pragma unroll
        for (int ks = 0; ks < 4; ks++) {
            uint32_t a[2][4];
#pragma unroll
            for (int s2 = 0; s2 < 2; s2++) {
                int row = mbase + s2 * 16 + a_roff;
                int seg = (ks * 2 + a_seg0) ^ sw;
                ldsm_x4(a[s2][0], a[s2][1], a[s2][2], a[s2][3],
                        As + row * 128 + (seg << 4));
            }
            uint32_t bh0, bh1;
            {
                int row = ncb + 64 + b2_roff;
                int seg = (ks * 2 + b2_seg0) ^ sw;
                ldsm_x2(bh0, bh1, Bs + row * 128 + (seg << 4));
            }
#pragma unroll
            for (int t = 0; t < 4; t++) {
                uint32_t b0, b1, b2, b3;
                int row = ncb + t * 16 + b_roff;
                int seg = (ks * 2 + b_seg0) ^ sw;
                ldsm_x4(b0, b1, b2, b3, Bs + row * 128 + (seg << 4));
#pragma unroll
                for (int s2 = 0; s2 < 2; s2++) {
                    int j0 = s2 * 36 + t * 8;
                    mma_f16(acc[j0 + 0], acc[j0 + 1], acc[j0 + 2], acc[j0 + 3],
                            a[s2][0], a[s2][1], a[s2][2], a[s2][3], b0, b1);
                    mma_f16(acc[j0 + 4], acc[j0 + 5], acc[j0 + 6], acc[j0 + 7],
                            a[s2][0], a[s2][1], a[s2][2], a[s2][3], b2, b3);
                }
            }
#pragma unroll
            for (int s2 = 0; s2 < 2; s2++) {
                int j0 = s2 * 36 + 32;
                mma_f16(acc[j0 + 0], acc[j0 + 1], acc[j0 + 2], acc[j0 + 3],
                        a[s2][0], a[s2][1], a[s2][2], a[s2][3], bh0, bh1);
            }
        }
    }
    __syncthreads();   // all warps done reading stages before S overwrites them

    // ---------------- write S + stage Gram/w1 ----------------
    float* S = (float*)smem;
    {
        const int cA = (lane & 3) * 2;
        const int rA = lane >> 2;
#pragma unroll
        for (int s2 = 0; s2 < 2; s2++) {
            int r1 = mbase + s2 * 16 + rA;
#pragma unroll
            for (int j = 0; j < 9; j++) {
                int col = ncb + j * 8 + cA;
                *(float2*)(S + r1 * SSTRIDE + col) =
                    make_float2(acc[s2 * 36 + j * 4 + 0], acc[s2 * 36 + j * 4 + 1]);
                *(float2*)(S + (r1 + 8) * SSTRIDE + col) =
                    make_float2(acc[s2 * 36 + j * 4 + 2], acc[s2 * 36 + j * 4 + 3]);
            }
        }
    }
    {
        float* Gs = (float*)(smem + SOFF_G);
        if (tid < 8 * NREG) {
            int blk = tid / NREG, r = tid - blk * NREG;
            const float4* src = (const float4*)(g_G + ((size_t)(i0 + blk) * NREG + r) * NREG);
            float4* dst = (float4*)(Gs + (blk * NREG + r) * 40);
#pragma unroll
            for (int q = 0; q < 9; q++) dst[q] = src[q];
        }
        float* w1s = (float*)(smem + SOFF_W1);
        if (tid >= 384) {
            int p = tid - 384;
            int cc = p >> 6, w = p & 63;
            w1s[p] = (w < MAXW) ? g_w1[(c0 + cc) * MAXW + w] : 0.f;
        }
    }
    __syncthreads();

    // ---------------- column norms -> scale ----------------
    float* scaleF = (float*)(smem + SOFF_SCALE);
    for (int task = tid; task < 576; task += 512) {
        int cap = task >= 288;
        int j = task - cap * 288;
        const float* p = S + (cap * 64) * SSTRIDE + j;
        float ssum = 0.f;
#pragma unroll 8
        for (int w = 0; w < 64; w++) {
            float v = p[w * SSTRIDE];
            v = (v < 0.f) ? LEAK * v : v;
            ssum += v * v;
        }
        scaleF[cap * 288 + j] = SMOOTH / (sqrtf(ssum) + EPSV);
    }
    __syncthreads();

    // ---------------- per-row epilogue (512 threads, 2 blks each) ----------
    {
        const int row = tid & 127;
        const int pair = tid >> 7;           // blk pair index 0..3
        const int cap = row >> 6;
        const int word = row & 63;
        const int mylen = cap_lens[c0 + cap];
        const bool valid = word < mylen;
        const float myw1 = ((const float*)(smem + SOFF_W1))[row];
        const float* Srow = S + row * SSTRIDE;
        float* wp = (float*)(smem + SOFF_WP);

#pragma unroll
        for (int bq = 0; bq < 2; bq++) {
            const int blk = pair * 2 + bq;
            const float* scl = scaleF + cap * 288 + blk * 36;
            float raw[36], e[36];
            {
                const float4* p4 = (const float4*)(Srow + blk * 36);
#pragma unroll
                for (int q = 0; q < 9; q++) {
                    float4 v = p4[q];
                    raw[q * 4 + 0] = v.x; raw[q * 4 + 1] = v.y;
                    raw[q * 4 + 2] = v.z; raw[q * 4 + 3] = v.w;
                }
            }
            float se = 0.f;
#pragma unroll
            for (int r = 0; r < 36; r++) {
                float v = raw[r];
                float l = ((v < 0.f) ? LEAK * v : v) * scl[r];
                e[r] = __expf(l);
                se += e[r];
            }
            float inv = 1.f / se;
            float w12 = 0.f;
#pragma unroll
            for (int r = 0; r < 36; r++) w12 += e[r] * raw[r];
            w12 *= inv;

            unsigned long long ep[18];
#pragma unroll
            for (int q = 0; q < 18; q++) ep[q] = pack2(e[2 * q], e[2 * q + 1]);
            const unsigned long long* Gb =
                (const unsigned long long*)(smem + SOFF_G) + (size_t)blk * NREG * 20;
            float t = 0.f;
#pragma unroll
            for (int r = 0; r < 36; r++) {
                const unsigned long long* grow = Gb + r * 20;
                unsigned long long d2 = 0ull;
#pragma unroll
                for (int q = 0; q < 18; q++) ffma2(d2, grow[q], ep[q]);
                float dlo, dhi;
                unpack2(d2, dlo, dhi);
                t += e[r] * (dlo + dhi);
            }
            float w2 = sqrtf(t) * inv;
            float sim = w12 / fmaxf(myw1 * w2, EPSV);
            sim = valid ? sim : 0.f;

            float ssum = warpSum(sim);
            if (lane == 0) wp[wid * 2 + bq] = ssum;
        }
    }
    __syncthreads();
    if (tid < 16) {
        int cc = tid >> 3, blk = tid & 7;
        int p = blk >> 1, b = blk & 1;
        float* wp = (float*)(smem + SOFF_WP);
        int w0 = p * 4 + cc * 2;
        float s = wp[w0 * 2 + b] + wp[(w0 + 1) * 2 + b];
        out[(size_t)(i0 + blk) * NCAP + (c0 + cc)] = s / (float)cap_lens[c0 + cc];
    }
}

// ---------------------------------------------------------------------------
extern "C" void kernel_launch(void* const* d_in, const int* in_sizes, int n_in,
                              void* d_out, int out_size) {
    const float* imgs     = (const float*)d_in[0];
    const float* caps     = (const float*)d_in[1];
    const int*   cap_lens = (const int*)d_in[3];
    float*       out      = (float*)d_out;

    prep_kernel<<<512, 256>>>(imgs, caps, cap_lens);

    cudaFuncSetAttribute(main_kernel, cudaFuncAttributeMaxDynamicSharedMemorySize,
                         SMEM_TOTAL_MAIN);
    dim3 grid(NIMG / 8, NCAP / 2);
    main_kernel<<<grid, 512, SMEM_TOTAL_MAIN>>>(cap_lens, out);
}

// round 9
// speedup vs baseline: 8.5945x; 1.0979x over previous
#include <cuda_runtime.h>
#include <cuda_fp16.h>
#include <cstdint>
#include <math.h>

#define NIMG 256
#define NREG 36
#define NCAP 256
#define MAXW 60
#define CAPW 64
#define DIM  1024

#define SMOOTH 9.0f
#define EPSV   1e-8f
#define LEAK   0.1f

// ---------------------------------------------------------------------------
// Device global scratch
// ---------------------------------------------------------------------------
__device__ __half g_caps_h[NCAP * CAPW * DIM];
__device__ __half g_imgs_h[NIMG * NREG * DIM];
__device__ float g_G[NIMG * NREG * NREG];
__device__ float g_w1[NCAP * MAXW];

// ---------------------------------------------------------------------------
// Helpers
// ---------------------------------------------------------------------------
__device__ __forceinline__ uint32_t smem_to_u32(const void* p) {
    uint32_t a;
    asm("{ .reg .u64 t; cvta.to.shared.u64 t, %1; cvt.u32.u64 %0, t; }"
        : "=r"(a) : "l"(p));
    return a;
}
__device__ __forceinline__ void cp16(uint32_t dst, const void* src) {
    asm volatile("cp.async.cg.shared.global [%0], [%1], 16;" :: "r"(dst), "l"(src) : "memory");
}
__device__ __forceinline__ void ldsm_x4(uint32_t &r0, uint32_t &r1, uint32_t &r2,
                                        uint32_t &r3, uint32_t addr) {
    asm volatile("ldmatrix.sync.aligned.m8n8.x4.shared.b16 {%0,%1,%2,%3}, [%4];"
                 : "=r"(r0), "=r"(r1), "=r"(r2), "=r"(r3) : "r"(addr));
}
__device__ __forceinline__ void ldsm_x2(uint32_t &r0, uint32_t &r1, uint32_t addr) {
    asm volatile("ldmatrix.sync.aligned.m8n8.x2.shared.b16 {%0,%1}, [%2];"
                 : "=r"(r0), "=r"(r1) : "r"(addr));
}
__device__ __forceinline__ void mma_f16(float &c0, float &c1, float &c2, float &c3,
                                        uint32_t a0, uint32_t a1, uint32_t a2, uint32_t a3,
                                        uint32_t b0, uint32_t b1) {
    asm volatile("mma.sync.aligned.m16n8k16.row.col.f32.f16.f16.f32 "
                 "{%0,%1,%2,%3}, {%4,%5,%6,%7}, {%8,%9}, {%0,%1,%2,%3};"
                 : "+f"(c0), "+f"(c1), "+f"(c2), "+f"(c3)
                 : "r"(a0), "r"(a1), "r"(a2), "r"(a3), "r"(b0), "r"(b1));
}
__device__ __forceinline__ unsigned long long pack2(float lo, float hi) {
    unsigned long long r;
    asm("mov.b64 %0, {%1, %2};" : "=l"(r) : "f"(lo), "f"(hi));
    return r;
}
__device__ __forceinline__ void unpack2(unsigned long long v, float &lo, float &hi) {
    asm("mov.b64 {%0, %1}, %2;" : "=f"(lo), "=f"(hi) : "l"(v));
}
__device__ __forceinline__ void ffma2(unsigned long long &d,
                                      unsigned long long a,
                                      unsigned long long b) {
    asm("fma.rn.f32x2 %0, %1, %2, %0;" : "+l"(d) : "l"(a), "l"(b));
}
__device__ __forceinline__ float warpSum(float v) {
    v += __shfl_xor_sync(0xffffffffu, v, 16);
    v += __shfl_xor_sync(0xffffffffu, v, 8);
    v += __shfl_xor_sync(0xffffffffu, v, 4);
    v += __shfl_xor_sync(0xffffffffu, v, 2);
    v += __shfl_xor_sync(0xffffffffu, v, 1);
    return v;
}

// ---------------------------------------------------------------------------
// Merged prep: blocks [0,256) caps; [256,512) imgs + Gram
// ---------------------------------------------------------------------------
__global__ void prep_kernel(const float* __restrict__ imgs,
                            const float* __restrict__ caps,
                            const int* __restrict__ cap_lens) {
    __shared__ float chunk[NREG * 132];
    if (blockIdx.x < 256) {
        const int c = blockIdx.x;
        const int wid = threadIdx.x >> 5, lane = threadIdx.x & 31;
        const int len = cap_lens[c];
        for (int w = wid; w < CAPW; w += 8) {
            size_t dsto = ((size_t)c * CAPW + w) * DIM;
            if (w < len) {
                const float* row = caps + ((size_t)c * MAXW + w) * DIM;
                float ss = 0.f;
#pragma unroll
                for (int j = 0; j < 8; j++) {
                    float4 v = *(const float4*)(row + j * 128 + lane * 4);
                    ss += v.x * v.x + v.y * v.y + v.z * v.z + v.w * v.w;
                    size_t o = dsto + j * 128 + lane * 4;
                    *(__half2*)(g_caps_h + o)     = __floats2half2_rn(v.x, v.y);
                    *(__half2*)(g_caps_h + o + 2) = __floats2half2_rn(v.z, v.w);
                }
                ss = warpSum(ss);
                if (lane == 0 && w < MAXW) g_w1[c * MAXW + w] = sqrtf(ss);
            } else {
                uint2 z = make_uint2(0u, 0u);
#pragma unroll
                for (int j = 0; j < 8; j++)
                    *(uint2*)(g_caps_h + dsto + j * 128 + lane * 4) = z;
                if (lane == 0 && w < MAXW) g_w1[c * MAXW + w] = 0.f;
            }
        }
    } else {
        const int i = blockIdx.x - 256;
        float acc[6];
#pragma unroll
        for (int j = 0; j < 6; j++) acc[j] = 0.f;
        for (int d0 = 0; d0 < DIM; d0 += 128) {
            __syncthreads();
            for (int idx = threadIdx.x; idx < NREG * 32; idx += 256) {
                int r = idx >> 5, dq = idx & 31;
                size_t e = ((size_t)i * NREG + r) * DIM + d0 + dq * 4;
                float4 v = *(const float4*)(imgs + e);
                *(float4*)(chunk + r * 132 + dq * 4) = v;
                *(__half2*)(g_imgs_h + e)     = __floats2half2_rn(v.x, v.y);
                *(__half2*)(g_imgs_h + e + 2) = __floats2half2_rn(v.z, v.w);
            }
            __syncthreads();
#pragma unroll
            for (int j = 0; j < 6; j++) {
                int p = threadIdx.x + j * 256;
                if (p < NREG * NREG) {
                    int r = p / NREG, rp = p - r * NREG;
                    const float4* A = (const float4*)(chunk + r * 132);
                    const float4* B = (const float4*)(chunk + rp * 132);
                    float s = 0.f;
#pragma unroll
                    for (int q = 0; q < 32; q++) {
                        float4 a = A[q], b = B[q];
                        s += a.x * b.x + a.y * b.y + a.z * b.z + a.w * b.w;
                    }
                    acc[j] += s;
                }
            }
        }
#pragma unroll
        for (int j = 0; j < 6; j++) {
            int p = threadIdx.x + j * 256;
            if (p < NREG * NREG) g_G[(size_t)i * NREG * NREG + p] = acc[j];
        }
    }
}

// ---------------------------------------------------------------------------
// Main fused kernel: fp16 GEMM M=128 x N=288 x K=1024 + SCAN epilogue.
// ---------------------------------------------------------------------------
#define STAGE_BYTES 53248
#define SB_OFF      16384
#define SOFF_SCALE  149504
#define SOFF_W1     151808
#define SOFF_WP     152320
#define SOFF_G      152448
#define SMEM_TOTAL_MAIN 198528
#define NCHUNK 16
#define SSTRIDE 292   // floats per S row

__device__ __forceinline__ void load_stage(uint32_t sbase, int chunk, int tid,
                                           int arowbase, int browbase) {
    const int k0 = chunk << 6;
    const uint32_t sA = sbase + (chunk % 3) * STAGE_BYTES;
    const uint32_t sB = sA + SB_OFF;
#pragma unroll
    for (int t = 0; t < 2; t++) {
        int o = tid + t * 512;
        int row = o >> 3, seg = o & 7;
        cp16(sA + row * 128 + (((seg ^ (row & 7))) << 4),
             g_caps_h + (((size_t)(arowbase + row)) << 10) + k0 + (seg << 3));
    }
#pragma unroll
    for (int t = 0; t < 5; t++) {
        int o = tid + t * 512;
        if (o < 2304) {
            int row = o >> 3, seg = o & 7;
            cp16(sB + row * 128 + (((seg ^ (row & 7))) << 4),
                 g_imgs_h + (((size_t)(browbase + row)) << 10) + k0 + (seg << 3));
        }
    }
    asm volatile("cp.async.commit_group;" ::: "memory");
}

__global__ void __launch_bounds__(512, 1)
main_kernel(const int* __restrict__ cap_lens, float* __restrict__ out) {
    extern __shared__ __align__(16) char smem[];
    const uint32_t sb = smem_to_u32(smem);
    const int tid = threadIdx.x, lane = tid & 31, wid = tid >> 5;
    const int c0 = blockIdx.y * 2;
    const int i0 = blockIdx.x * 8;
    const int arowbase = blockIdx.y * 128;
    const int browbase = blockIdx.x * 288;

    float acc[72];
#pragma unroll
    for (int j = 0; j < 72; j++) acc[j] = 0.f;

    load_stage(sb, 0, tid, arowbase, browbase);
    load_stage(sb, 1, tid, arowbase, browbase);

    const int mbase = (wid & 3) * 32;
    const int ncb = (wid >> 2) * 72;
    const int a_roff = lane & 15;
    const int a_seg0 = lane >> 4;
    const int b_roff = ((lane >> 4) << 3) + (lane & 7);
    const int b_seg0 = (lane >> 3) & 1;
    const int l16 = lane & 15;
    const int b2_roff = l16 & 7;
    const int b2_seg0 = (l16 >> 3) & 1;
    const int sw = lane & 7;

    for (int i = 0; i < NCHUNK; i++) {
        if (i == NCHUNK - 1) asm volatile("cp.async.wait_group 0;" ::: "memory");
        else                 asm volatile("cp.async.wait_group 1;" ::: "memory");
        __syncthreads();
        if (i + 2 < NCHUNK)
            load_stage(sb, i + 2, tid, arowbase, browbase);

        const uint32_t As = sb + (i % 3) * STAGE_BYTES;
        const uint32_t Bs = As + SB_OFF;
#pragma unroll
        for (int ks = 0; ks < 4; ks++) {
            uint32_t a[2][4];
#pragma unroll
            for (int s2 = 0; s2 < 2; s2++) {
                int row = mbase + s2 * 16 + a_roff;
                int seg = (ks * 2 + a_seg0) ^ sw;
                ldsm_x4(a[s2][0], a[s2][1], a[s2][2], a[s2][3],
                        As + row * 128 + (seg << 4));
            }
            uint32_t bh0, bh1;
            {
                int row = ncb + 64 + b2_roff;
                int seg = (ks * 2 + b2_seg0) ^ sw;
                ldsm_x2(bh0, bh1, Bs + row * 128 + (seg << 4));
            }
#pragma unroll
            for (int t = 0; t < 4; t++) {
                uint32_t b0, b1, b2, b3;
                int row = ncb + t * 16 + b_roff;
                int seg = (ks * 2 + b_seg0) ^ sw;
                ldsm_x4(b0, b1, b2, b3, Bs + row * 128 + (seg << 4));
#pragma unroll
                for (int s2 = 0; s2 < 2; s2++) {
                    int j0 = s2 * 36 + t * 8;
                    mma_f16(acc[j0 + 0], acc[j0 + 1], acc[j0 + 2], acc[j0 + 3],
                            a[s2][0], a[s2][1], a[s2][2], a[s2][3], b0, b1);
                    mma_f16(acc[j0 + 4], acc[j0 + 5], acc[j0 + 6], acc[j0 + 7],
                            a[s2][0], a[s2][1], a[s2][2], a[s2][3], b2, b3);
                }
            }
#pragma unroll
            for (int s2 = 0; s2 < 2; s2++) {
                int j0 = s2 * 36 + 32;
                mma_f16(acc[j0 + 0], acc[j0 + 1], acc[j0 + 2], acc[j0 + 3],
                        a[s2][0], a[s2][1], a[s2][2], a[s2][3], bh0, bh1);
            }
        }
    }
    __syncthreads();   // stages fully consumed before S overwrites them

    // ---------------- write S + stage Gram (zero-padded to 40) / w1 --------
    float* S = (float*)smem;
    {
        const int cA = (lane & 3) * 2;
        const int rA = lane >> 2;
#pragma unroll
        for (int s2 = 0; s2 < 2; s2++) {
            int r1 = mbase + s2 * 16 + rA;
#pragma unroll
            for (int j = 0; j < 9; j++) {
                int col = ncb + j * 8 + cA;
                *(float2*)(S + r1 * SSTRIDE + col) =
                    make_float2(acc[s2 * 36 + j * 4 + 0], acc[s2 * 36 + j * 4 + 1]);
                *(float2*)(S + (r1 + 8) * SSTRIDE + col) =
                    make_float2(acc[s2 * 36 + j * 4 + 2], acc[s2 * 36 + j * 4 + 3]);
            }
        }
    }
    {
        float* Gs = (float*)(smem + SOFF_G);
        if (tid < 8 * NREG) {
            int blk = tid / NREG, r = tid - blk * NREG;
            const float4* src = (const float4*)(g_G + ((size_t)(i0 + blk) * NREG + r) * NREG);
            float4* dst = (float4*)(Gs + (blk * NREG + r) * 40);
#pragma unroll
            for (int q = 0; q < 9; q++) dst[q] = src[q];
            dst[9] = make_float4(0.f, 0.f, 0.f, 0.f);
        }
        float* w1s = (float*)(smem + SOFF_W1);
        if (tid >= 384) {
            int p = tid - 384;
            int cc = p >> 6, w = p & 63;
            w1s[p] = (w < MAXW) ? g_w1[(c0 + cc) * MAXW + w] : 0.f;
        }
    }
    __syncthreads();

    // ---------------- column norms -> scale (loop bounded by cap_len) ------
    float* scaleF = (float*)(smem + SOFF_SCALE);
    for (int task = tid; task < 576; task += 512) {
        int cap = task >= 288;
        int j = task - cap * 288;
        int lenc = cap_lens[c0 + cap];
        const float* p = S + (cap * 64) * SSTRIDE + j;
        float ssum = 0.f;
        for (int w = 0; w < lenc; w++) {
            float v = p[w * SSTRIDE];
            v = (v < 0.f) ? LEAK * v : v;
            ssum += v * v;
        }
        scaleF[cap * 288 + j] = SMOOTH / (sqrtf(ssum) + EPSV);
    }
    __syncthreads();

    // ---------------- per-row epilogue (512 threads, 2 blks each) ----------
    {
        const int row = tid & 127;
        const int pair = tid >> 7;
        const int cap = row >> 6;
        const int word = row & 63;
        const int mylen = cap_lens[c0 + cap];
        const int wstart = ((wid & 1) << 5);        // warp word range start
        const bool warp_active = (wstart < mylen);
        const bool valid = word < mylen;
        float* wp = (float*)(smem + SOFF_WP);

        if (!warp_active) {
            if (lane == 0) { wp[wid * 2 + 0] = 0.f; wp[wid * 2 + 1] = 0.f; }
        } else {
            const float myw1 = ((const float*)(smem + SOFF_W1))[row];
            const float* Srow = S + row * SSTRIDE;
#pragma unroll
            for (int bq = 0; bq < 2; bq++) {
                const int blk = pair * 2 + bq;
                const float* scl = scaleF + cap * 288 + blk * 36;
                float raw[36], e[40];
                {
                    const float4* p4 = (const float4*)(Srow + blk * 36);
#pragma unroll
                    for (int q = 0; q < 9; q++) {
                        float4 v = p4[q];
                        raw[q * 4 + 0] = v.x; raw[q * 4 + 1] = v.y;
                        raw[q * 4 + 2] = v.z; raw[q * 4 + 3] = v.w;
                    }
                }
                float se = 0.f;
#pragma unroll
                for (int r = 0; r < 36; r++) {
                    float v = raw[r];
                    float l = ((v < 0.f) ? LEAK * v : v) * scl[r];
                    e[r] = __expf(l);
                    se += e[r];
                }
                e[36] = 0.f; e[37] = 0.f; e[38] = 0.f; e[39] = 0.f;
                float inv = 1.f / se;
                float w12 = 0.f;
#pragma unroll
                for (int r = 0; r < 36; r++) w12 += e[r] * raw[r];
                w12 *= inv;

                // t = e^T G e using symmetry: t = sum_r e_r (G_rr e_r + 2 sum_{q>r} G_rq e_q)
                unsigned long long ep[20];
#pragma unroll
                for (int q = 0; q < 20; q++) ep[q] = pack2(e[2 * q], e[2 * q + 1]);
                const float* Gbase =
                    (const float*)(smem + SOFF_G) + (size_t)blk * NREG * 40;
                float t = 0.f;
#pragma unroll
                for (int r = 0; r < 36; r++) {
                    const float* grow = Gbase + r * 40;
                    const unsigned long long* grow2 = (const unsigned long long*)grow;
                    float head = 0.f;
                    int q0 = r + 1;
                    if (q0 & 1) { head = grow[q0] * e[q0]; q0++; }
                    unsigned long long d2 = 0ull;
#pragma unroll
                    for (int qq = q0 >> 1; qq < 20; qq++) ffma2(d2, grow2[qq], ep[qq]);
                    float dlo, dhi;
                    unpack2(d2, dlo, dhi);
                    t += e[r] * (grow[r] * e[r] + 2.f * (head + dlo + dhi));
                }
                float w2 = sqrtf(t) * inv;
                float sim = w12 / fmaxf(myw1 * w2, EPSV);
                sim = valid ? sim : 0.f;

                float ssum = warpSum(sim);
                if (lane == 0) wp[wid * 2 + bq] = ssum;
            }
        }
    }
    __syncthreads();
    if (tid < 16) {
        int cc = tid >> 3, blk = tid & 7;
        int p = blk >> 1, b = blk & 1;
        float* wp = (float*)(smem + SOFF_WP);
        int w0 = p * 4 + cc * 2;
        float s = wp[w0 * 2 + b] + wp[(w0 + 1) * 2 + b];
        out[(size_t)(i0 + blk) * NCAP + (c0 + cc)] = s / (float)cap_lens[c0 + cc];
    }
}

// ---------------------------------------------------------------------------
extern "C" void kernel_launch(void* const* d_in, const int* in_sizes, int n_in,
                              void* d_out, int out_size) {
    const float* imgs     = (const float*)d_in[0];
    const float* caps     = (const float*)d_in[1];
    const int*   cap_lens = (const int*)d_in[3];
    float*       out      = (float*)d_out;

    prep_kernel<<<512, 256>>>(imgs, caps, cap_lens);

    cudaFuncSetAttribute(main_kernel, cudaFuncAttributeMaxDynamicSharedMemorySize,
                         SMEM_TOTAL_MAIN);
    dim3 grid(NIMG / 8, NCAP / 2);
    main_kernel<<<grid, 512, SMEM_TOTAL_MAIN>>>(cap_lens, out);
}

// round 10
// speedup vs baseline: 8.6202x; 1.0030x over previous
#include <cuda_runtime.h>
#include <cuda_fp16.h>
#include <cstdint>
#include <math.h>

#define NIMG 256
#define NREG 36
#define NCAP 256
#define MAXW 60
#define CAPW 64
#define DIM  1024

#define SMOOTH 9.0f
#define EPSV   1e-8f
#define LEAK   0.1f

// ---------------------------------------------------------------------------
// Device global scratch
// ---------------------------------------------------------------------------
__device__ __half g_caps_h[NCAP * CAPW * DIM];
__device__ __half g_imgs_h[NIMG * NREG * DIM];
__device__ float g_G[NIMG * NREG * NREG];
__device__ float g_w1[NCAP * MAXW];

// ---------------------------------------------------------------------------
// Helpers
// ---------------------------------------------------------------------------
__device__ __forceinline__ uint32_t smem_to_u32(const void* p) {
    uint32_t a;
    asm("{ .reg .u64 t; cvta.to.shared.u64 t, %1; cvt.u32.u64 %0, t; }"
        : "=r"(a) : "l"(p));
    return a;
}
__device__ __forceinline__ void cp16(uint32_t dst, const void* src) {
    asm volatile("cp.async.cg.shared.global [%0], [%1], 16;" :: "r"(dst), "l"(src) : "memory");
}
__device__ __forceinline__ void ldsm_x4(uint32_t &r0, uint32_t &r1, uint32_t &r2,
                                        uint32_t &r3, uint32_t addr) {
    asm volatile("ldmatrix.sync.aligned.m8n8.x4.shared.b16 {%0,%1,%2,%3}, [%4];"
                 : "=r"(r0), "=r"(r1), "=r"(r2), "=r"(r3) : "r"(addr));
}
__device__ __forceinline__ void ldsm_x2(uint32_t &r0, uint32_t &r1, uint32_t addr) {
    asm volatile("ldmatrix.sync.aligned.m8n8.x2.shared.b16 {%0,%1}, [%2];"
                 : "=r"(r0), "=r"(r1) : "r"(addr));
}
__device__ __forceinline__ void mma_f16(float &c0, float &c1, float &c2, float &c3,
                                        uint32_t a0, uint32_t a1, uint32_t a2, uint32_t a3,
                                        uint32_t b0, uint32_t b1) {
    asm volatile("mma.sync.aligned.m16n8k16.row.col.f32.f16.f16.f32 "
                 "{%0,%1,%2,%3}, {%4,%5,%6,%7}, {%8,%9}, {%0,%1,%2,%3};"
                 : "+f"(c0), "+f"(c1), "+f"(c2), "+f"(c3)
                 : "r"(a0), "r"(a1), "r"(a2), "r"(a3), "r"(b0), "r"(b1));
}
__device__ __forceinline__ unsigned long long pack2(float lo, float hi) {
    unsigned long long r;
    asm("mov.b64 %0, {%1, %2};" : "=l"(r) : "f"(lo), "f"(hi));
    return r;
}
__device__ __forceinline__ void unpack2(unsigned long long v, float &lo, float &hi) {
    asm("mov.b64 {%0, %1}, %2;" : "=f"(lo), "=f"(hi) : "l"(v));
}
__device__ __forceinline__ void ffma2(unsigned long long &d,
                                      unsigned long long a,
                                      unsigned long long b) {
    asm("fma.rn.f32x2 %0, %1, %2, %0;" : "+l"(d) : "l"(a), "l"(b));
}
__device__ __forceinline__ float warpSum(float v) {
    v += __shfl_xor_sync(0xffffffffu, v, 16);
    v += __shfl_xor_sync(0xffffffffu, v, 8);
    v += __shfl_xor_sync(0xffffffffu, v, 4);
    v += __shfl_xor_sync(0xffffffffu, v, 2);
    v += __shfl_xor_sync(0xffffffffu, v, 1);
    return v;
}

// ---------------------------------------------------------------------------
// Merged prep: blocks [0,256) caps; [256,512) imgs + Gram
// ---------------------------------------------------------------------------
__global__ void prep_kernel(const float* __restrict__ imgs,
                            const float* __restrict__ caps,
                            const int* __restrict__ cap_lens) {
    __shared__ float chunk[NREG * 132];
    if (blockIdx.x < 256) {
        const int c = blockIdx.x;
        const int wid = threadIdx.x >> 5, lane = threadIdx.x & 31;
        const int len = cap_lens[c];
        for (int w = wid; w < CAPW; w += 8) {
            size_t dsto = ((size_t)c * CAPW + w) * DIM;
            if (w < len) {
                const float* row = caps + ((size_t)c * MAXW + w) * DIM;
                float ss = 0.f;
#pragma unroll
                for (int j = 0; j < 8; j++) {
                    float4 v = *(const float4*)(row + j * 128 + lane * 4);
                    ss += v.x * v.x + v.y * v.y + v.z * v.z + v.w * v.w;
                    size_t o = dsto + j * 128 + lane * 4;
                    *(__half2*)(g_caps_h + o)     = __floats2half2_rn(v.x, v.y);
                    *(__half2*)(g_caps_h + o + 2) = __floats2half2_rn(v.z, v.w);
                }
                ss = warpSum(ss);
                if (lane == 0 && w < MAXW) g_w1[c * MAXW + w] = sqrtf(ss);
            } else {
                uint2 z = make_uint2(0u, 0u);
#pragma unroll
                for (int j = 0; j < 8; j++)
                    *(uint2*)(g_caps_h + dsto + j * 128 + lane * 4) = z;
                if (lane == 0 && w < MAXW) g_w1[c * MAXW + w] = 0.f;
            }
        }
    } else {
        const int i = blockIdx.x - 256;
        float acc[6];
#pragma unroll
        for (int j = 0; j < 6; j++) acc[j] = 0.f;
        for (int d0 = 0; d0 < DIM; d0 += 128) {
            __syncthreads();
            for (int idx = threadIdx.x; idx < NREG * 32; idx += 256) {
                int r = idx >> 5, dq = idx & 31;
                size_t e = ((size_t)i * NREG + r) * DIM + d0 + dq * 4;
                float4 v = *(const float4*)(imgs + e);
                *(float4*)(chunk + r * 132 + dq * 4) = v;
                *(__half2*)(g_imgs_h + e)     = __floats2half2_rn(v.x, v.y);
                *(__half2*)(g_imgs_h + e + 2) = __floats2half2_rn(v.z, v.w);
            }
            __syncthreads();
#pragma unroll
            for (int j = 0; j < 6; j++) {
                int p = threadIdx.x + j * 256;
                if (p < NREG * NREG) {
                    int r = p / NREG, rp = p - r * NREG;
                    const float4* A = (const float4*)(chunk + r * 132);
                    const float4* B = (const float4*)(chunk + rp * 132);
                    float s = 0.f;
#pragma unroll
                    for (int q = 0; q < 32; q++) {
                        float4 a = A[q], b = B[q];
                        s += a.x * b.x + a.y * b.y + a.z * b.z + a.w * b.w;
                    }
                    acc[j] += s;
                }
            }
        }
#pragma unroll
        for (int j = 0; j < 6; j++) {
            int p = threadIdx.x + j * 256;
            if (p < NREG * NREG) g_G[(size_t)i * NREG * NREG + p] = acc[j];
        }
    }
}

// ---------------------------------------------------------------------------
// Main fused kernel: fp16 GEMM M=128 x N=288 x K=1024 + SCAN epilogue.
// Warps whose 32-row M-strip is entirely padding (upper strip of a caption
// with len <= 32) skip all LDSM/MMA work.
// ---------------------------------------------------------------------------
#define STAGE_BYTES 53248
#define SB_OFF      16384
#define SOFF_SCALE  149504
#define SOFF_W1     151808
#define SOFF_WP     152320
#define SOFF_G      152448
#define SMEM_TOTAL_MAIN 198528
#define NCHUNK 16
#define SSTRIDE 292   // floats per S row

__device__ __forceinline__ void load_stage(uint32_t sbase, int chunk, int tid,
                                           int arowbase, int browbase) {
    const int k0 = chunk << 6;
    const uint32_t sA = sbase + (chunk % 3) * STAGE_BYTES;
    const uint32_t sB = sA + SB_OFF;
#pragma unroll
    for (int t = 0; t < 2; t++) {
        int o = tid + t * 512;
        int row = o >> 3, seg = o & 7;
        cp16(sA + row * 128 + (((seg ^ (row & 7))) << 4),
             g_caps_h + (((size_t)(arowbase + row)) << 10) + k0 + (seg << 3));
    }
#pragma unroll
    for (int t = 0; t < 5; t++) {
        int o = tid + t * 512;
        if (o < 2304) {
            int row = o >> 3, seg = o & 7;
            cp16(sB + row * 128 + (((seg ^ (row & 7))) << 4),
                 g_imgs_h + (((size_t)(browbase + row)) << 10) + k0 + (seg << 3));
        }
    }
    asm volatile("cp.async.commit_group;" ::: "memory");
}

__global__ void __launch_bounds__(512, 1)
main_kernel(const int* __restrict__ cap_lens, float* __restrict__ out) {
    extern __shared__ __align__(16) char smem[];
    const uint32_t sb = smem_to_u32(smem);
    const int tid = threadIdx.x, lane = tid & 31, wid = tid >> 5;
    const int c0 = blockIdx.y * 2;
    const int i0 = blockIdx.x * 8;
    const int arowbase = blockIdx.y * 128;
    const int browbase = blockIdx.x * 288;

    float acc[72];
#pragma unroll
    for (int j = 0; j < 72; j++) acc[j] = 0.f;

    load_stage(sb, 0, tid, arowbase, browbase);
    load_stage(sb, 1, tid, arowbase, browbase);

    const int mstrip = wid & 3;               // 0..3
    const int mbase = mstrip * 32;
    const int ncb = (wid >> 2) * 72;
    // GEMM-active predicate: upper strip of a caption with len<=32 is all zeros
    const bool gemm_active =
        ((mstrip & 1) == 0) || (cap_lens[c0 + (mstrip >> 1)] > 32);

    const int a_roff = lane & 15;
    const int a_seg0 = lane >> 4;
    const int b_roff = ((lane >> 4) << 3) + (lane & 7);
    const int b_seg0 = (lane >> 3) & 1;
    const int l16 = lane & 15;
    const int b2_roff = l16 & 7;
    const int b2_seg0 = (l16 >> 3) & 1;
    const int sw = lane & 7;

    for (int i = 0; i < NCHUNK; i++) {
        if (i == NCHUNK - 1) asm volatile("cp.async.wait_group 0;" ::: "memory");
        else                 asm volatile("cp.async.wait_group 1;" ::: "memory");
        __syncthreads();
        if (i + 2 < NCHUNK)
            load_stage(sb, i + 2, tid, arowbase, browbase);

        if (gemm_active) {
            const uint32_t As = sb + (i % 3) * STAGE_BYTES;
            const uint32_t Bs = As + SB_OFF;
#pragma unroll
            for (int ks = 0; ks < 4; ks++) {
                uint32_t a[2][4];
#pragma unroll
                for (int s2 = 0; s2 < 2; s2++) {
                    int row = mbase + s2 * 16 + a_roff;
                    int seg = (ks * 2 + a_seg0) ^ sw;
                    ldsm_x4(a[s2][0], a[s2][1], a[s2][2], a[s2][3],
                            As + row * 128 + (seg << 4));
                }
                uint32_t bh0, bh1;
                {
                    int row = ncb + 64 + b2_roff;
                    int seg = (ks * 2 + b2_seg0) ^ sw;
                    ldsm_x2(bh0, bh1, Bs + row * 128 + (seg << 4));
                }
#pragma unroll
                for (int t = 0; t < 4; t++) {
                    uint32_t b0, b1, b2, b3;
                    int row = ncb + t * 16 + b_roff;
                    int seg = (ks * 2 + b_seg0) ^ sw;
                    ldsm_x4(b0, b1, b2, b3, Bs + row * 128 + (seg << 4));
#pragma unroll
                    for (int s2 = 0; s2 < 2; s2++) {
                        int j0 = s2 * 36 + t * 8;
                        mma_f16(acc[j0 + 0], acc[j0 + 1], acc[j0 + 2], acc[j0 + 3],
                                a[s2][0], a[s2][1], a[s2][2], a[s2][3], b0, b1);
                        mma_f16(acc[j0 + 4], acc[j0 + 5], acc[j0 + 6], acc[j0 + 7],
                                a[s2][0], a[s2][1], a[s2][2], a[s2][3], b2, b3);
                    }
                }
#pragma unroll
                for (int s2 = 0; s2 < 2; s2++) {
                    int j0 = s2 * 36 + 32;
                    mma_f16(acc[j0 + 0], acc[j0 + 1], acc[j0 + 2], acc[j0 + 3],
                            a[s2][0], a[s2][1], a[s2][2], a[s2][3], bh0, bh1);
                }
            }
        }
    }
    __syncthreads();   // stages fully consumed before S overwrites them

    // ---------------- write S + stage Gram (zero-padded to 40) / w1 --------
    float* S = (float*)smem;
    {
        const int cA = (lane & 3) * 2;
        const int rA = lane >> 2;
#pragma unroll
        for (int s2 = 0; s2 < 2; s2++) {
            int r1 = mbase + s2 * 16 + rA;
#pragma unroll
            for (int j = 0; j < 9; j++) {
                int col = ncb + j * 8 + cA;
                *(float2*)(S + r1 * SSTRIDE + col) =
                    make_float2(acc[s2 * 36 + j * 4 + 0], acc[s2 * 36 + j * 4 + 1]);
                *(float2*)(S + (r1 + 8) * SSTRIDE + col) =
                    make_float2(acc[s2 * 36 + j * 4 + 2], acc[s2 * 36 + j * 4 + 3]);
            }
        }
    }
    {
        float* Gs = (float*)(smem + SOFF_G);
        if (tid < 8 * NREG) {
            int blk = tid / NREG, r = tid - blk * NREG;
            const float4* src = (const float4*)(g_G + ((size_t)(i0 + blk) * NREG + r) * NREG);
            float4* dst = (float4*)(Gs + (blk * NREG + r) * 40);
#pragma unroll
            for (int q = 0; q < 9; q++) dst[q] = src[q];
            dst[9] = make_float4(0.f, 0.f, 0.f, 0.f);
        }
        float* w1s = (float*)(smem + SOFF_W1);
        if (tid >= 384) {
            int p = tid - 384;
            int cc = p >> 6, w = p & 63;
            w1s[p] = (w < MAXW) ? g_w1[(c0 + cc) * MAXW + w] : 0.f;
        }
    }
    __syncthreads();

    // ---------------- column norms -> scale (loop bounded by cap_len) ------
    float* scaleF = (float*)(smem + SOFF_SCALE);
    for (int task = tid; task < 576; task += 512) {
        int cap = task >= 288;
        int j = task - cap * 288;
        int lenc = cap_lens[c0 + cap];
        const float* p = S + (cap * 64) * SSTRIDE + j;
        float ssum = 0.f;
        for (int w = 0; w < lenc; w++) {
            float v = p[w * SSTRIDE];
            v = (v < 0.f) ? LEAK * v : v;
            ssum += v * v;
        }
        scaleF[cap * 288 + j] = SMOOTH / (sqrtf(ssum) + EPSV);
    }
    __syncthreads();

    // ---------------- per-row epilogue (512 threads, 2 blks each) ----------
    {
        const int row = tid & 127;
        const int pair = tid >> 7;
        const int cap = row >> 6;
        const int word = row & 63;
        const int mylen = cap_lens[c0 + cap];
        const int wstart = ((wid & 1) << 5);
        const bool warp_active = (wstart < mylen);
        const bool valid = word < mylen;
        float* wp = (float*)(smem + SOFF_WP);

        if (!warp_active) {
            if (lane == 0) { wp[wid * 2 + 0] = 0.f; wp[wid * 2 + 1] = 0.f; }
        } else {
            const float myw1 = ((const float*)(smem + SOFF_W1))[row];
            const float* Srow = S + row * SSTRIDE;
#pragma unroll
            for (int bq = 0; bq < 2; bq++) {
                const int blk = pair * 2 + bq;
                const float* scl = scaleF + cap * 288 + blk * 36;
                float raw[36], e[40];
                {
                    const float4* p4 = (const float4*)(Srow + blk * 36);
#pragma unroll
                    for (int q = 0; q < 9; q++) {
                        float4 v = p4[q];
                        raw[q * 4 + 0] = v.x; raw[q * 4 + 1] = v.y;
                        raw[q * 4 + 2] = v.z; raw[q * 4 + 3] = v.w;
                    }
                }
                float se = 0.f;
#pragma unroll
                for (int r = 0; r < 36; r++) {
                    float v = raw[r];
                    float l = ((v < 0.f) ? LEAK * v : v) * scl[r];
                    e[r] = __expf(l);
                    se += e[r];
                }
                e[36] = 0.f; e[37] = 0.f; e[38] = 0.f; e[39] = 0.f;
                float inv = 1.f / se;
                float w12 = 0.f;
#pragma unroll
                for (int r = 0; r < 36; r++) w12 += e[r] * raw[r];
                w12 *= inv;

                // t = e^T G e via symmetry (triangular f32x2 loop)
                unsigned long long ep[20];
#pragma unroll
                for (int q = 0; q < 20; q++) ep[q] = pack2(e[2 * q], e[2 * q + 1]);
                const float* Gbase =
                    (const float*)(smem + SOFF_G) + (size_t)blk * NREG * 40;
                float t = 0.f;
#pragma unroll
                for (int r = 0; r < 36; r++) {
                    const float* grow = Gbase + r * 40;
                    const unsigned long long* grow2 = (const unsigned long long*)grow;
                    float head = 0.f;
                    int q0 = r + 1;
                    if (q0 & 1) { head = grow[q0] * e[q0]; q0++; }
                    unsigned long long d2 = 0ull;
#pragma unroll
                    for (int qq = q0 >> 1; qq < 20; qq++) ffma2(d2, grow2[qq], ep[qq]);
                    float dlo, dhi;
                    unpack2(d2, dlo, dhi);
                    t += e[r] * (grow[r] * e[r] + 2.f * (head + dlo + dhi));
                }
                float w2 = sqrtf(t) * inv;
                float sim = w12 / fmaxf(myw1 * w2, EPSV);
                sim = valid ? sim : 0.f;

                float ssum = warpSum(sim);
                if (lane == 0) wp[wid * 2 + bq] = ssum;
            }
        }
    }
    __syncthreads();
    if (tid < 16) {
        int cc = tid >> 3, blk = tid & 7;
        int p = blk >> 1, b = blk & 1;
        float* wp = (float*)(smem + SOFF_WP);
        int w0 = p * 4 + cc * 2;
        float s = wp[w0 * 2 + b] + wp[(w0 + 1) * 2 + b];
        out[(size_t)(i0 + blk) * NCAP + (c0 + cc)] = s / (float)cap_lens[c0 + cc];
    }
}

// ---------------------------------------------------------------------------
extern "C" void kernel_launch(void* const* d_in, const int* in_sizes, int n_in,
                              void* d_out, int out_size) {
    const float* imgs     = (const float*)d_in[0];
    const float* caps     = (const float*)d_in[1];
    const int*   cap_lens = (const int*)d_in[3];
    float*       out      = (float*)d_out;

    prep_kernel<<<512, 256>>>(imgs, caps, cap_lens);

    cudaFuncSetAttribute(main_kernel, cudaFuncAttributeMaxDynamicSharedMemorySize,
                         SMEM_TOTAL_MAIN);
    dim3 grid(NIMG / 8, NCAP / 2);
    main_kernel<<<grid, 512, SMEM_TOTAL_MAIN>>>(cap_lens, out);
}

// round 11
// speedup vs baseline: 9.7415x; 1.1301x over previous
#include <cuda_runtime.h>
#include <cuda_fp16.h>
#include <cstdint>
#include <math.h>

#define NIMG 256
#define NREG 36
#define NCAP 256
#define MAXW 60
#define CAPW 64
#define DIM  1024

#define SMOOTH 9.0f
#define EPSV   1e-8f
#define LEAK   0.1f

// ---------------------------------------------------------------------------
// Device global scratch
// ---------------------------------------------------------------------------
__device__ __half g_caps_h[NCAP * CAPW * DIM];
__device__ __half g_imgs_h[NIMG * NREG * DIM];
__device__ float g_G[NIMG * NREG * NREG];
__device__ float g_w1[NCAP * MAXW];

// ---------------------------------------------------------------------------
// Helpers
// ---------------------------------------------------------------------------
__device__ __forceinline__ uint32_t smem_to_u32(const void* p) {
    uint32_t a;
    asm("{ .reg .u64 t; cvta.to.shared.u64 t, %1; cvt.u32.u64 %0, t; }"
        : "=r"(a) : "l"(p));
    return a;
}
__device__ __forceinline__ void cp16(uint32_t dst, const void* src) {
    asm volatile("cp.async.cg.shared.global [%0], [%1], 16;" :: "r"(dst), "l"(src) : "memory");
}
__device__ __forceinline__ void ldsm_x4(uint32_t &r0, uint32_t &r1, uint32_t &r2,
                                        uint32_t &r3, uint32_t addr) {
    asm volatile("ldmatrix.sync.aligned.m8n8.x4.shared.b16 {%0,%1,%2,%3}, [%4];"
                 : "=r"(r0), "=r"(r1), "=r"(r2), "=r"(r3) : "r"(addr));
}
__device__ __forceinline__ void ldsm_x2(uint32_t &r0, uint32_t &r1, uint32_t addr) {
    asm volatile("ldmatrix.sync.aligned.m8n8.x2.shared.b16 {%0,%1}, [%2];"
                 : "=r"(r0), "=r"(r1) : "r"(addr));
}
__device__ __forceinline__ void mma_f16(float &c0, float &c1, float &c2, float &c3,
                                        uint32_t a0, uint32_t a1, uint32_t a2, uint32_t a3,
                                        uint32_t b0, uint32_t b1) {
    asm volatile("mma.sync.aligned.m16n8k16.row.col.f32.f16.f16.f32 "
                 "{%0,%1,%2,%3}, {%4,%5,%6,%7}, {%8,%9}, {%0,%1,%2,%3};"
                 : "+f"(c0), "+f"(c1), "+f"(c2), "+f"(c3)
                 : "r"(a0), "r"(a1), "r"(a2), "r"(a3), "r"(b0), "r"(b1));
}
__device__ __forceinline__ unsigned long long pack2(float lo, float hi) {
    unsigned long long r;
    asm("mov.b64 %0, {%1, %2};" : "=l"(r) : "f"(lo), "f"(hi));
    return r;
}
__device__ __forceinline__ void unpack2(unsigned long long v, float &lo, float &hi) {
    asm("mov.b64 {%0, %1}, %2;" : "=f"(lo), "=f"(hi) : "l"(v));
}
__device__ __forceinline__ void ffma2(unsigned long long &d,
                                      unsigned long long a,
                                      unsigned long long b) {
    asm("fma.rn.f32x2 %0, %1, %2, %0;" : "+l"(d) : "l"(a), "l"(b));
}
__device__ __forceinline__ float warpSum(float v) {
    v += __shfl_xor_sync(0xffffffffu, v, 16);
    v += __shfl_xor_sync(0xffffffffu, v, 8);
    v += __shfl_xor_sync(0xffffffffu, v, 4);
    v += __shfl_xor_sync(0xffffffffu, v, 2);
    v += __shfl_xor_sync(0xffffffffu, v, 1);
    return v;
}

// ---------------------------------------------------------------------------
// Merged prep: blocks [0,256) caps; [256,512) imgs + Gram
// ---------------------------------------------------------------------------
__global__ void prep_kernel(const float* __restrict__ imgs,
                            const float* __restrict__ caps,
                            const int* __restrict__ cap_lens) {
    __shared__ float chunk[NREG * 132];
    if (blockIdx.x < 256) {
        const int c = blockIdx.x;
        const int wid = threadIdx.x >> 5, lane = threadIdx.x & 31;
        const int len = cap_lens[c];
        for (int w = wid; w < CAPW; w += 8) {
            size_t dsto = ((size_t)c * CAPW + w) * DIM;
            if (w < len) {
                const float* row = caps + ((size_t)c * MAXW + w) * DIM;
                float ss = 0.f;
#pragma unroll
                for (int j = 0; j < 8; j++) {
                    float4 v = *(const float4*)(row + j * 128 + lane * 4);
                    ss += v.x * v.x + v.y * v.y + v.z * v.z + v.w * v.w;
                    size_t o = dsto + j * 128 + lane * 4;
                    *(__half2*)(g_caps_h + o)     = __floats2half2_rn(v.x, v.y);
                    *(__half2*)(g_caps_h + o + 2) = __floats2half2_rn(v.z, v.w);
                }
                ss = warpSum(ss);
                if (lane == 0 && w < MAXW) g_w1[c * MAXW + w] = sqrtf(ss);
            } else {
                uint2 z = make_uint2(0u, 0u);
#pragma unroll
                for (int j = 0; j < 8; j++)
                    *(uint2*)(g_caps_h + dsto + j * 128 + lane * 4) = z;
                if (lane == 0 && w < MAXW) g_w1[c * MAXW + w] = 0.f;
            }
        }
    } else {
        const int i = blockIdx.x - 256;
        float acc[6];
#pragma unroll
        for (int j = 0; j < 6; j++) acc[j] = 0.f;
        for (int d0 = 0; d0 < DIM; d0 += 128) {
            __syncthreads();
            for (int idx = threadIdx.x; idx < NREG * 32; idx += 256) {
                int r = idx >> 5, dq = idx & 31;
                size_t e = ((size_t)i * NREG + r) * DIM + d0 + dq * 4;
                float4 v = *(const float4*)(imgs + e);
                *(float4*)(chunk + r * 132 + dq * 4) = v;
                *(__half2*)(g_imgs_h + e)     = __floats2half2_rn(v.x, v.y);
                *(__half2*)(g_imgs_h + e + 2) = __floats2half2_rn(v.z, v.w);
            }
            __syncthreads();
#pragma unroll
            for (int j = 0; j < 6; j++) {
                int p = threadIdx.x + j * 256;
                if (p < NREG * NREG) {
                    int r = p / NREG, rp = p - r * NREG;
                    const float4* A = (const float4*)(chunk + r * 132);
                    const float4* B = (const float4*)(chunk + rp * 132);
                    float s = 0.f;
#pragma unroll
                    for (int q = 0; q < 32; q++) {
                        float4 a = A[q], b = B[q];
                        s += a.x * b.x + a.y * b.y + a.z * b.z + a.w * b.w;
                    }
                    acc[j] += s;
                }
            }
        }
#pragma unroll
        for (int j = 0; j < 6; j++) {
            int p = threadIdx.x + j * 256;
            if (p < NREG * NREG) g_G[(size_t)i * NREG * NREG + p] = acc[j];
        }
    }
}

// ---------------------------------------------------------------------------
// Main fused kernel: fp16 GEMM M=128 x N=144 x K=1024 + SCAN epilogue.
// 256 threads / 8 warps (warp tile 32x72), 3-stage pipeline, 2 CTAs/SM.
// ---------------------------------------------------------------------------
#define STAGE_BYTES 34816
#define SB_OFF      16384
#define SOFF_SCALE  75776
#define SOFF_W1     76928
#define SOFF_WP     77440
#define SOFF_G      77504
#define SMEM_TOTAL_MAIN 104448
#define NCHUNK 16
#define SSTRIDE 148   // floats per S row

__device__ __forceinline__ void load_stage(uint32_t sbase, int chunk, int tid,
                                           int arowbase, int browbase) {
    const int k0 = chunk << 6;
    const uint32_t sA = sbase + (chunk % 3) * STAGE_BYTES;
    const uint32_t sB = sA + SB_OFF;
#pragma unroll
    for (int t = 0; t < 4; t++) {
        int o = tid + t * 256;                 // 1024 A lines
        int row = o >> 3, seg = o & 7;
        cp16(sA + row * 128 + (((seg ^ (row & 7))) << 4),
             g_caps_h + (((size_t)(arowbase + row)) << 10) + k0 + (seg << 3));
    }
#pragma unroll
    for (int t = 0; t < 4; t++) {
        int o = tid + t * 256;                 // first 1024 B lines
        int row = o >> 3, seg = o & 7;
        cp16(sB + row * 128 + (((seg ^ (row & 7))) << 4),
             g_imgs_h + (((size_t)(browbase + row)) << 10) + k0 + (seg << 3));
    }
    {   // B tail rows 128..143
        int o = tid + 1024;
        if (o < 1152) {
            int row = o >> 3, seg = o & 7;
            cp16(sB + row * 128 + (((seg ^ (row & 7))) << 4),
                 g_imgs_h + (((size_t)(browbase + row)) << 10) + k0 + (seg << 3));
        }
    }
    asm volatile("cp.async.commit_group;" ::: "memory");
}

__global__ void __launch_bounds__(256, 2)
main_kernel(const int* __restrict__ cap_lens, float* __restrict__ out) {
    extern __shared__ __align__(16) char smem[];
    const uint32_t sb = smem_to_u32(smem);
    const int tid = threadIdx.x, lane = tid & 31, wid = tid >> 5;
    const int c0 = blockIdx.y * 2;
    const int i0 = blockIdx.x * 4;
    const int arowbase = blockIdx.y * 128;
    const int browbase = blockIdx.x * 144;

    float acc[72];
#pragma unroll
    for (int j = 0; j < 72; j++) acc[j] = 0.f;

    load_stage(sb, 0, tid, arowbase, browbase);
    load_stage(sb, 1, tid, arowbase, browbase);

    const int mstrip = wid & 3;
    const int mbase = mstrip * 32;
    const int ncb = (wid >> 2) * 72;
    // upper strip of a caption with len<=32 is all zeros -> skip GEMM work
    const bool gemm_active =
        ((mstrip & 1) == 0) || (cap_lens[c0 + (mstrip >> 1)] > 32);

    const int a_roff = lane & 15;
    const int a_seg0 = lane >> 4;
    const int b_roff = ((lane >> 4) << 3) + (lane & 7);
    const int b_seg0 = (lane >> 3) & 1;
    const int l16 = lane & 15;
    const int b2_roff = l16 & 7;
    const int b2_seg0 = (l16 >> 3) & 1;
    const int sw = lane & 7;

    for (int i = 0; i < NCHUNK; i++) {
        if (i == NCHUNK - 1) asm volatile("cp.async.wait_group 0;" ::: "memory");
        else                 asm volatile("cp.async.wait_group 1;" ::: "memory");
        __syncthreads();
        if (i + 2 < NCHUNK)
            load_stage(sb, i + 2, tid, arowbase, browbase);

        if (gemm_active) {
            const uint32_t As = sb + (i % 3) * STAGE_BYTES;
            const uint32_t Bs = As + SB_OFF;
#pragma unroll
            for (int ks = 0; ks < 4; ks++) {
                uint32_t a[2][4];
#pragma unroll
                for (int s2 = 0; s2 < 2; s2++) {
                    int row = mbase + s2 * 16 + a_roff;
                    int seg = (ks * 2 + a_seg0) ^ sw;
                    ldsm_x4(a[s2][0], a[s2][1], a[s2][2], a[s2][3],
                            As + row * 128 + (seg << 4));
                }
                uint32_t bh0, bh1;
                {
                    int row = ncb + 64 + b2_roff;
                    int seg = (ks * 2 + b2_seg0) ^ sw;
                    ldsm_x2(bh0, bh1, Bs + row * 128 + (seg << 4));
                }
#pragma unroll
                for (int t = 0; t < 4; t++) {
                    uint32_t b0, b1, b2, b3;
                    int row = ncb + t * 16 + b_roff;
                    int seg = (ks * 2 + b_seg0) ^ sw;
                    ldsm_x4(b0, b1, b2, b3, Bs + row * 128 + (seg << 4));
#pragma unroll
                    for (int s2 = 0; s2 < 2; s2++) {
                        int j0 = s2 * 36 + t * 8;
                        mma_f16(acc[j0 + 0], acc[j0 + 1], acc[j0 + 2], acc[j0 + 3],
                                a[s2][0], a[s2][1], a[s2][2], a[s2][3], b0, b1);
                        mma_f16(acc[j0 + 4], acc[j0 + 5], acc[j0 + 6], acc[j0 + 7],
                                a[s2][0], a[s2][1], a[s2][2], a[s2][3], b2, b3);
                    }
                }
#pragma unroll
                for (int s2 = 0; s2 < 2; s2++) {
                    int j0 = s2 * 36 + 32;
                    mma_f16(acc[j0 + 0], acc[j0 + 1], acc[j0 + 2], acc[j0 + 3],
                            a[s2][0], a[s2][1], a[s2][2], a[s2][3], bh0, bh1);
                }
            }
        }
    }
    __syncthreads();   // stages fully consumed before S overwrites them

    // ---------------- write S + stage Gram (zero-padded to 40) / w1 --------
    float* S = (float*)smem;
    {
        const int cA = (lane & 3) * 2;
        const int rA = lane >> 2;
#pragma unroll
        for (int s2 = 0; s2 < 2; s2++) {
            int r1 = mbase + s2 * 16 + rA;
#pragma unroll
            for (int j = 0; j < 9; j++) {
                int col = ncb + j * 8 + cA;
                *(float2*)(S + r1 * SSTRIDE + col) =
                    make_float2(acc[s2 * 36 + j * 4 + 0], acc[s2 * 36 + j * 4 + 1]);
                *(float2*)(S + (r1 + 8) * SSTRIDE + col) =
                    make_float2(acc[s2 * 36 + j * 4 + 2], acc[s2 * 36 + j * 4 + 3]);
            }
        }
    }
    {
        float* Gs = (float*)(smem + SOFF_G);
        if (tid < 4 * NREG) {
            int blk = tid / NREG, r = tid - blk * NREG;
            const float4* src = (const float4*)(g_G + ((size_t)(i0 + blk) * NREG + r) * NREG);
            float4* dst = (float4*)(Gs + (blk * NREG + r) * 40);
#pragma unroll
            for (int q = 0; q < 9; q++) dst[q] = src[q];
            dst[9] = make_float4(0.f, 0.f, 0.f, 0.f);
        }
        float* w1s = (float*)(smem + SOFF_W1);
        if (tid >= 128) {
            int p = tid - 128;
            int cc = p >> 6, w = p & 63;
            w1s[p] = (w < MAXW) ? g_w1[(c0 + cc) * MAXW + w] : 0.f;
        }
    }
    __syncthreads();

    // ---------------- column norms -> scale (loop bounded by cap_len) ------
    float* scaleF = (float*)(smem + SOFF_SCALE);
    for (int task = tid; task < 288; task += 256) {
        int cap = task >= 144;
        int j = task - cap * 144;
        int lenc = cap_lens[c0 + cap];
        const float* p = S + (cap * 64) * SSTRIDE + j;
        float ssum = 0.f;
        for (int w = 0; w < lenc; w++) {
            float v = p[w * SSTRIDE];
            v = (v < 0.f) ? LEAK * v : v;
            ssum += v * v;
        }
        scaleF[cap * 144 + j] = SMOOTH / (sqrtf(ssum) + EPSV);
    }
    __syncthreads();

    // ---------------- per-row epilogue (256 threads, 2 blks each) ----------
    {
        const int row = tid & 127;
        const int pair = tid >> 7;              // 0: blks {0,1}; 1: blks {2,3}
        const int cap = row >> 6;
        const int word = row & 63;
        const int mylen = cap_lens[c0 + cap];
        const int wstart = ((wid & 1) << 5);
        const bool warp_active = (wstart < mylen);
        const bool valid = word < mylen;
        float* wp = (float*)(smem + SOFF_WP);

        if (!warp_active) {
            if (lane == 0) { wp[wid * 2 + 0] = 0.f; wp[wid * 2 + 1] = 0.f; }
        } else {
            const float myw1 = ((const float*)(smem + SOFF_W1))[row];
            const float* Srow = S + row * SSTRIDE;
#pragma unroll
            for (int bq = 0; bq < 2; bq++) {
                const int blk = pair * 2 + bq;
                const float* scl = scaleF + cap * 144 + blk * 36;
                float raw[36], e[40];
                {
                    const float4* p4 = (const float4*)(Srow + blk * 36);
#pragma unroll
                    for (int q = 0; q < 9; q++) {
                        float4 v = p4[q];
                        raw[q * 4 + 0] = v.x; raw[q * 4 + 1] = v.y;
                        raw[q * 4 + 2] = v.z; raw[q * 4 + 3] = v.w;
                    }
                }
                float se = 0.f;
#pragma unroll
                for (int r = 0; r < 36; r++) {
                    float v = raw[r];
                    float l = ((v < 0.f) ? LEAK * v : v) * scl[r];
                    e[r] = __expf(l);
                    se += e[r];
                }
                e[36] = 0.f; e[37] = 0.f; e[38] = 0.f; e[39] = 0.f;
                float inv = 1.f / se;
                float w12 = 0.f;
#pragma unroll
                for (int r = 0; r < 36; r++) w12 += e[r] * raw[r];
                w12 *= inv;

                // t = e^T G e via symmetry (triangular f32x2 loop)
                unsigned long long ep[20];
#pragma unroll
                for (int q = 0; q < 20; q++) ep[q] = pack2(e[2 * q], e[2 * q + 1]);
                const float* Gbase =
                    (const float*)(smem + SOFF_G) + (size_t)blk * NREG * 40;
                float t = 0.f;
#pragma unroll
                for (int r = 0; r < 36; r++) {
                    const float* grow = Gbase + r * 40;
                    const unsigned long long* grow2 = (const unsigned long long*)grow;
                    float head = 0.f;
                    int q0 = r + 1;
                    if (q0 & 1) { head = grow[q0] * e[q0]; q0++; }
                    unsigned long long d2 = 0ull;
#pragma unroll
                    for (int qq = q0 >> 1; qq < 20; qq++) ffma2(d2, grow2[qq], ep[qq]);
                    float dlo, dhi;
                    unpack2(d2, dlo, dhi);
                    t += e[r] * (grow[r] * e[r] + 2.f * (head + dlo + dhi));
                }
                float w2 = sqrtf(t) * inv;
                float sim = w12 / fmaxf(myw1 * w2, EPSV);
                sim = valid ? sim : 0.f;

                float ssum = warpSum(sim);
                if (lane == 0) wp[wid * 2 + bq] = ssum;
            }
        }
    }
    __syncthreads();
    if (tid < 8) {
        int blk = tid & 3, cc = tid >> 2;
        int p = blk >> 1, b = blk & 1;
        float* wp = (float*)(smem + SOFF_WP);
        int w0 = p * 4 + cc * 2;
        float s = wp[w0 * 2 + b] + wp[(w0 + 1) * 2 + b];
        out[(size_t)(i0 + blk) * NCAP + (c0 + cc)] = s / (float)cap_lens[c0 + cc];
    }
}

// ---------------------------------------------------------------------------
extern "C" void kernel_launch(void* const* d_in, const int* in_sizes, int n_in,
                              void* d_out, int out_size) {
    const float* imgs     = (const float*)d_in[0];
    const float* caps     = (const float*)d_in[1];
    const int*   cap_lens = (const int*)d_in[3];
    float*       out      = (float*)d_out;

    prep_kernel<<<512, 256>>>(imgs, caps, cap_lens);

    cudaFuncSetAttribute(main_kernel, cudaFuncAttributeMaxDynamicSharedMemorySize,
                         SMEM_TOTAL_MAIN);
    dim3 grid(NIMG / 4, NCAP / 2);
    main_kernel<<<grid, 256, SMEM_TOTAL_MAIN>>>(cap_lens, out);
}

// round 12
// speedup vs baseline: 9.8464x; 1.0108x over previous
#include <cuda_runtime.h>
#include <cuda_fp16.h>
#include <cstdint>
#include <math.h>

#define NIMG 256
#define NREG 36
#define NCAP 256
#define MAXW 60
#define CAPW 64
#define DIM  1024

#define SMOOTH 9.0f
#define EPSV   1e-8f
#define LEAK   0.1f

// ---------------------------------------------------------------------------
// Device global scratch
// ---------------------------------------------------------------------------
__device__ __half g_caps_h[NCAP * CAPW * DIM];
__device__ __half g_imgs_h[NIMG * NREG * DIM];
__device__ float g_G[NIMG * NREG * NREG];
__device__ float g_w1[NCAP * MAXW];

// ---------------------------------------------------------------------------
// Helpers
// ---------------------------------------------------------------------------
__device__ __forceinline__ uint32_t smem_to_u32(const void* p) {
    uint32_t a;
    asm("{ .reg .u64 t; cvta.to.shared.u64 t, %1; cvt.u32.u64 %0, t; }"
        : "=r"(a) : "l"(p));
    return a;
}
__device__ __forceinline__ void cp16(uint32_t dst, const void* src) {
    asm volatile("cp.async.cg.shared.global [%0], [%1], 16;" :: "r"(dst), "l"(src) : "memory");
}
__device__ __forceinline__ void ldsm_x4(uint32_t &r0, uint32_t &r1, uint32_t &r2,
                                        uint32_t &r3, uint32_t addr) {
    asm volatile("ldmatrix.sync.aligned.m8n8.x4.shared.b16 {%0,%1,%2,%3}, [%4];"
                 : "=r"(r0), "=r"(r1), "=r"(r2), "=r"(r3) : "r"(addr));
}
__device__ __forceinline__ void ldsm_x2(uint32_t &r0, uint32_t &r1, uint32_t addr) {
    asm volatile("ldmatrix.sync.aligned.m8n8.x2.shared.b16 {%0,%1}, [%2];"
                 : "=r"(r0), "=r"(r1) : "r"(addr));
}
__device__ __forceinline__ void mma_f16(float &c0, float &c1, float &c2, float &c3,
                                        uint32_t a0, uint32_t a1, uint32_t a2, uint32_t a3,
                                        uint32_t b0, uint32_t b1) {
    asm volatile("mma.sync.aligned.m16n8k16.row.col.f32.f16.f16.f32 "
                 "{%0,%1,%2,%3}, {%4,%5,%6,%7}, {%8,%9}, {%0,%1,%2,%3};"
                 : "+f"(c0), "+f"(c1), "+f"(c2), "+f"(c3)
                 : "r"(a0), "r"(a1), "r"(a2), "r"(a3), "r"(b0), "r"(b1));
}
__device__ __forceinline__ unsigned long long pack2(float lo, float hi) {
    unsigned long long r;
    asm("mov.b64 %0, {%1, %2};" : "=l"(r) : "f"(lo), "f"(hi));
    return r;
}
__device__ __forceinline__ void unpack2(unsigned long long v, float &lo, float &hi) {
    asm("mov.b64 {%0, %1}, %2;" : "=f"(lo), "=f"(hi) : "l"(v));
}
__device__ __forceinline__ void ffma2(unsigned long long &d,
                                      unsigned long long a,
                                      unsigned long long b) {
    asm("fma.rn.f32x2 %0, %1, %2, %0;" : "+l"(d) : "l"(a), "l"(b));
}
__device__ __forceinline__ float warpSum(float v) {
    v += __shfl_xor_sync(0xffffffffu, v, 16);
    v += __shfl_xor_sync(0xffffffffu, v, 8);
    v += __shfl_xor_sync(0xffffffffu, v, 4);
    v += __shfl_xor_sync(0xffffffffu, v, 2);
    v += __shfl_xor_sync(0xffffffffu, v, 1);
    return v;
}
__device__ __forceinline__ float dot4(float4 a, float4 b) {
    return a.x * b.x + a.y * b.y + a.z * b.z + a.w * b.w;
}

// ---------------------------------------------------------------------------
// Merged prep: blocks [0,256) caps; [256,512) imgs + Gram (4x4 reg-blocked)
// ---------------------------------------------------------------------------
__global__ void prep_kernel(const float* __restrict__ imgs,
                            const float* __restrict__ caps,
                            const int* __restrict__ cap_lens) {
    __shared__ float chunk[NREG * 132];
    if (blockIdx.x < 256) {
        const int c = blockIdx.x;
        const int wid = threadIdx.x >> 5, lane = threadIdx.x & 31;
        const int len = cap_lens[c];
        for (int w = wid; w < CAPW; w += 8) {
            size_t dsto = ((size_t)c * CAPW + w) * DIM;
            if (w < len) {
                const float* row = caps + ((size_t)c * MAXW + w) * DIM;
                float ss = 0.f;
#pragma unroll
                for (int j = 0; j < 8; j++) {
                    float4 v = *(const float4*)(row + j * 128 + lane * 4);
                    ss += v.x * v.x + v.y * v.y + v.z * v.z + v.w * v.w;
                    size_t o = dsto + j * 128 + lane * 4;
                    *(__half2*)(g_caps_h + o)     = __floats2half2_rn(v.x, v.y);
                    *(__half2*)(g_caps_h + o + 2) = __floats2half2_rn(v.z, v.w);
                }
                ss = warpSum(ss);
                if (lane == 0 && w < MAXW) g_w1[c * MAXW + w] = sqrtf(ss);
            } else {
                uint2 z = make_uint2(0u, 0u);
#pragma unroll
                for (int j = 0; j < 8; j++)
                    *(uint2*)(g_caps_h + dsto + j * 128 + lane * 4) = z;
                if (lane == 0 && w < MAXW) g_w1[c * MAXW + w] = 0.f;
            }
        }
    } else {
        const int i = blockIdx.x - 256;
        // 4x4 register-blocked Gram: 81 threads own (4 rows) x (4 cols) tiles
        const int ty = threadIdx.x / 9;   // 0..8 (for tid < 81)
        const int tx = threadIdx.x % 9;
        float acc[4][4];
#pragma unroll
        for (int u = 0; u < 4; u++)
#pragma unroll
            for (int v = 0; v < 4; v++) acc[u][v] = 0.f;

        for (int d0 = 0; d0 < DIM; d0 += 128) {
            __syncthreads();
            for (int idx = threadIdx.x; idx < NREG * 32; idx += 256) {
                int r = idx >> 5, dq = idx & 31;
                size_t e = ((size_t)i * NREG + r) * DIM + d0 + dq * 4;
                float4 v = *(const float4*)(imgs + e);
                *(float4*)(chunk + r * 132 + dq * 4) = v;
                *(__half2*)(g_imgs_h + e)     = __floats2half2_rn(v.x, v.y);
                *(__half2*)(g_imgs_h + e + 2) = __floats2half2_rn(v.z, v.w);
            }
            __syncthreads();
            if (threadIdx.x < 81) {
                const float4* A0 = (const float4*)(chunk + (ty * 4 + 0) * 132);
                const float4* A1 = (const float4*)(chunk + (ty * 4 + 1) * 132);
                const float4* A2 = (const float4*)(chunk + (ty * 4 + 2) * 132);
                const float4* A3 = (const float4*)(chunk + (ty * 4 + 3) * 132);
                const float4* B0 = (const float4*)(chunk + (tx * 4 + 0) * 132);
                const float4* B1 = (const float4*)(chunk + (tx * 4 + 1) * 132);
                const float4* B2 = (const float4*)(chunk + (tx * 4 + 2) * 132);
                const float4* B3 = (const float4*)(chunk + (tx * 4 + 3) * 132);
#pragma unroll 8
                for (int q = 0; q < 32; q++) {
                    float4 a0 = A0[q], a1 = A1[q], a2 = A2[q], a3 = A3[q];
                    float4 b0 = B0[q], b1 = B1[q], b2 = B2[q], b3 = B3[q];
                    acc[0][0] += dot4(a0, b0); acc[0][1] += dot4(a0, b1);
                    acc[0][2] += dot4(a0, b2); acc[0][3] += dot4(a0, b3);
                    acc[1][0] += dot4(a1, b0); acc[1][1] += dot4(a1, b1);
                    acc[1][2] += dot4(a1, b2); acc[1][3] += dot4(a1, b3);
                    acc[2][0] += dot4(a2, b0); acc[2][1] += dot4(a2, b1);
                    acc[2][2] += dot4(a2, b2); acc[2][3] += dot4(a2, b3);
                    acc[3][0] += dot4(a3, b0); acc[3][1] += dot4(a3, b1);
                    acc[3][2] += dot4(a3, b2); acc[3][3] += dot4(a3, b3);
                }
            }
        }
        if (threadIdx.x < 81) {
            float* Gi = g_G + (size_t)i * NREG * NREG;
#pragma unroll
            for (int u = 0; u < 4; u++) {
                float4 v0 = make_float4(acc[u][0], acc[u][1], acc[u][2], acc[u][3]);
                *(float4*)(Gi + (ty * 4 + u) * NREG + tx * 4) = v0;
            }
        }
    }
}

// ---------------------------------------------------------------------------
// Main fused kernel: fp16 GEMM M=128 x N=144 x K=1024 + SCAN epilogue.
// 256 threads / 8 warps (warp tile 32x72), 3-stage pipeline, 2 CTAs/SM.
// ---------------------------------------------------------------------------
#define STAGE_BYTES 34816
#define SB_OFF      16384
#define SOFF_SCALE  75776
#define SOFF_W1     76928
#define SOFF_WP     77440
#define SOFF_G      77504
#define SMEM_TOTAL_MAIN 104448
#define NCHUNK 16
#define SSTRIDE 148   // floats per S row

__device__ __forceinline__ void load_stage(uint32_t sbase, int chunk, int tid,
                                           int arowbase, int browbase) {
    const int k0 = chunk << 6;
    const uint32_t sA = sbase + (chunk % 3) * STAGE_BYTES;
    const uint32_t sB = sA + SB_OFF;
#pragma unroll
    for (int t = 0; t < 4; t++) {
        int o = tid + t * 256;
        int row = o >> 3, seg = o & 7;
        cp16(sA + row * 128 + (((seg ^ (row & 7))) << 4),
             g_caps_h + (((size_t)(arowbase + row)) << 10) + k0 + (seg << 3));
    }
#pragma unroll
    for (int t = 0; t < 4; t++) {
        int o = tid + t * 256;
        int row = o >> 3, seg = o & 7;
        cp16(sB + row * 128 + (((seg ^ (row & 7))) << 4),
             g_imgs_h + (((size_t)(browbase + row)) << 10) + k0 + (seg << 3));
    }
    {
        int o = tid + 1024;
        if (o < 1152) {
            int row = o >> 3, seg = o & 7;
            cp16(sB + row * 128 + (((seg ^ (row & 7))) << 4),
                 g_imgs_h + (((size_t)(browbase + row)) << 10) + k0 + (seg << 3));
        }
    }
    asm volatile("cp.async.commit_group;" ::: "memory");
}

__global__ void __launch_bounds__(256, 2)
main_kernel(const int* __restrict__ cap_lens, float* __restrict__ out) {
    extern __shared__ __align__(16) char smem[];
    const uint32_t sb = smem_to_u32(smem);
    const int tid = threadIdx.x, lane = tid & 31, wid = tid >> 5;
    const int c0 = blockIdx.y * 2;
    const int i0 = blockIdx.x * 4;
    const int arowbase = blockIdx.y * 128;
    const int browbase = blockIdx.x * 144;

    float acc[72];
#pragma unroll
    for (int j = 0; j < 72; j++) acc[j] = 0.f;

    load_stage(sb, 0, tid, arowbase, browbase);
    load_stage(sb, 1, tid, arowbase, browbase);

    const int mstrip = wid & 3;
    const int mbase = mstrip * 32;
    const int ncb = (wid >> 2) * 72;
    const bool gemm_active =
        ((mstrip & 1) == 0) || (cap_lens[c0 + (mstrip >> 1)] > 32);

    const int a_roff = lane & 15;
    const int a_seg0 = lane >> 4;
    const int b_roff = ((lane >> 4) << 3) + (lane & 7);
    const int b_seg0 = (lane >> 3) & 1;
    const int l16 = lane & 15;
    const int b2_roff = l16 & 7;
    const int b2_seg0 = (l16 >> 3) & 1;
    const int sw = lane & 7;

    for (int i = 0; i < NCHUNK; i++) {
        if (i == NCHUNK - 1) asm volatile("cp.async.wait_group 0;" ::: "memory");
        else                 asm volatile("cp.async.wait_group 1;" ::: "memory");
        __syncthreads();
        if (i + 2 < NCHUNK)
            load_stage(sb, i + 2, tid, arowbase, browbase);

        if (gemm_active) {
            const uint32_t As = sb + (i % 3) * STAGE_BYTES;
            const uint32_t Bs = As + SB_OFF;
#pragma unroll
            for (int ks = 0; ks < 4; ks++) {
                uint32_t a[2][4];
#pragma unroll
                for (int s2 = 0; s2 < 2; s2++) {
                    int row = mbase + s2 * 16 + a_roff;
                    int seg = (ks * 2 + a_seg0) ^ sw;
                    ldsm_x4(a[s2][0], a[s2][1], a[s2][2], a[s2][3],
                            As + row * 128 + (seg << 4));
                }
                uint32_t bh0, bh1;
                {
                    int row = ncb + 64 + b2_roff;
                    int seg = (ks * 2 + b2_seg0) ^ sw;
                    ldsm_x2(bh0, bh1, Bs + row * 128 + (seg << 4));
                }
#pragma unroll
                for (int t = 0; t < 4; t++) {
                    uint32_t b0, b1, b2, b3;
                    int row = ncb + t * 16 + b_roff;
                    int seg = (ks * 2 + b_seg0) ^ sw;
                    ldsm_x4(b0, b1, b2, b3, Bs + row * 128 + (seg << 4));
#pragma unroll
                    for (int s2 = 0; s2 < 2; s2++) {
                        int j0 = s2 * 36 + t * 8;
                        mma_f16(acc[j0 + 0], acc[j0 + 1], acc[j0 + 2], acc[j0 + 3],
                                a[s2][0], a[s2][1], a[s2][2], a[s2][3], b0, b1);
                        mma_f16(acc[j0 + 4], acc[j0 + 5], acc[j0 + 6], acc[j0 + 7],
                                a[s2][0], a[s2][1], a[s2][2], a[s2][3], b2, b3);
                    }
                }
#pragma unroll
                for (int s2 = 0; s2 < 2; s2++) {
                    int j0 = s2 * 36 + 32;
                    mma_f16(acc[j0 + 0], acc[j0 + 1], acc[j0 + 2], acc[j0 + 3],
                            a[s2][0], a[s2][1], a[s2][2], a[s2][3], bh0, bh1);
                }
            }
        }
    }
    __syncthreads();

    // ---------------- write S + stage Gram (zero-padded to 40) / w1 --------
    float* S = (float*)smem;
    {
        const int cA = (lane & 3) * 2;
        const int rA = lane >> 2;
#pragma unroll
        for (int s2 = 0; s2 < 2; s2++) {
            int r1 = mbase + s2 * 16 + rA;
#pragma unroll
            for (int j = 0; j < 9; j++) {
                int col = ncb + j * 8 + cA;
                *(float2*)(S + r1 * SSTRIDE + col) =
                    make_float2(acc[s2 * 36 + j * 4 + 0], acc[s2 * 36 + j * 4 + 1]);
                *(float2*)(S + (r1 + 8) * SSTRIDE + col) =
                    make_float2(acc[s2 * 36 + j * 4 + 2], acc[s2 * 36 + j * 4 + 3]);
            }
        }
    }
    {
        float* Gs = (float*)(smem + SOFF_G);
        if (tid < 4 * NREG) {
            int blk = tid / NREG, r = tid - blk * NREG;
            const float4* src = (const float4*)(g_G + ((size_t)(i0 + blk) * NREG + r) * NREG);
            float4* dst = (float4*)(Gs + (blk * NREG + r) * 40);
#pragma unroll
            for (int q = 0; q < 9; q++) dst[q] = src[q];
            dst[9] = make_float4(0.f, 0.f, 0.f, 0.f);
        }
        float* w1s = (float*)(smem + SOFF_W1);
        if (tid >= 128) {
            int p = tid - 128;
            int cc = p >> 6, w = p & 63;
            w1s[p] = (w < MAXW) ? g_w1[(c0 + cc) * MAXW + w] : 0.f;
        }
    }
    __syncthreads();

    // ---------------- column norms -> scale (loop bounded by cap_len) ------
    float* scaleF = (float*)(smem + SOFF_SCALE);
    for (int task = tid; task < 288; task += 256) {
        int cap = task >= 144;
        int j = task - cap * 144;
        int lenc = cap_lens[c0 + cap];
        const float* p = S + (cap * 64) * SSTRIDE + j;
        float ssum = 0.f;
        for (int w = 0; w < lenc; w++) {
            float v = p[w * SSTRIDE];
            v = (v < 0.f) ? LEAK * v : v;
            ssum += v * v;
        }
        scaleF[cap * 144 + j] = SMOOTH / (sqrtf(ssum) + EPSV);
    }
    __syncthreads();

    // ---------------- per-row epilogue (256 threads, 2 blks each) ----------
    {
        const int row = tid & 127;
        const int pair = tid >> 7;
        const int cap = row >> 6;
        const int word = row & 63;
        const int mylen = cap_lens[c0 + cap];
        const int wstart = ((wid & 1) << 5);
        const bool warp_active = (wstart < mylen);
        const bool valid = word < mylen;
        float* wp = (float*)(smem + SOFF_WP);

        if (!warp_active) {
            if (lane == 0) { wp[wid * 2 + 0] = 0.f; wp[wid * 2 + 1] = 0.f; }
        } else {
            const float myw1 = ((const float*)(smem + SOFF_W1))[row];
            const float* Srow = S + row * SSTRIDE;
#pragma unroll
            for (int bq = 0; bq < 2; bq++) {
                const int blk = pair * 2 + bq;
                const float* scl = scaleF + cap * 144 + blk * 36;
                float raw[36], e[40];
                {
                    const float4* p4 = (const float4*)(Srow + blk * 36);
#pragma unroll
                    for (int q = 0; q < 9; q++) {
                        float4 v = p4[q];
                        raw[q * 4 + 0] = v.x; raw[q * 4 + 1] = v.y;
                        raw[q * 4 + 2] = v.z; raw[q * 4 + 3] = v.w;
                    }
                }
                float se = 0.f;
#pragma unroll
                for (int r = 0; r < 36; r++) {
                    float v = raw[r];
                    float l = ((v < 0.f) ? LEAK * v : v) * scl[r];
                    e[r] = __expf(l);
                    se += e[r];
                }
                e[36] = 0.f; e[37] = 0.f; e[38] = 0.f; e[39] = 0.f;
                float inv = 1.f / se;
                float w12 = 0.f;
#pragma unroll
                for (int r = 0; r < 36; r++) w12 += e[r] * raw[r];
                w12 *= inv;

                unsigned long long ep[20];
#pragma unroll
                for (int q = 0; q < 20; q++) ep[q] = pack2(e[2 * q], e[2 * q + 1]);
                const float* Gbase =
                    (const float*)(smem + SOFF_G) + (size_t)blk * NREG * 40;
                float t = 0.f;
#pragma unroll
                for (int r = 0; r < 36; r++) {
                    const float* grow = Gbase + r * 40;
                    const unsigned long long* grow2 = (const unsigned long long*)grow;
                    float head = 0.f;
                    int q0 = r + 1;
                    if (q0 & 1) { head = grow[q0] * e[q0]; q0++; }
                    unsigned long long d2 = 0ull;
#pragma unroll
                    for (int qq = q0 >> 1; qq < 20; qq++) ffma2(d2, grow2[qq], ep[qq]);
                    float dlo, dhi;
                    unpack2(d2, dlo, dhi);
                    t += e[r] * (grow[r] * e[r] + 2.f * (head + dlo + dhi));
                }
                float w2 = sqrtf(t) * inv;
                float sim = w12 / fmaxf(myw1 * w2, EPSV);
                sim = valid ? sim : 0.f;

                float ssum = warpSum(sim);
                if (lane == 0) wp[wid * 2 + bq] = ssum;
            }
        }
    }
    __syncthreads();
    if (tid < 8) {
        int blk = tid & 3, cc = tid >> 2;
        int p = blk >> 1, b = blk & 1;
        float* wp = (float*)(smem + SOFF_WP);
        int w0 = p * 4 + cc * 2;
        float s = wp[w0 * 2 + b] + wp[(w0 + 1) * 2 + b];
        out[(size_t)(i0 + blk) * NCAP + (c0 + cc)] = s / (float)cap_lens[c0 + cc];
    }
}

// ---------------------------------------------------------------------------
extern "C" void kernel_launch(void* const* d_in, const int* in_sizes, int n_in,
                              void* d_out, int out_size) {
    const float* imgs     = (const float*)d_in[0];
    const float* caps     = (const float*)d_in[1];
    const int*   cap_lens = (const int*)d_in[3];
    float*       out      = (float*)d_out;

    prep_kernel<<<512, 256>>>(imgs, caps, cap_lens);

    cudaFuncSetAttribute(main_kernel, cudaFuncAttributeMaxDynamicSharedMemorySize,
                         SMEM_TOTAL_MAIN);
    dim3 grid(NIMG / 4, NCAP / 2);
    main_kernel<<<grid, 256, SMEM_TOTAL_MAIN>>>(cap_lens, out);
}